// round 2
// baseline (speedup 1.0000x reference)
#include <cuda_runtime.h>

// Problem constants
#define BB   16
#define CC   768
#define HWs  576
#define NTOK (BB*HWs)          // 9216
#define ELEMS (BB*CC*HWs)      // 7,077,888
#define NLAYER 4

// Scratch (device globals; no allocation allowed)
__device__ float g_cur[ELEMS];       // running x51 (input to each block)
__device__ float g_x5[ELEMS];        // post-conv x5 inside a block
__device__ float g_q[ELEMS];
__device__ float g_k[ELEMS];
__device__ float g_maxpart[BB*NTOK]; // [bk][n] per-key-batch row maxima
__device__ int   g_hwstar[BB];
__device__ float g_norm[BB*HWs];
__device__ float g_seeds[BB*CC];
__device__ float g_cor[BB*HWs];
__device__ float g_consen[CC];

// ---------------------------------------------------------------------------
// GEMM: Y[b,o,hw] = sum_c W[o,c] * X[b,c,hw] + bias[o] (+ residual X[b,o,hw])
// 64x64 tile, BK=32, 256 threads, 4x4 microtile, float4 smem paths.
// src_sel: 0 -> Xin (layer-0 external input), 1 -> g_cur, 2 -> g_x5
// dst_sel: 0 -> g_x5, 1 -> g_q, 2 -> g_k
// ---------------------------------------------------------------------------
__global__ void gemm_kernel(const float* __restrict__ Xin, int src_sel, int dst_sel,
                            const float* __restrict__ W, const float* __restrict__ bias,
                            int residual)
{
    const float* X = (src_sel == 0) ? Xin : (src_sel == 1 ? g_cur : g_x5);
    float* Y = (dst_sel == 0) ? g_x5 : (dst_sel == 1 ? g_q : g_k);

    const int b  = blockIdx.z;
    const int o0 = blockIdx.y * 64;
    const int n0 = blockIdx.x * 64;
    const float* Xb = X + b * CC * HWs;

    __shared__ float Ws[32][68];
    __shared__ float Xs[32][68];

    const int t  = threadIdx.x;
    const int ty = t >> 4;       // 0..15
    const int tx = t & 15;       // 0..15

    float acc[4][4] = {};

    for (int k0 = 0; k0 < CC; k0 += 32) {
        // Load W tile [64 o][32 k], transpose into Ws[k][o]
        // 256 threads x 2 float4 = 64*32 floats
        {
            int oo = t >> 2;            // 0..63
            int kk = (t & 3) << 3;      // 0,8,16,24
            float4 w4a = *(const float4*)(W + (o0 + oo) * CC + k0 + kk);
            float4 w4b = *(const float4*)(W + (o0 + oo) * CC + k0 + kk + 4);
            Ws[kk + 0][oo] = w4a.x; Ws[kk + 1][oo] = w4a.y;
            Ws[kk + 2][oo] = w4a.z; Ws[kk + 3][oo] = w4a.w;
            Ws[kk + 4][oo] = w4b.x; Ws[kk + 5][oo] = w4b.y;
            Ws[kk + 6][oo] = w4b.z; Ws[kk + 7][oo] = w4b.w;
        }
        // Load X tile [32 k][64 n] directly (contiguous along n)
        {
            int kk = t >> 4;            // 0..15 -> rows kk and kk+16
            int nn = (t & 15) << 2;     // 0..60
            *(float4*)&Xs[kk][nn]      = *(const float4*)(Xb + (k0 + kk)      * HWs + n0 + nn);
            *(float4*)&Xs[kk + 16][nn] = *(const float4*)(Xb + (k0 + kk + 16) * HWs + n0 + nn);
        }
        __syncthreads();

        #pragma unroll
        for (int kk = 0; kk < 32; kk++) {
            float4 a4 = *(float4*)&Ws[kk][ty << 2];
            float4 b4 = *(float4*)&Xs[kk][tx << 2];
            float av[4] = {a4.x, a4.y, a4.z, a4.w};
            float bv[4] = {b4.x, b4.y, b4.z, b4.w};
            #pragma unroll
            for (int i = 0; i < 4; i++)
                #pragma unroll
                for (int j = 0; j < 4; j++)
                    acc[i][j] = fmaf(av[i], bv[j], acc[i][j]);
        }
        __syncthreads();
    }

    #pragma unroll
    for (int i = 0; i < 4; i++) {
        int o = o0 + (ty << 2) + i;
        float bs = bias[o];
        #pragma unroll
        for (int j = 0; j < 4; j++) {
            int n = n0 + (tx << 2) + j;
            float v = acc[i][j] + bs;
            if (residual) v += Xb[o * HWs + n];
            Y[b * CC * HWs + o * HWs + n] = v;
        }
    }
}

// ---------------------------------------------------------------------------
// Attention row-max: for 64 query rows (one strip of batch bq) against ALL 576
// keys of batch bk, compute max_{hw_k} (q . k) and store into g_maxpart[bk][n].
// Never materializes the [9216,9216] matrix. 64 threads, 8x8 microtile, BK=32.
// grid = (144 row strips, 16 key batches)
// ---------------------------------------------------------------------------
__global__ void attn_kernel()
{
    const int rs  = blockIdx.x;        // 0..143
    const int bk  = blockIdx.y;        // 0..15
    const int bq  = rs / 9;
    const int hq0 = (rs % 9) * 64;

    const float* Qb = g_q + bq * CC * HWs;
    const float* Kb = g_k + bk * CC * HWs;

    __shared__ float Qs[32][68];
    __shared__ float Ks[32][68];

    const int t   = threadIdx.x;       // 0..63
    const int ty  = t >> 3;            // 0..7 (row group)
    const int tx  = t & 7;             // 0..7 (col group)
    const int lkk = t >> 1;            // 0..31 load row
    const int lc0 = (t & 1) << 5;      // 0,32 load col base

    float runmax[8];
    #pragma unroll
    for (int i = 0; i < 8; i++) runmax[i] = -3.402823e38f;

    for (int ct = 0; ct < 9; ct++) {
        const int hk0 = ct * 64;
        float acc[8][8] = {};

        for (int k0 = 0; k0 < CC; k0 += 32) {
            const float* qsrc = Qb + (k0 + lkk) * HWs + hq0 + lc0;
            const float* ksrc = Kb + (k0 + lkk) * HWs + hk0 + lc0;
            #pragma unroll
            for (int u = 0; u < 8; u++) {
                *(float4*)&Qs[lkk][lc0 + 4 * u] = *(const float4*)(qsrc + 4 * u);
                *(float4*)&Ks[lkk][lc0 + 4 * u] = *(const float4*)(ksrc + 4 * u);
            }
            __syncthreads();

            #pragma unroll
            for (int kk = 0; kk < 32; kk++) {
                float a[8], bb[8];
                *(float4*)&a[0]  = *(float4*)&Qs[kk][ty << 3];
                *(float4*)&a[4]  = *(float4*)&Qs[kk][(ty << 3) + 4];
                *(float4*)&bb[0] = *(float4*)&Ks[kk][tx << 3];
                *(float4*)&bb[4] = *(float4*)&Ks[kk][(tx << 3) + 4];
                #pragma unroll
                for (int i = 0; i < 8; i++)
                    #pragma unroll
                    for (int j = 0; j < 8; j++)
                        acc[i][j] = fmaf(a[i], bb[j], acc[i][j]);
            }
            __syncthreads();
        }

        #pragma unroll
        for (int i = 0; i < 8; i++) {
            float m = acc[i][0];
            #pragma unroll
            for (int j = 1; j < 8; j++) m = fmaxf(m, acc[i][j]);
            runmax[i] = fmaxf(runmax[i], m);
        }
    }

    // reduce row max across the 8 tx threads (xor-shuffle within warp)
    #pragma unroll
    for (int i = 0; i < 8; i++) {
        float m = runmax[i];
        m = fmaxf(m, __shfl_xor_sync(0xffffffffu, m, 1));
        m = fmaxf(m, __shfl_xor_sync(0xffffffffu, m, 2));
        m = fmaxf(m, __shfl_xor_sync(0xffffffffu, m, 4));
        runmax[i] = m;
    }
    if (tx == 0) {
        #pragma unroll
        for (int i = 0; i < 8; i++)
            g_maxpart[bk * NTOK + bq * HWs + hq0 + (ty << 3) + i] = runmax[i];
    }
}

// ---------------------------------------------------------------------------
// Per-batch argmax of xw (sum of per-bk maxima; softmax/scale/mean skipped —
// they are monotone and don't move the argmax). grid=16, block=256.
// ---------------------------------------------------------------------------
__global__ void argmax_kernel()
{
    const int b = blockIdx.x;
    const int tid = threadIdx.x;
    __shared__ float sv[256];
    __shared__ int   si[256];

    float best = -3.402823e38f;
    int   bidx = 0;
    for (int hw = tid; hw < HWs; hw += 256) {
        float s = 0.f;
        #pragma unroll
        for (int bk = 0; bk < BB; bk++)
            s += g_maxpart[bk * NTOK + b * HWs + hw];
        if (s > best) { best = s; bidx = hw; }
    }
    sv[tid] = best; si[tid] = bidx;
    __syncthreads();
    for (int s = 128; s > 0; s >>= 1) {
        if (tid < s) {
            if (sv[tid + s] > sv[tid] ||
                (sv[tid + s] == sv[tid] && si[tid + s] < si[tid])) {
                sv[tid] = sv[tid + s];
                si[tid] = si[tid + s];
            }
        }
        __syncthreads();
    }
    if (tid == 0) g_hwstar[b] = si[0];
}

// ---------------------------------------------------------------------------
// Channel L2 norms per spatial position: norm[b,hw] = max(||x5[b,:,hw]||, 1e-12)
// ---------------------------------------------------------------------------
__global__ void norm_kernel()
{
    int p = blockIdx.x * blockDim.x + threadIdx.x;   // 0..9215
    if (p >= NTOK) return;
    int b = p / HWs, hw = p % HWs;
    const float* xp = g_x5 + b * CC * HWs + hw;
    float s = 0.f;
    #pragma unroll 8
    for (int c = 0; c < CC; c++) {
        float v = xp[c * HWs];
        s = fmaf(v, v, s);
    }
    g_norm[p] = fmaxf(sqrtf(s), 1e-12f);
}

// seeds[b,c] = x5[b,c,hw*] / norm[b,hw*]   (grid=16, block=768)
__global__ void seeds_kernel()
{
    int b = blockIdx.x;
    int c = threadIdx.x;
    int hws = g_hwstar[b];
    float inv = 1.f / g_norm[b * HWs + hws];
    g_seeds[b * CC + c] = g_x5[b * CC * HWs + c * HWs + hws] * inv;
}

// ---------------------------------------------------------------------------
// cor[b,hw] = (1/16) * sum_{b'} relu(x5[b,:,hw] . seeds[b',:]) / norm[b,hw]
// (1/norm factored out of relu since norm > 0). grid=(16,3), block=192.
// ---------------------------------------------------------------------------
__global__ void cor_kernel()
{
    __shared__ float ss[BB * CC];   // 48 KB exactly
    const int b = blockIdx.x;
    for (int i = threadIdx.x; i < BB * CC; i += blockDim.x) ss[i] = g_seeds[i];
    __syncthreads();

    const int hw = blockIdx.y * 192 + threadIdx.x;
    const float* xp = g_x5 + b * CC * HWs + hw;
    float acc[BB] = {};
    for (int c = 0; c < CC; c++) {
        float v = xp[c * HWs];
        #pragma unroll
        for (int o = 0; o < BB; o++)
            acc[o] = fmaf(v, ss[o * CC + c], acc[o]);
    }
    float s = 0.f;
    #pragma unroll
    for (int o = 0; o < BB; o++) s += fmaxf(acc[o], 0.f);
    g_cor[b * HWs + hw] = s / (16.f * g_norm[b * HWs + hw]);
}

// Per-batch min-max normalize of cor. grid=16, block=256.
__global__ void minmax_kernel()
{
    const int b = blockIdx.x;
    const int tid = threadIdx.x;
    __shared__ float smn[256], smx[256];
    float mn = 3.402823e38f, mx = -3.402823e38f;
    for (int hw = tid; hw < HWs; hw += 256) {
        float v = g_cor[b * HWs + hw];
        mn = fminf(mn, v);
        mx = fmaxf(mx, v);
    }
    smn[tid] = mn; smx[tid] = mx;
    __syncthreads();
    for (int s = 128; s > 0; s >>= 1) {
        if (tid < s) {
            smn[tid] = fminf(smn[tid], smn[tid + s]);
            smx[tid] = fmaxf(smx[tid], smx[tid + s]);
        }
        __syncthreads();
    }
    float m0 = smn[0];
    float inv = 1.f / (smx[0] - m0 + 1e-12f);
    for (int hw = tid; hw < HWs; hw += 256)
        g_cor[b * HWs + hw] = (g_cor[b * HWs + hw] - m0) * inv;
}

// cur = (add_prev ? cur : 0) + x5 * cor   (grid-stride exact: 27648x256)
__global__ void apply_kernel(int add_prev)
{
    int idx = blockIdx.x * 256 + threadIdx.x;
    int b  = idx / (CC * HWs);
    int hw = idx % HWs;
    float v = g_x5[idx] * g_cor[b * HWs + hw];
    g_cur[idx] = (add_prev ? g_cur[idx] : 0.f) + v;
}

// consen[c] = mean over (b,hw) of cur. grid=768, block=256.
__global__ void consen_kernel()
{
    const int c = blockIdx.x;
    const int tid = threadIdx.x;
    __shared__ float sm[256];
    float s = 0.f;
    for (int b = 0; b < BB; b++) {
        const float* p = g_cur + b * CC * HWs + c * HWs;
        for (int hw = tid; hw < HWs; hw += 256) s += p[hw];
    }
    sm[tid] = s;
    __syncthreads();
    for (int st = 128; st > 0; st >>= 1) {
        if (tid < st) sm[tid] += sm[tid + st];
        __syncthreads();
    }
    if (tid == 0) g_consen[c] = sm[0] * (1.f / (float)(BB * HWs));
}

// out = cur + x_in * consen[c]
__global__ void final_kernel(const float* __restrict__ xin, float* __restrict__ out)
{
    int idx = blockIdx.x * 256 + threadIdx.x;
    int c = (idx / HWs) % CC;
    out[idx] = g_cur[idx] + xin[idx] * g_consen[c];
}

// ---------------------------------------------------------------------------
extern "C" void kernel_launch(void* const* d_in, const int* in_sizes, int n_in,
                              void* d_out, int out_size)
{
    const float* x5      = (const float*)d_in[0];
    const float* conv_w  = (const float*)d_in[1];
    const float* conv_b  = (const float*)d_in[2];
    const float* query_w = (const float*)d_in[3];
    const float* query_b = (const float*)d_in[4];
    const float* key_w   = (const float*)d_in[5];
    const float* key_b   = (const float*)d_in[6];
    float* out = (float*)d_out;

    dim3 ggrid(HWs / 64, CC / 64, BB);      // (9, 12, 16)
    dim3 agrid(NTOK / 64, BB);              // (144, 16)
    dim3 cgrid(BB, HWs / 192);              // (16, 3)
    const int egrid = ELEMS / 256;          // 27648

    for (int i = 0; i < NLAYER; i++) {
        // x5 = conv(x) + bias + x
        gemm_kernel<<<ggrid, 256>>>((i == 0) ? x5 : nullptr, (i == 0) ? 0 : 1, 0,
                                    conv_w + i * CC * CC, conv_b + i * CC, 1);
        // q, k
        gemm_kernel<<<ggrid, 256>>>(nullptr, 2, 1,
                                    query_w + i * CC * CC, query_b + i * CC, 0);
        gemm_kernel<<<ggrid, 256>>>(nullptr, 2, 2,
                                    key_w + i * CC * CC, key_b + i * CC, 0);
        // attention row-max reduction + argmax (softmax skipped: monotone)
        attn_kernel<<<agrid, 64>>>();
        argmax_kernel<<<BB, 256>>>();
        // norms, seeds, correlation, min-max, apply
        norm_kernel<<<NTOK / 256, 256>>>();
        seeds_kernel<<<BB, CC>>>();
        cor_kernel<<<cgrid, 192>>>();
        minmax_kernel<<<BB, 256>>>();
        apply_kernel<<<egrid, 256>>>(i > 0 ? 1 : 0);
    }
    consen_kernel<<<CC, 256>>>();
    final_kernel<<<egrid, 256>>>(x5, out);
}

// round 5
// speedup vs baseline: 2.3166x; 2.3166x over previous
#include <cuda_runtime.h>
#include <cuda_bf16.h>
#include <cstdint>

// Problem constants
#define BB   16
#define CC   768
#define HWs  576
#define NTOK (BB*HWs)          // 9216
#define ELEMS (BB*CC*HWs)      // 7,077,888
#define NLAYER 4

// Scratch (device globals; no allocation allowed)
__device__ float g_cur[ELEMS];
__device__ float g_x5[ELEMS];
__device__ float g_q[ELEMS];
__device__ float g_k[ELEMS];
__device__ __nv_bfloat16 g_qh[(size_t)NTOK*CC];
__device__ __nv_bfloat16 g_ql[(size_t)NTOK*CC];
__device__ __nv_bfloat16 g_kh[(size_t)NTOK*CC];
__device__ __nv_bfloat16 g_kl[(size_t)NTOK*CC];
__device__ float g_maxpart[BB*NTOK];
__device__ int   g_hwstar[BB];
__device__ float g_norm[BB*HWs];
__device__ float g_seeds[BB*CC];
__device__ float g_cor[BB*HWs];
__device__ float g_consen[CC];

// ============================ PTX helpers (sm_80+ only) =====================
__device__ __forceinline__ uint32_t smem_u32(const void* p) {
    uint32_t a;
    asm("{ .reg .u64 t; cvta.to.shared.u64 t, %1; cvt.u32.u64 %0, t; }" : "=r"(a) : "l"(p));
    return a;
}
__device__ __forceinline__ void cp16(uint32_t d, const void* s) {
    asm volatile("cp.async.cg.shared.global [%0], [%1], 16;" :: "r"(d), "l"(s));
}
__device__ __forceinline__ void cp_commit() { asm volatile("cp.async.commit_group;"); }
template<int N> __device__ __forceinline__ void cp_wait() {
    asm volatile("cp.async.wait_group %0;" :: "n"(N));
}
__device__ __forceinline__ void ldsm4(uint32_t* r, uint32_t a) {
    asm volatile("ldmatrix.sync.aligned.m8n8.x4.shared.b16 {%0,%1,%2,%3}, [%4];"
                 : "=r"(r[0]), "=r"(r[1]), "=r"(r[2]), "=r"(r[3]) : "r"(a));
}
__device__ __forceinline__ void mma16816(float* d, const uint32_t* a, const uint32_t* b) {
    asm volatile("mma.sync.aligned.m16n8k16.row.col.f32.bf16.bf16.f32 "
                 "{%0,%1,%2,%3}, {%4,%5,%6,%7}, {%8,%9}, {%0,%1,%2,%3};"
                 : "+f"(d[0]), "+f"(d[1]), "+f"(d[2]), "+f"(d[3])
                 : "r"(a[0]), "r"(a[1]), "r"(a[2]), "r"(a[3]), "r"(b[0]), "r"(b[1]));
}

// ---------------------------------------------------------------------------
// convert+transpose: q,k [b][c][hw] fp32 -> [n=b*HW+hw][c] bf16 hi/lo.
// grid (18, 24, 32): z<16 -> q batch z; z>=16 -> k batch z-16. block (32,8).
// ---------------------------------------------------------------------------
__global__ void convert_qk_kernel()
{
    __shared__ float tile[32][33];
    const int z = blockIdx.z;
    const int b = z & 15;
    const float* src = ((z < 16) ? g_q : g_k) + (size_t)b * CC * HWs;
    __nv_bfloat16* dh = (z < 16) ? g_qh : g_kh;
    __nv_bfloat16* dl = (z < 16) ? g_ql : g_kl;
    const int hw0 = blockIdx.x * 32;
    const int c0  = blockIdx.y * 32;
    const int tx = threadIdx.x, ty = threadIdx.y;

    #pragma unroll
    for (int j = 0; j < 4; j++) {
        int c = ty * 4 + j;
        tile[c][tx] = src[(size_t)(c0 + c) * HWs + hw0 + tx];
    }
    __syncthreads();
    #pragma unroll
    for (int j = 0; j < 4; j++) {
        int hwl = ty * 4 + j;
        float v = tile[tx][hwl];
        __nv_bfloat16 h = __float2bfloat16(v);
        __nv_bfloat16 l = __float2bfloat16(v - __bfloat162float(h));
        size_t o = (size_t)(b * HWs + hw0 + hwl) * CC + c0 + tx;
        dh[o] = h;
        dl[o] = l;
    }
}

// ---------------------------------------------------------------------------
// mma.sync attention row-max. grid (72 m-tiles, 16 bk), 256 threads (8 warps).
// CTA: 128 query rows vs 576 keys of batch bk. 9 key-tiles of 64 (ct);
// K=768 in 24 chunks of 32, cp.async double-buffered.
// Per stage smem (stride 80B rows, conflict-free ldmatrix):
//   Ahi[128][40bf16] @0 (10240) | Alo @10240 | Bhi[64][40] @20480 (5120) | Blo @25600
// 3-pass bf16 split MMA (hh + hl + lh) in fp32 accumulators.
// ---------------------------------------------------------------------------
#define STAGE_B 30720
#define ATT_DYN (2*STAGE_B)      // 61440
#define NSTAGE  216              // 9 ct * 24 k-chunks

__global__ void __launch_bounds__(256) attn_mma_kernel()
{
    extern __shared__ __align__(16) char sm[];
    __shared__ float srow[2][128];

    const int t   = threadIdx.x;
    const int wid = t >> 5;
    const int lid = t & 31;
    const int n0  = blockIdx.x * 128;
    const int bk  = blockIdx.y;
    const int warp_m = wid & 3;      // 0..3 -> 32-row slice
    const int warp_n = wid >> 2;     // 0..1 -> 32-col slice

    const uint32_t smbase = smem_u32(sm);

    // cp.async stage loader: 6 x 16B per thread
    auto load_stage = [&](int s) {
        const int hk0 = (s / 24) * 64;
        const int k0  = (s % 24) * 32;
        const uint32_t st = smbase + (uint32_t)(s & 1) * STAGE_B;
        const int arow = t >> 2;          // 0..63
        const int seg  = t & 3;           // 0..3 (16B segments of 64B row)
        #pragma unroll
        for (int it = 0; it < 2; it++) {
            int row = arow + it * 64;
            uint32_t d = st + (uint32_t)row * 80u + (uint32_t)seg * 16u;
            cp16(d,          g_qh + (size_t)(n0 + row) * CC + k0 + seg * 8);
            cp16(d + 10240u, g_ql + (size_t)(n0 + row) * CC + k0 + seg * 8);
        }
        {
            int row = t >> 2;             // 0..63
            uint32_t d = st + 20480u + (uint32_t)row * 80u + (uint32_t)seg * 16u;
            cp16(d,         g_kh + (size_t)(bk * HWs + hk0 + row) * CC + k0 + seg * 8);
            cp16(d + 5120u, g_kl + (size_t)(bk * HWs + hk0 + row) * CC + k0 + seg * 8);
        }
    };

    float acc[2][4][4];
    float rm[2][2] = {{-3.402823e38f, -3.402823e38f}, {-3.402823e38f, -3.402823e38f}};

    load_stage(0);
    cp_commit();

    for (int s = 0; s < NSTAGE; s++) {
        if ((s % 24) == 0) {
            #pragma unroll
            for (int mt = 0; mt < 2; mt++)
                #pragma unroll
                for (int j = 0; j < 4; j++)
                    #pragma unroll
                    for (int r = 0; r < 4; r++)
                        acc[mt][j][r] = 0.f;
        }
        if (s + 1 < NSTAGE) { load_stage(s + 1); cp_commit(); cp_wait<1>(); }
        else                { cp_wait<0>(); }
        __syncthreads();

        const uint32_t st = smbase + (uint32_t)(s & 1) * STAGE_B;
        #pragma unroll
        for (int k16 = 0; k16 < 2; k16++) {
            const int kb = k16 * 16;
            // B fragments: 4 n8-tiles, hi+lo.  x4 matrices: [n0-7@k0, n0-7@k8, n8-15@k0, n8-15@k8]
            uint32_t bh[8], bl[8];
            #pragma unroll
            for (int nt = 0; nt < 2; nt++) {
                uint32_t ba = st + 20480u
                    + (uint32_t)(warp_n * 32 + nt * 16 + (lid & 7) + ((lid >> 4) & 1) * 8) * 80u
                    + (uint32_t)(kb + ((lid >> 3) & 1) * 8) * 2u;
                ldsm4(&bh[nt * 4], ba);
                ldsm4(&bl[nt * 4], ba + 5120u);
            }
            #pragma unroll
            for (int mt = 0; mt < 2; mt++) {
                uint32_t ah[4], al[4];
                uint32_t aa = st
                    + (uint32_t)(warp_m * 32 + mt * 16 + (lid & 15)) * 80u
                    + (uint32_t)(kb + ((lid >> 4) & 1) * 8) * 2u;
                ldsm4(ah, aa);
                ldsm4(al, aa + 10240u);
                #pragma unroll
                for (int j = 0; j < 4; j++) {
                    const uint32_t* bhp = &bh[(j >> 1) * 4 + (j & 1) * 2];
                    const uint32_t* blp = &bl[(j >> 1) * 4 + (j & 1) * 2];
                    mma16816(acc[mt][j], ah, bhp);
                    mma16816(acc[mt][j], ah, blp);
                    mma16816(acc[mt][j], al, bhp);
                }
            }
        }

        if ((s % 24) == 23) {
            // fold 32x32 accumulator tile into running row maxima
            #pragma unroll
            for (int mt = 0; mt < 2; mt++) {
                float m0 = -3.402823e38f, m1 = -3.402823e38f;
                #pragma unroll
                for (int j = 0; j < 4; j++) {
                    m0 = fmaxf(m0, fmaxf(acc[mt][j][0], acc[mt][j][1]));
                    m1 = fmaxf(m1, fmaxf(acc[mt][j][2], acc[mt][j][3]));
                }
                m0 = fmaxf(m0, __shfl_xor_sync(0xffffffffu, m0, 1));
                m0 = fmaxf(m0, __shfl_xor_sync(0xffffffffu, m0, 2));
                m1 = fmaxf(m1, __shfl_xor_sync(0xffffffffu, m1, 1));
                m1 = fmaxf(m1, __shfl_xor_sync(0xffffffffu, m1, 2));
                rm[mt][0] = fmaxf(rm[mt][0], m0);
                rm[mt][1] = fmaxf(rm[mt][1], m1);
            }
        }
        __syncthreads();
    }

    if ((lid & 3) == 0) {
        #pragma unroll
        for (int mt = 0; mt < 2; mt++) {
            int r = warp_m * 32 + mt * 16 + (lid >> 2);
            srow[warp_n][r]     = rm[mt][0];
            srow[warp_n][r + 8] = rm[mt][1];
        }
    }
    __syncthreads();
    if (t < 128)
        g_maxpart[bk * NTOK + n0 + t] = fmaxf(srow[0][t], srow[1][t]);
}

// ---------------------------------------------------------------------------
// GEMM: Y[b,o,hw] = sum_c W[o,c] * X[b,c,hw] + bias[o] (+ residual)
// 64x64 tile, BK=32, 256 threads, 4x4 microtile.
// ---------------------------------------------------------------------------
__global__ void gemm_kernel(const float* __restrict__ Xin, int src_sel, int dst_sel,
                            const float* __restrict__ W, const float* __restrict__ bias,
                            int residual)
{
    const float* X = (src_sel == 0) ? Xin : (src_sel == 1 ? g_cur : g_x5);
    float* Y = (dst_sel == 0) ? g_x5 : (dst_sel == 1 ? g_q : g_k);

    const int b  = blockIdx.z;
    const int o0 = blockIdx.y * 64;
    const int n0 = blockIdx.x * 64;
    const float* Xb = X + b * CC * HWs;

    __shared__ float Ws[32][68];
    __shared__ float Xs[32][68];

    const int t  = threadIdx.x;
    const int ty = t >> 4;
    const int tx = t & 15;

    float acc[4][4] = {};

    for (int k0 = 0; k0 < CC; k0 += 32) {
        {
            int oo = t >> 2;
            int kk = (t & 3) << 3;
            float4 w4a = *(const float4*)(W + (o0 + oo) * CC + k0 + kk);
            float4 w4b = *(const float4*)(W + (o0 + oo) * CC + k0 + kk + 4);
            Ws[kk + 0][oo] = w4a.x; Ws[kk + 1][oo] = w4a.y;
            Ws[kk + 2][oo] = w4a.z; Ws[kk + 3][oo] = w4a.w;
            Ws[kk + 4][oo] = w4b.x; Ws[kk + 5][oo] = w4b.y;
            Ws[kk + 6][oo] = w4b.z; Ws[kk + 7][oo] = w4b.w;
        }
        {
            int kk = t >> 4;
            int nn = (t & 15) << 2;
            *(float4*)&Xs[kk][nn]      = *(const float4*)(Xb + (k0 + kk)      * HWs + n0 + nn);
            *(float4*)&Xs[kk + 16][nn] = *(const float4*)(Xb + (k0 + kk + 16) * HWs + n0 + nn);
        }
        __syncthreads();

        #pragma unroll
        for (int kk = 0; kk < 32; kk++) {
            float4 a4 = *(float4*)&Ws[kk][ty << 2];
            float4 b4 = *(float4*)&Xs[kk][tx << 2];
            float av[4] = {a4.x, a4.y, a4.z, a4.w};
            float bv[4] = {b4.x, b4.y, b4.z, b4.w};
            #pragma unroll
            for (int i = 0; i < 4; i++)
                #pragma unroll
                for (int j = 0; j < 4; j++)
                    acc[i][j] = fmaf(av[i], bv[j], acc[i][j]);
        }
        __syncthreads();
    }

    #pragma unroll
    for (int i = 0; i < 4; i++) {
        int o = o0 + (ty << 2) + i;
        float bs = bias[o];
        #pragma unroll
        for (int j = 0; j < 4; j++) {
            int n = n0 + (tx << 2) + j;
            float v = acc[i][j] + bs;
            if (residual) v += Xb[o * HWs + n];
            Y[b * CC * HWs + o * HWs + n] = v;
        }
    }
}

// ---------------------------------------------------------------------------
__global__ void argmax_kernel()
{
    const int b = blockIdx.x;
    const int tid = threadIdx.x;
    __shared__ float sv[256];
    __shared__ int   si[256];

    float best = -3.402823e38f;
    int   bidx = 0;
    for (int hw = tid; hw < HWs; hw += 256) {
        float s = 0.f;
        #pragma unroll
        for (int bk = 0; bk < BB; bk++)
            s += g_maxpart[bk * NTOK + b * HWs + hw];
        if (s > best) { best = s; bidx = hw; }
    }
    sv[tid] = best; si[tid] = bidx;
    __syncthreads();
    for (int s = 128; s > 0; s >>= 1) {
        if (tid < s) {
            if (sv[tid + s] > sv[tid] ||
                (sv[tid + s] == sv[tid] && si[tid + s] < si[tid])) {
                sv[tid] = sv[tid + s];
                si[tid] = si[tid + s];
            }
        }
        __syncthreads();
    }
    if (tid == 0) g_hwstar[b] = si[0];
}

__global__ void norm_kernel()
{
    int p = blockIdx.x * blockDim.x + threadIdx.x;
    if (p >= NTOK) return;
    int b = p / HWs, hw = p % HWs;
    const float* xp = g_x5 + b * CC * HWs + hw;
    float s = 0.f;
    #pragma unroll 8
    for (int c = 0; c < CC; c++) {
        float v = xp[c * HWs];
        s = fmaf(v, v, s);
    }
    g_norm[p] = fmaxf(sqrtf(s), 1e-12f);
}

__global__ void seeds_kernel()
{
    int b = blockIdx.x;
    int c = threadIdx.x;
    int hws = g_hwstar[b];
    float inv = 1.f / g_norm[b * HWs + hws];
    g_seeds[b * CC + c] = g_x5[b * CC * HWs + c * HWs + hws] * inv;
}

__global__ void cor_kernel()
{
    __shared__ float ss[BB * CC];
    const int b = blockIdx.x;
    for (int i = threadIdx.x; i < BB * CC; i += blockDim.x) ss[i] = g_seeds[i];
    __syncthreads();

    const int hw = blockIdx.y * 192 + threadIdx.x;
    const float* xp = g_x5 + b * CC * HWs + hw;
    float acc[BB] = {};
    for (int c = 0; c < CC; c++) {
        float v = xp[c * HWs];
        #pragma unroll
        for (int o = 0; o < BB; o++)
            acc[o] = fmaf(v, ss[o * CC + c], acc[o]);
    }
    float s = 0.f;
    #pragma unroll
    for (int o = 0; o < BB; o++) s += fmaxf(acc[o], 0.f);
    g_cor[b * HWs + hw] = s / (16.f * g_norm[b * HWs + hw]);
}

__global__ void minmax_kernel()
{
    const int b = blockIdx.x;
    const int tid = threadIdx.x;
    __shared__ float smn[256], smx[256];
    float mn = 3.402823e38f, mx = -3.402823e38f;
    for (int hw = tid; hw < HWs; hw += 256) {
        float v = g_cor[b * HWs + hw];
        mn = fminf(mn, v);
        mx = fmaxf(mx, v);
    }
    smn[tid] = mn; smx[tid] = mx;
    __syncthreads();
    for (int s = 128; s > 0; s >>= 1) {
        if (tid < s) {
            smn[tid] = fminf(smn[tid], smn[tid + s]);
            smx[tid] = fmaxf(smx[tid], smx[tid + s]);
        }
        __syncthreads();
    }
    float m0 = smn[0];
    float inv = 1.f / (smx[0] - m0 + 1e-12f);
    for (int hw = tid; hw < HWs; hw += 256)
        g_cor[b * HWs + hw] = (g_cor[b * HWs + hw] - m0) * inv;
}

__global__ void apply_kernel(int add_prev)
{
    int idx = blockIdx.x * 256 + threadIdx.x;
    int b  = idx / (CC * HWs);
    int hw = idx % HWs;
    float v = g_x5[idx] * g_cor[b * HWs + hw];
    g_cur[idx] = (add_prev ? g_cur[idx] : 0.f) + v;
}

__global__ void consen_kernel()
{
    const int c = blockIdx.x;
    const int tid = threadIdx.x;
    __shared__ float sm[256];
    float s = 0.f;
    for (int b = 0; b < BB; b++) {
        const float* p = g_cur + b * CC * HWs + c * HWs;
        for (int hw = tid; hw < HWs; hw += 256) s += p[hw];
    }
    sm[tid] = s;
    __syncthreads();
    for (int st = 128; st > 0; st >>= 1) {
        if (tid < st) sm[tid] += sm[tid + st];
        __syncthreads();
    }
    if (tid == 0) g_consen[c] = sm[0] * (1.f / (float)(BB * HWs));
}

__global__ void final_kernel(const float* __restrict__ xin, float* __restrict__ out)
{
    int idx = blockIdx.x * 256 + threadIdx.x;
    int c = (idx / HWs) % CC;
    out[idx] = g_cur[idx] + xin[idx] * g_consen[c];
}

// ---------------------------------------------------------------------------
extern "C" void kernel_launch(void* const* d_in, const int* in_sizes, int n_in,
                              void* d_out, int out_size)
{
    const float* x5      = (const float*)d_in[0];
    const float* conv_w  = (const float*)d_in[1];
    const float* conv_b  = (const float*)d_in[2];
    const float* query_w = (const float*)d_in[3];
    const float* query_b = (const float*)d_in[4];
    const float* key_w   = (const float*)d_in[5];
    const float* key_b   = (const float*)d_in[6];
    float* out = (float*)d_out;

    cudaFuncSetAttribute(attn_mma_kernel,
                         cudaFuncAttributeMaxDynamicSharedMemorySize, ATT_DYN);

    dim3 ggrid(HWs / 64, CC / 64, BB);      // (9, 12, 16)
    dim3 cvgrid(HWs / 32, CC / 32, 32);     // (18, 24, 32)
    dim3 agrid(NTOK / 128, BB);             // (72, 16)
    dim3 cgrid(BB, HWs / 192);              // (16, 3)
    const int egrid = ELEMS / 256;          // 27648

    for (int i = 0; i < NLAYER; i++) {
        gemm_kernel<<<ggrid, 256>>>((i == 0) ? x5 : nullptr, (i == 0) ? 0 : 1, 0,
                                    conv_w + i * CC * CC, conv_b + i * CC, 1);
        gemm_kernel<<<ggrid, 256>>>(nullptr, 2, 1,
                                    query_w + i * CC * CC, query_b + i * CC, 0);
        gemm_kernel<<<ggrid, 256>>>(nullptr, 2, 2,
                                    key_w + i * CC * CC, key_b + i * CC, 0);
        convert_qk_kernel<<<cvgrid, dim3(32, 8)>>>();
        attn_mma_kernel<<<agrid, 256, ATT_DYN>>>();
        argmax_kernel<<<BB, 256>>>();
        norm_kernel<<<NTOK / 256, 256>>>();
        seeds_kernel<<<BB, CC>>>();
        cor_kernel<<<cgrid, 192>>>();
        minmax_kernel<<<BB, 256>>>();
        apply_kernel<<<egrid, 256>>>(i > 0 ? 1 : 0);
    }
    consen_kernel<<<CC, 256>>>();
    final_kernel<<<egrid, 256>>>(x5, out);
}

// round 6
// speedup vs baseline: 3.0373x; 1.3111x over previous
#include <cuda_runtime.h>
#include <cuda_bf16.h>
#include <cstdint>

// Problem constants
#define BB   16
#define CC   768
#define HWs  576
#define NTOK (BB*HWs)          // 9216
#define ELEMS (BB*CC*HWs)      // 7,077,888
#define NLAYER 4

// Scratch (device globals; no allocation allowed)
__device__ float g_cur[ELEMS];
__device__ float g_x5[ELEMS];
__device__ float g_q[ELEMS];
__device__ float g_k[ELEMS];
__device__ __nv_bfloat16 g_qh[(size_t)NTOK*CC];
__device__ __nv_bfloat16 g_ql[(size_t)NTOK*CC];
__device__ __nv_bfloat16 g_kh[(size_t)NTOK*CC];
__device__ __nv_bfloat16 g_kl[(size_t)NTOK*CC];
__device__ __nv_bfloat16 g_xth[(size_t)NTOK*CC];   // GEMM B operand (X^T) hi
__device__ __nv_bfloat16 g_xtl[(size_t)NTOK*CC];   // lo
__device__ __nv_bfloat16 g_wh[(size_t)3*NLAYER*CC*CC];  // weights hi (conv|query|key)
__device__ __nv_bfloat16 g_wl[(size_t)3*NLAYER*CC*CC];  // weights lo
__device__ float g_maxpart[BB*NTOK];
__device__ int   g_hwstar[BB];
__device__ float g_norm[BB*HWs];
__device__ float g_seeds[BB*CC];
__device__ float g_cor[BB*HWs];
__device__ float g_consen[CC];

// ============================ PTX helpers (sm_80+ only) =====================
__device__ __forceinline__ uint32_t smem_u32(const void* p) {
    uint32_t a;
    asm("{ .reg .u64 t; cvta.to.shared.u64 t, %1; cvt.u32.u64 %0, t; }" : "=r"(a) : "l"(p));
    return a;
}
__device__ __forceinline__ void cp16(uint32_t d, const void* s) {
    asm volatile("cp.async.cg.shared.global [%0], [%1], 16;" :: "r"(d), "l"(s));
}
__device__ __forceinline__ void cp_commit() { asm volatile("cp.async.commit_group;"); }
template<int N> __device__ __forceinline__ void cp_wait() {
    asm volatile("cp.async.wait_group %0;" :: "n"(N));
}
__device__ __forceinline__ void ldsm4(uint32_t* r, uint32_t a) {
    asm volatile("ldmatrix.sync.aligned.m8n8.x4.shared.b16 {%0,%1,%2,%3}, [%4];"
                 : "=r"(r[0]), "=r"(r[1]), "=r"(r[2]), "=r"(r[3]) : "r"(a));
}
__device__ __forceinline__ void mma16816(float* d, const uint32_t* a, const uint32_t* b) {
    asm volatile("mma.sync.aligned.m16n8k16.row.col.f32.bf16.bf16.f32 "
                 "{%0,%1,%2,%3}, {%4,%5,%6,%7}, {%8,%9}, {%0,%1,%2,%3};"
                 : "+f"(d[0]), "+f"(d[1]), "+f"(d[2]), "+f"(d[3])
                 : "r"(a[0]), "r"(a[1]), "r"(a[2]), "r"(a[3]), "r"(b[0]), "r"(b[1]));
}

// Shared smem stage geometry (A:128 rows, B:64 rows, 32 k per stage, 80B rows)
#define STAGE_B 30720
#define DYN_SMEM (2*STAGE_B)     // 61440

// ---------------------------------------------------------------------------
// Weight conversion: fp32 [o][c] -> bf16 hi/lo, all 3 tensors x 4 layers.
// grid (9216, 3), block 256.
// ---------------------------------------------------------------------------
__global__ void convert_w_kernel(const float* __restrict__ cw,
                                 const float* __restrict__ qw,
                                 const float* __restrict__ kw)
{
    const int z = blockIdx.y;
    const float* src = (z == 0) ? cw : (z == 1 ? qw : kw);
    const size_t off = (size_t)z * NLAYER * CC * CC;
    const size_t idx = (size_t)blockIdx.x * 256 + threadIdx.x;
    float v = src[idx];
    __nv_bfloat16 h = __float2bfloat16(v);
    __nv_bfloat16 l = __float2bfloat16(v - __bfloat162float(h));
    g_wh[off + idx] = h;
    g_wl[off + idx] = l;
}

// ---------------------------------------------------------------------------
// X conversion+transpose: src [b][c][hw] fp32 -> g_xt [b*HW+hw][c] bf16 hi/lo.
// src_sel: 0 ext, 1 g_cur, 2 g_x5.  grid (18, 24, 16), block (32,8).
// ---------------------------------------------------------------------------
__global__ void convert_x_kernel(const float* __restrict__ ext, int src_sel)
{
    __shared__ float tile[32][33];
    const int b = blockIdx.z;
    const float* src = ((src_sel == 0) ? ext : (src_sel == 1 ? g_cur : g_x5))
                       + (size_t)b * CC * HWs;
    const int hw0 = blockIdx.x * 32;
    const int c0  = blockIdx.y * 32;
    const int tx = threadIdx.x, ty = threadIdx.y;

    #pragma unroll
    for (int j = 0; j < 4; j++) {
        int c = ty * 4 + j;
        tile[c][tx] = src[(size_t)(c0 + c) * HWs + hw0 + tx];
    }
    __syncthreads();
    #pragma unroll
    for (int j = 0; j < 4; j++) {
        int hwl = ty * 4 + j;
        float v = tile[tx][hwl];
        __nv_bfloat16 h = __float2bfloat16(v);
        __nv_bfloat16 l = __float2bfloat16(v - __bfloat162float(h));
        size_t o = (size_t)(b * HWs + hw0 + hwl) * CC + c0 + tx;
        g_xth[o] = h;
        g_xtl[o] = l;
    }
}

// ---------------------------------------------------------------------------
// convert+transpose: q,k [b][c][hw] fp32 -> [n][c] bf16 hi/lo (for attention).
// grid (18, 24, 32). block (32,8).
// ---------------------------------------------------------------------------
__global__ void convert_qk_kernel()
{
    __shared__ float tile[32][33];
    const int z = blockIdx.z;
    const int b = z & 15;
    const float* src = ((z < 16) ? g_q : g_k) + (size_t)b * CC * HWs;
    __nv_bfloat16* dh = (z < 16) ? g_qh : g_kh;
    __nv_bfloat16* dl = (z < 16) ? g_ql : g_kl;
    const int hw0 = blockIdx.x * 32;
    const int c0  = blockIdx.y * 32;
    const int tx = threadIdx.x, ty = threadIdx.y;

    #pragma unroll
    for (int j = 0; j < 4; j++) {
        int c = ty * 4 + j;
        tile[c][tx] = src[(size_t)(c0 + c) * HWs + hw0 + tx];
    }
    __syncthreads();
    #pragma unroll
    for (int j = 0; j < 4; j++) {
        int hwl = ty * 4 + j;
        float v = tile[tx][hwl];
        __nv_bfloat16 h = __float2bfloat16(v);
        __nv_bfloat16 l = __float2bfloat16(v - __bfloat162float(h));
        size_t o = (size_t)(b * HWs + hw0 + hwl) * CC + c0 + tx;
        dh[o] = h;
        dl[o] = l;
    }
}

// ---------------------------------------------------------------------------
// Split-bf16 mma.sync GEMM: Y[b,o,hw] = sum_c W[o,c] X[b,c,hw] + bias[o] (+res)
// A = W hi/lo [o][c] row-major, B = X^T hi/lo [n][c] (col-major for mma).
// CTA: 128 o x 64 hw; grid (9 hw-tiles, 6 o-tiles, 16 b). K=768 in 24 chunks,
// cp.async double-buffered; 3-pass split (hh + hl + lh).
// ---------------------------------------------------------------------------
__global__ void __launch_bounds__(256) gemm_mma_kernel(
    const __nv_bfloat16* __restrict__ Wh, const __nv_bfloat16* __restrict__ Wl,
    const float* __restrict__ bias, const float* __restrict__ resid, int residual,
    float* __restrict__ Y)
{
    extern __shared__ __align__(16) char sm[];
    const int t   = threadIdx.x;
    const int wid = t >> 5;
    const int lid = t & 31;
    const int n0  = blockIdx.x * 64;      // hw
    const int m0  = blockIdx.y * 128;     // o
    const int b   = blockIdx.z;
    const int warp_m = wid & 3;
    const int warp_n = wid >> 2;
    const uint32_t smbase = smem_u32(sm);

    auto load_stage = [&](int s) {
        const int k0 = s * 32;
        const uint32_t st = smbase + (uint32_t)(s & 1) * STAGE_B;
        const int arow = t >> 2;
        const int seg  = t & 3;
        #pragma unroll
        for (int it = 0; it < 2; it++) {
            int row = arow + it * 64;
            uint32_t d = st + (uint32_t)row * 80u + (uint32_t)seg * 16u;
            cp16(d,          Wh + (size_t)(m0 + row) * CC + k0 + seg * 8);
            cp16(d + 10240u, Wl + (size_t)(m0 + row) * CC + k0 + seg * 8);
        }
        {
            int row = t >> 2;
            uint32_t d = st + 20480u + (uint32_t)row * 80u + (uint32_t)seg * 16u;
            cp16(d,         g_xth + (size_t)(b * HWs + n0 + row) * CC + k0 + seg * 8);
            cp16(d + 5120u, g_xtl + (size_t)(b * HWs + n0 + row) * CC + k0 + seg * 8);
        }
    };

    float acc[2][4][4];
    #pragma unroll
    for (int mt = 0; mt < 2; mt++)
        #pragma unroll
        for (int j = 0; j < 4; j++)
            #pragma unroll
            for (int r = 0; r < 4; r++)
                acc[mt][j][r] = 0.f;

    load_stage(0);
    cp_commit();

    for (int s = 0; s < 24; s++) {
        if (s + 1 < 24) { load_stage(s + 1); cp_commit(); cp_wait<1>(); }
        else            { cp_wait<0>(); }
        __syncthreads();

        const uint32_t st = smbase + (uint32_t)(s & 1) * STAGE_B;
        #pragma unroll
        for (int k16 = 0; k16 < 2; k16++) {
            const int kb = k16 * 16;
            uint32_t bh[8], bl[8];
            #pragma unroll
            for (int nt = 0; nt < 2; nt++) {
                uint32_t ba = st + 20480u
                    + (uint32_t)(warp_n * 32 + nt * 16 + (lid & 7) + ((lid >> 4) & 1) * 8) * 80u
                    + (uint32_t)(kb + ((lid >> 3) & 1) * 8) * 2u;
                ldsm4(&bh[nt * 4], ba);
                ldsm4(&bl[nt * 4], ba + 5120u);
            }
            #pragma unroll
            for (int mt = 0; mt < 2; mt++) {
                uint32_t ah[4], al[4];
                uint32_t aa = st
                    + (uint32_t)(warp_m * 32 + mt * 16 + (lid & 15)) * 80u
                    + (uint32_t)(kb + ((lid >> 4) & 1) * 8) * 2u;
                ldsm4(ah, aa);
                ldsm4(al, aa + 10240u);
                #pragma unroll
                for (int j = 0; j < 4; j++) {
                    const uint32_t* bhp = &bh[(j >> 1) * 4 + (j & 1) * 2];
                    const uint32_t* blp = &bl[(j >> 1) * 4 + (j & 1) * 2];
                    mma16816(acc[mt][j], ah, bhp);
                    mma16816(acc[mt][j], ah, blp);
                    mma16816(acc[mt][j], al, bhp);
                }
            }
        }
        __syncthreads();
    }

    // epilogue: acc(mt,j,r) -> Y[o][hw], + bias, + optional residual
    const size_t Yb = (size_t)b * CC * HWs;
    #pragma unroll
    for (int mt = 0; mt < 2; mt++) {
        int R = m0 + warp_m * 32 + mt * 16 + (lid >> 2);
        float bs0 = bias[R], bs1 = bias[R + 8];
        #pragma unroll
        for (int j = 0; j < 4; j++) {
            int cb = n0 + warp_n * 32 + (j >> 1) * 16 + (j & 1) * 8 + (lid & 3) * 2;
            size_t a0 = Yb + (size_t)R * HWs + cb;
            size_t a1 = a0 + 8 * HWs;
            float2 v0 = make_float2(acc[mt][j][0] + bs0, acc[mt][j][1] + bs0);
            float2 v1 = make_float2(acc[mt][j][2] + bs1, acc[mt][j][3] + bs1);
            if (residual) {
                float2 r0 = *(const float2*)(resid + a0);
                float2 r1 = *(const float2*)(resid + a1);
                v0.x += r0.x; v0.y += r0.y;
                v1.x += r1.x; v1.y += r1.y;
            }
            *(float2*)(Y + a0) = v0;
            *(float2*)(Y + a1) = v1;
        }
    }
}

// ---------------------------------------------------------------------------
// mma.sync attention row-max (unchanged from R5 — validated).
// ---------------------------------------------------------------------------
#define NSTAGE  216              // 9 ct * 24 k-chunks

__global__ void __launch_bounds__(256) attn_mma_kernel()
{
    extern __shared__ __align__(16) char sm[];
    __shared__ float srow[2][128];

    const int t   = threadIdx.x;
    const int wid = t >> 5;
    const int lid = t & 31;
    const int n0  = blockIdx.x * 128;
    const int bk  = blockIdx.y;
    const int warp_m = wid & 3;
    const int warp_n = wid >> 2;
    const uint32_t smbase = smem_u32(sm);

    auto load_stage = [&](int s) {
        const int hk0 = (s / 24) * 64;
        const int k0  = (s % 24) * 32;
        const uint32_t st = smbase + (uint32_t)(s & 1) * STAGE_B;
        const int arow = t >> 2;
        const int seg  = t & 3;
        #pragma unroll
        for (int it = 0; it < 2; it++) {
            int row = arow + it * 64;
            uint32_t d = st + (uint32_t)row * 80u + (uint32_t)seg * 16u;
            cp16(d,          g_qh + (size_t)(n0 + row) * CC + k0 + seg * 8);
            cp16(d + 10240u, g_ql + (size_t)(n0 + row) * CC + k0 + seg * 8);
        }
        {
            int row = t >> 2;
            uint32_t d = st + 20480u + (uint32_t)row * 80u + (uint32_t)seg * 16u;
            cp16(d,         g_kh + (size_t)(bk * HWs + hk0 + row) * CC + k0 + seg * 8);
            cp16(d + 5120u, g_kl + (size_t)(bk * HWs + hk0 + row) * CC + k0 + seg * 8);
        }
    };

    float acc[2][4][4];
    float rm[2][2] = {{-3.402823e38f, -3.402823e38f}, {-3.402823e38f, -3.402823e38f}};

    load_stage(0);
    cp_commit();

    for (int s = 0; s < NSTAGE; s++) {
        if ((s % 24) == 0) {
            #pragma unroll
            for (int mt = 0; mt < 2; mt++)
                #pragma unroll
                for (int j = 0; j < 4; j++)
                    #pragma unroll
                    for (int r = 0; r < 4; r++)
                        acc[mt][j][r] = 0.f;
        }
        if (s + 1 < NSTAGE) { load_stage(s + 1); cp_commit(); cp_wait<1>(); }
        else                { cp_wait<0>(); }
        __syncthreads();

        const uint32_t st = smbase + (uint32_t)(s & 1) * STAGE_B;
        #pragma unroll
        for (int k16 = 0; k16 < 2; k16++) {
            const int kb = k16 * 16;
            uint32_t bh[8], bl[8];
            #pragma unroll
            for (int nt = 0; nt < 2; nt++) {
                uint32_t ba = st + 20480u
                    + (uint32_t)(warp_n * 32 + nt * 16 + (lid & 7) + ((lid >> 4) & 1) * 8) * 80u
                    + (uint32_t)(kb + ((lid >> 3) & 1) * 8) * 2u;
                ldsm4(&bh[nt * 4], ba);
                ldsm4(&bl[nt * 4], ba + 5120u);
            }
            #pragma unroll
            for (int mt = 0; mt < 2; mt++) {
                uint32_t ah[4], al[4];
                uint32_t aa = st
                    + (uint32_t)(warp_m * 32 + mt * 16 + (lid & 15)) * 80u
                    + (uint32_t)(kb + ((lid >> 4) & 1) * 8) * 2u;
                ldsm4(ah, aa);
                ldsm4(al, aa + 10240u);
                #pragma unroll
                for (int j = 0; j < 4; j++) {
                    const uint32_t* bhp = &bh[(j >> 1) * 4 + (j & 1) * 2];
                    const uint32_t* blp = &bl[(j >> 1) * 4 + (j & 1) * 2];
                    mma16816(acc[mt][j], ah, bhp);
                    mma16816(acc[mt][j], ah, blp);
                    mma16816(acc[mt][j], al, bhp);
                }
            }
        }

        if ((s % 24) == 23) {
            #pragma unroll
            for (int mt = 0; mt < 2; mt++) {
                float m0 = -3.402823e38f, m1 = -3.402823e38f;
                #pragma unroll
                for (int j = 0; j < 4; j++) {
                    m0 = fmaxf(m0, fmaxf(acc[mt][j][0], acc[mt][j][1]));
                    m1 = fmaxf(m1, fmaxf(acc[mt][j][2], acc[mt][j][3]));
                }
                m0 = fmaxf(m0, __shfl_xor_sync(0xffffffffu, m0, 1));
                m0 = fmaxf(m0, __shfl_xor_sync(0xffffffffu, m0, 2));
                m1 = fmaxf(m1, __shfl_xor_sync(0xffffffffu, m1, 1));
                m1 = fmaxf(m1, __shfl_xor_sync(0xffffffffu, m1, 2));
                rm[mt][0] = fmaxf(rm[mt][0], m0);
                rm[mt][1] = fmaxf(rm[mt][1], m1);
            }
        }
        __syncthreads();
    }

    if ((lid & 3) == 0) {
        #pragma unroll
        for (int mt = 0; mt < 2; mt++) {
            int r = warp_m * 32 + mt * 16 + (lid >> 2);
            srow[warp_n][r]     = rm[mt][0];
            srow[warp_n][r + 8] = rm[mt][1];
        }
    }
    __syncthreads();
    if (t < 128)
        g_maxpart[bk * NTOK + n0 + t] = fmaxf(srow[0][t], srow[1][t]);
}

// ---------------------------------------------------------------------------
__global__ void argmax_kernel()
{
    const int b = blockIdx.x;
    const int tid = threadIdx.x;
    __shared__ float sv[256];
    __shared__ int   si[256];

    float best = -3.402823e38f;
    int   bidx = 0;
    for (int hw = tid; hw < HWs; hw += 256) {
        float s = 0.f;
        #pragma unroll
        for (int bk = 0; bk < BB; bk++)
            s += g_maxpart[bk * NTOK + b * HWs + hw];
        if (s > best) { best = s; bidx = hw; }
    }
    sv[tid] = best; si[tid] = bidx;
    __syncthreads();
    for (int s = 128; s > 0; s >>= 1) {
        if (tid < s) {
            if (sv[tid + s] > sv[tid] ||
                (sv[tid + s] == sv[tid] && si[tid + s] < si[tid])) {
                sv[tid] = sv[tid + s];
                si[tid] = si[tid + s];
            }
        }
        __syncthreads();
    }
    if (tid == 0) g_hwstar[b] = si[0];
}

__global__ void norm_kernel()
{
    int p = blockIdx.x * blockDim.x + threadIdx.x;
    if (p >= NTOK) return;
    int b = p / HWs, hw = p % HWs;
    const float* xp = g_x5 + b * CC * HWs + hw;
    float s = 0.f;
    #pragma unroll 8
    for (int c = 0; c < CC; c++) {
        float v = xp[c * HWs];
        s = fmaf(v, v, s);
    }
    g_norm[p] = fmaxf(sqrtf(s), 1e-12f);
}

__global__ void seeds_kernel()
{
    int b = blockIdx.x;
    int c = threadIdx.x;
    int hws = g_hwstar[b];
    float inv = 1.f / g_norm[b * HWs + hws];
    g_seeds[b * CC + c] = g_x5[b * CC * HWs + c * HWs + hws] * inv;
}

__global__ void cor_kernel()
{
    __shared__ float ss[BB * CC];
    const int b = blockIdx.x;
    for (int i = threadIdx.x; i < BB * CC; i += blockDim.x) ss[i] = g_seeds[i];
    __syncthreads();

    const int hw = blockIdx.y * 192 + threadIdx.x;
    const float* xp = g_x5 + b * CC * HWs + hw;
    float acc[BB] = {};
    for (int c = 0; c < CC; c++) {
        float v = xp[c * HWs];
        #pragma unroll
        for (int o = 0; o < BB; o++)
            acc[o] = fmaf(v, ss[o * CC + c], acc[o]);
    }
    float s = 0.f;
    #pragma unroll
    for (int o = 0; o < BB; o++) s += fmaxf(acc[o], 0.f);
    g_cor[b * HWs + hw] = s / (16.f * g_norm[b * HWs + hw]);
}

__global__ void minmax_kernel()
{
    const int b = blockIdx.x;
    const int tid = threadIdx.x;
    __shared__ float smn[256], smx[256];
    float mn = 3.402823e38f, mx = -3.402823e38f;
    for (int hw = tid; hw < HWs; hw += 256) {
        float v = g_cor[b * HWs + hw];
        mn = fminf(mn, v);
        mx = fmaxf(mx, v);
    }
    smn[tid] = mn; smx[tid] = mx;
    __syncthreads();
    for (int s = 128; s > 0; s >>= 1) {
        if (tid < s) {
            smn[tid] = fminf(smn[tid], smn[tid + s]);
            smx[tid] = fmaxf(smx[tid], smx[tid + s]);
        }
        __syncthreads();
    }
    float m0 = smn[0];
    float inv = 1.f / (smx[0] - m0 + 1e-12f);
    for (int hw = tid; hw < HWs; hw += 256)
        g_cor[b * HWs + hw] = (g_cor[b * HWs + hw] - m0) * inv;
}

__global__ void apply_kernel(int add_prev)
{
    int idx = blockIdx.x * 256 + threadIdx.x;
    int b  = idx / (CC * HWs);
    int hw = idx % HWs;
    float v = g_x5[idx] * g_cor[b * HWs + hw];
    g_cur[idx] = (add_prev ? g_cur[idx] : 0.f) + v;
}

__global__ void consen_kernel()
{
    const int c = blockIdx.x;
    const int tid = threadIdx.x;
    __shared__ float sm[256];
    float s = 0.f;
    for (int b = 0; b < BB; b++) {
        const float* p = g_cur + b * CC * HWs + c * HWs;
        for (int hw = tid; hw < HWs; hw += 256) s += p[hw];
    }
    sm[tid] = s;
    __syncthreads();
    for (int st = 128; st > 0; st >>= 1) {
        if (tid < st) sm[tid] += sm[tid + st];
        __syncthreads();
    }
    if (tid == 0) g_consen[c] = sm[0] * (1.f / (float)(BB * HWs));
}

__global__ void final_kernel(const float* __restrict__ xin, float* __restrict__ out)
{
    int idx = blockIdx.x * 256 + threadIdx.x;
    int c = (idx / HWs) % CC;
    out[idx] = g_cur[idx] + xin[idx] * g_consen[c];
}

// ---------------------------------------------------------------------------
extern "C" void kernel_launch(void* const* d_in, const int* in_sizes, int n_in,
                              void* d_out, int out_size)
{
    const float* x5      = (const float*)d_in[0];
    const float* conv_w  = (const float*)d_in[1];
    const float* conv_b  = (const float*)d_in[2];
    const float* query_w = (const float*)d_in[3];
    const float* query_b = (const float*)d_in[4];
    const float* key_w   = (const float*)d_in[5];
    const float* key_b   = (const float*)d_in[6];
    float* out = (float*)d_out;

    static bool attr_done = false;
    cudaFuncSetAttribute(attn_mma_kernel,
                         cudaFuncAttributeMaxDynamicSharedMemorySize, DYN_SMEM);
    cudaFuncSetAttribute(gemm_mma_kernel,
                         cudaFuncAttributeMaxDynamicSharedMemorySize, DYN_SMEM);
    (void)attr_done;

    // device-global symbol addresses (host-side)
    __nv_bfloat16 *wh_p, *wl_p;
    cudaGetSymbolAddress((void**)&wh_p, g_wh);
    cudaGetSymbolAddress((void**)&wl_p, g_wl);
    float *x5g_p, *cur_p, *q_p, *k_p;
    cudaGetSymbolAddress((void**)&x5g_p, g_x5);
    cudaGetSymbolAddress((void**)&cur_p, g_cur);
    cudaGetSymbolAddress((void**)&q_p, g_q);
    cudaGetSymbolAddress((void**)&k_p, g_k);

    dim3 wgrid(NLAYER * CC * CC / 256, 3);  // (9216, 3)
    dim3 xgrid(HWs / 32, CC / 32, BB);      // (18, 24, 16)
    dim3 cvgrid(HWs / 32, CC / 32, 32);     // (18, 24, 32)
    dim3 mgrid(HWs / 64, CC / 128, BB);     // (9, 6, 16)
    dim3 agrid(NTOK / 128, BB);             // (72, 16)
    dim3 cgrid(BB, HWs / 192);              // (16, 3)
    const int egrid = ELEMS / 256;          // 27648

    convert_w_kernel<<<wgrid, 256>>>(conv_w, query_w, key_w);

    const size_t WSZ = (size_t)CC * CC;
    for (int i = 0; i < NLAYER; i++) {
        // x5 = conv(cur) + bias + cur
        convert_x_kernel<<<xgrid, dim3(32, 8)>>>(x5, (i == 0) ? 0 : 1);
        gemm_mma_kernel<<<mgrid, 256, DYN_SMEM>>>(
            wh_p + i * WSZ, wl_p + i * WSZ, conv_b + i * CC,
            (i == 0) ? x5 : cur_p, 1, x5g_p);
        // q, k from x5
        convert_x_kernel<<<xgrid, dim3(32, 8)>>>(nullptr, 2);
        gemm_mma_kernel<<<mgrid, 256, DYN_SMEM>>>(
            wh_p + (NLAYER + i) * WSZ, wl_p + (NLAYER + i) * WSZ, query_b + i * CC,
            x5g_p, 0, q_p);
        gemm_mma_kernel<<<mgrid, 256, DYN_SMEM>>>(
            wh_p + (2 * NLAYER + i) * WSZ, wl_p + (2 * NLAYER + i) * WSZ, key_b + i * CC,
            x5g_p, 0, k_p);
        convert_qk_kernel<<<cvgrid, dim3(32, 8)>>>();
        attn_mma_kernel<<<agrid, 256, DYN_SMEM>>>();
        argmax_kernel<<<BB, 256>>>();
        norm_kernel<<<NTOK / 256, 256>>>();
        seeds_kernel<<<BB, CC>>>();
        cor_kernel<<<cgrid, 192>>>();
        minmax_kernel<<<BB, 256>>>();
        apply_kernel<<<egrid, 256>>>(i > 0 ? 1 : 0);
    }
    consen_kernel<<<CC, 256>>>();
    final_kernel<<<egrid, 256>>>(x5, out);
}

// round 7
// speedup vs baseline: 3.1913x; 1.0507x over previous
#include <cuda_runtime.h>
#include <cuda_bf16.h>
#include <cstdint>

// Problem constants
#define BB   16
#define CC   768
#define HWs  576
#define NTOK (BB*HWs)          // 9216
#define ELEMS (BB*CC*HWs)      // 7,077,888
#define NLAYER 4

// Scratch (device globals; no allocation allowed)
__device__ float g_cur[ELEMS];
__device__ float g_x5[ELEMS];
__device__ __nv_bfloat16 g_qh[(size_t)NTOK*CC];
__device__ __nv_bfloat16 g_ql[(size_t)NTOK*CC];
__device__ __nv_bfloat16 g_kh[(size_t)NTOK*CC];
__device__ __nv_bfloat16 g_kl[(size_t)NTOK*CC];
__device__ __nv_bfloat16 g_xth[(size_t)NTOK*CC];    // layer input (cur) transposed hi
__device__ __nv_bfloat16 g_xtl[(size_t)NTOK*CC];    // lo
__device__ __nv_bfloat16 g_x5th[(size_t)NTOK*CC];   // x5 transposed hi (conv output)
__device__ __nv_bfloat16 g_x5tl[(size_t)NTOK*CC];   // lo
__device__ __nv_bfloat16 g_wh[(size_t)3*NLAYER*CC*CC];
__device__ __nv_bfloat16 g_wl[(size_t)3*NLAYER*CC*CC];
__device__ float g_maxpart[BB*NTOK];
__device__ int   g_hwstar[BB];
__device__ float g_norm[BB*HWs];
__device__ float g_seeds[BB*CC];
__device__ float g_cor[BB*HWs];
__device__ float g_consen[CC];

// ============================ PTX helpers (sm_80+ only) =====================
__device__ __forceinline__ uint32_t smem_u32(const void* p) {
    uint32_t a;
    asm("{ .reg .u64 t; cvta.to.shared.u64 t, %1; cvt.u32.u64 %0, t; }" : "=r"(a) : "l"(p));
    return a;
}
__device__ __forceinline__ void cp16(uint32_t d, const void* s) {
    asm volatile("cp.async.cg.shared.global [%0], [%1], 16;" :: "r"(d), "l"(s));
}
__device__ __forceinline__ void cp_commit() { asm volatile("cp.async.commit_group;"); }
template<int N> __device__ __forceinline__ void cp_wait() {
    asm volatile("cp.async.wait_group %0;" :: "n"(N));
}
__device__ __forceinline__ void ldsm4(uint32_t* r, uint32_t a) {
    asm volatile("ldmatrix.sync.aligned.m8n8.x4.shared.b16 {%0,%1,%2,%3}, [%4];"
                 : "=r"(r[0]), "=r"(r[1]), "=r"(r[2]), "=r"(r[3]) : "r"(a));
}
__device__ __forceinline__ void mma16816(float* d, const uint32_t* a, const uint32_t* b) {
    asm volatile("mma.sync.aligned.m16n8k16.row.col.f32.bf16.bf16.f32 "
                 "{%0,%1,%2,%3}, {%4,%5,%6,%7}, {%8,%9}, {%0,%1,%2,%3};"
                 : "+f"(d[0]), "+f"(d[1]), "+f"(d[2]), "+f"(d[3])
                 : "r"(a[0]), "r"(a[1]), "r"(a[2]), "r"(a[3]), "r"(b[0]), "r"(b[1]));
}

// gemm stage geometry (A:128 rows, B:64 rows, 32 k per stage, 80B rows)
#define STAGE_B 30720
#define GEMM_DYN (2*STAGE_B)     // 61440

// ---------------------------------------------------------------------------
// Weight conversion: fp32 [o][c] -> bf16 hi/lo.  grid (9216, 3), block 256.
// ---------------------------------------------------------------------------
__global__ void convert_w_kernel(const float* __restrict__ cw,
                                 const float* __restrict__ qw,
                                 const float* __restrict__ kw)
{
    const int z = blockIdx.y;
    const float* src = (z == 0) ? cw : (z == 1 ? qw : kw);
    const size_t off = (size_t)z * NLAYER * CC * CC;
    const size_t idx = (size_t)blockIdx.x * 256 + threadIdx.x;
    float v = src[idx];
    __nv_bfloat16 h = __float2bfloat16(v);
    __nv_bfloat16 l = __float2bfloat16(v - __bfloat162float(h));
    g_wh[off + idx] = h;
    g_wl[off + idx] = l;
}

// ---------------------------------------------------------------------------
// Layer-input conversion+transpose: src [b][c][hw] fp32 -> g_xt [n][c] bf16.
// src_sel: 0 ext, 1 g_cur.  grid (18, 24, 16), block (32,8).
// ---------------------------------------------------------------------------
__global__ void convert_x_kernel(const float* __restrict__ ext, int src_sel)
{
    __shared__ float tile[32][33];
    const int b = blockIdx.z;
    const float* src = ((src_sel == 0) ? ext : g_cur) + (size_t)b * CC * HWs;
    const int hw0 = blockIdx.x * 32;
    const int c0  = blockIdx.y * 32;
    const int tx = threadIdx.x, ty = threadIdx.y;

    #pragma unroll
    for (int j = 0; j < 4; j++) {
        int c = ty * 4 + j;
        tile[c][tx] = src[(size_t)(c0 + c) * HWs + hw0 + tx];
    }
    __syncthreads();
    #pragma unroll
    for (int j = 0; j < 4; j++) {
        int hwl = ty * 4 + j;
        float v = tile[tx][hwl];
        __nv_bfloat16 h = __float2bfloat16(v);
        __nv_bfloat16 l = __float2bfloat16(v - __bfloat162float(h));
        size_t o = (size_t)(b * HWs + hw0 + hwl) * CC + c0 + tx;
        g_xth[o] = h;
        g_xtl[o] = l;
    }
}

// ---------------------------------------------------------------------------
// Split-bf16 mma.sync GEMM with fused bf16 hi/lo transposed output.
// Y[b,o,hw] = sum_c W[o,c] X[b,c,hw] + bias[o] (+res).
// Epilogue always writes dh/dl[(b*HWs+hw)*CC + o] (bf16 hi/lo);
// optionally also Y fp32 and residual add.
// CTA: 128 o x 64 hw; grid (9, 6, 16). 256 threads.
// ---------------------------------------------------------------------------
__global__ void __launch_bounds__(256) gemm_mma_kernel(
    const __nv_bfloat16* __restrict__ Wh, const __nv_bfloat16* __restrict__ Wl,
    const __nv_bfloat16* __restrict__ Bh, const __nv_bfloat16* __restrict__ Bl,
    const float* __restrict__ bias, const float* __restrict__ resid, int residual,
    float* __restrict__ Y, int write_f32,
    __nv_bfloat16* __restrict__ dh, __nv_bfloat16* __restrict__ dl)
{
    extern __shared__ __align__(16) char sm[];
    const int t   = threadIdx.x;
    const int wid = t >> 5;
    const int lid = t & 31;
    const int n0  = blockIdx.x * 64;      // hw
    const int m0  = blockIdx.y * 128;     // o
    const int b   = blockIdx.z;
    const int warp_m = wid & 3;
    const int warp_n = wid >> 2;
    const uint32_t smbase = smem_u32(sm);

    auto load_stage = [&](int s) {
        const int k0 = s * 32;
        const uint32_t st = smbase + (uint32_t)(s & 1) * STAGE_B;
        const int arow = t >> 2;
        const int seg  = t & 3;
        #pragma unroll
        for (int it = 0; it < 2; it++) {
            int row = arow + it * 64;
            uint32_t d = st + (uint32_t)row * 80u + (uint32_t)seg * 16u;
            cp16(d,          Wh + (size_t)(m0 + row) * CC + k0 + seg * 8);
            cp16(d + 10240u, Wl + (size_t)(m0 + row) * CC + k0 + seg * 8);
        }
        {
            int row = t >> 2;
            uint32_t d = st + 20480u + (uint32_t)row * 80u + (uint32_t)seg * 16u;
            cp16(d,         Bh + (size_t)(b * HWs + n0 + row) * CC + k0 + seg * 8);
            cp16(d + 5120u, Bl + (size_t)(b * HWs + n0 + row) * CC + k0 + seg * 8);
        }
    };

    float acc[2][4][4];
    #pragma unroll
    for (int mt = 0; mt < 2; mt++)
        #pragma unroll
        for (int j = 0; j < 4; j++)
            #pragma unroll
            for (int r = 0; r < 4; r++)
                acc[mt][j][r] = 0.f;

    load_stage(0);
    cp_commit();

    for (int s = 0; s < 24; s++) {
        if (s + 1 < 24) { load_stage(s + 1); cp_commit(); cp_wait<1>(); }
        else            { cp_wait<0>(); }
        __syncthreads();

        const uint32_t st = smbase + (uint32_t)(s & 1) * STAGE_B;
        #pragma unroll
        for (int k16 = 0; k16 < 2; k16++) {
            const int kb = k16 * 16;
            uint32_t bh[8], bl[8];
            #pragma unroll
            for (int nt = 0; nt < 2; nt++) {
                uint32_t ba = st + 20480u
                    + (uint32_t)(warp_n * 32 + nt * 16 + (lid & 7) + ((lid >> 4) & 1) * 8) * 80u
                    + (uint32_t)(kb + ((lid >> 3) & 1) * 8) * 2u;
                ldsm4(&bh[nt * 4], ba);
                ldsm4(&bl[nt * 4], ba + 5120u);
            }
            #pragma unroll
            for (int mt = 0; mt < 2; mt++) {
                uint32_t ah[4], al[4];
                uint32_t aa = st
                    + (uint32_t)(warp_m * 32 + mt * 16 + (lid & 15)) * 80u
                    + (uint32_t)(kb + ((lid >> 4) & 1) * 8) * 2u;
                ldsm4(ah, aa);
                ldsm4(al, aa + 10240u);
                #pragma unroll
                for (int j = 0; j < 4; j++) {
                    const uint32_t* bhp = &bh[(j >> 1) * 4 + (j & 1) * 2];
                    const uint32_t* blp = &bl[(j >> 1) * 4 + (j & 1) * 2];
                    mma16816(acc[mt][j], ah, bhp);
                    mma16816(acc[mt][j], ah, blp);
                    mma16816(acc[mt][j], al, bhp);
                }
            }
        }
        __syncthreads();
    }

    // epilogue
    const size_t Yb = (size_t)b * CC * HWs;
    const int nb = b * HWs;
    #pragma unroll
    for (int mt = 0; mt < 2; mt++) {
        int R = m0 + warp_m * 32 + mt * 16 + (lid >> 2);
        float bs0 = bias[R], bs1 = bias[R + 8];
        #pragma unroll
        for (int j = 0; j < 4; j++) {
            int cb = n0 + warp_n * 32 + (j >> 1) * 16 + (j & 1) * 8 + (lid & 3) * 2;
            float v00 = acc[mt][j][0] + bs0, v01 = acc[mt][j][1] + bs0;
            float v10 = acc[mt][j][2] + bs1, v11 = acc[mt][j][3] + bs1;
            size_t a0 = Yb + (size_t)R * HWs + cb;
            size_t a1 = a0 + 8 * HWs;
            if (residual) {
                float2 r0 = *(const float2*)(resid + a0);
                float2 r1 = *(const float2*)(resid + a1);
                v00 += r0.x; v01 += r0.y; v10 += r1.x; v11 += r1.y;
            }
            if (write_f32) {
                *(float2*)(Y + a0) = make_float2(v00, v01);
                *(float2*)(Y + a1) = make_float2(v10, v11);
            }
            // bf16 hi/lo transposed: dst[(nb+hw)*CC + o]
            size_t r0o = (size_t)(nb + cb) * CC;
            size_t r1o = r0o + CC;
            __nv_bfloat16 h;
            h = __float2bfloat16(v00); dh[r0o + R]     = h; dl[r0o + R]     = __float2bfloat16(v00 - __bfloat162float(h));
            h = __float2bfloat16(v01); dh[r1o + R]     = h; dl[r1o + R]     = __float2bfloat16(v01 - __bfloat162float(h));
            h = __float2bfloat16(v10); dh[r0o + R + 8] = h; dl[r0o + R + 8] = __float2bfloat16(v10 - __bfloat162float(h));
            h = __float2bfloat16(v11); dh[r1o + R + 8] = h; dl[r1o + R + 8] = __float2bfloat16(v11 - __bfloat162float(h));
        }
    }
}

// ---------------------------------------------------------------------------
// mma.sync attention row-max, retiled: CTA 128 q x 192 keys, 512 threads
// (warps 4x4, 32x48 each), 3 ct-tiles, 24 k-chunks, 3-stage cp.async ring,
// one __syncthreads per stage. 3-pass split (hh + hl + lh).
// grid (72 m-tiles, 16 bk).
// Stage: Ah[128][80B]@0 | Al@10240 | Bh[192][80B]@20480 | Bl@35840 = 51200 B.
// ---------------------------------------------------------------------------
#define A_STAGE 51200
#define A_DYN   (3*A_STAGE)      // 153600
#define A_NSTG  72               // 3 ct * 24 k-chunks

__global__ void __launch_bounds__(512, 1) attn_mma_kernel()
{
    extern __shared__ __align__(16) char sm[];
    __shared__ float srow[4][128];

    const int t   = threadIdx.x;
    const int wid = t >> 5;
    const int lid = t & 31;
    const int n0  = blockIdx.x * 128;
    const int bk  = blockIdx.y;
    const int warp_m = wid & 3;       // 0..3 -> 32-row slice
    const int warp_n = wid >> 2;      // 0..3 -> 48-col slice
    const uint32_t smbase = smem_u32(sm);

    auto load_stage = [&](int s, int slot) {
        const int hk0 = (s / 24) * 192;
        const int k0  = (s % 24) * 32;
        const uint32_t st = smbase + (uint32_t)slot * A_STAGE;
        {   // A: 128 rows x 4 segs, hi+lo (512 threads -> 1 each)
            int row = t >> 2, seg = t & 3;
            uint32_t d = st + (uint32_t)row * 80u + (uint32_t)seg * 16u;
            cp16(d,          g_qh + (size_t)(n0 + row) * CC + k0 + seg * 8);
            cp16(d + 10240u, g_ql + (size_t)(n0 + row) * CC + k0 + seg * 8);
        }
        // B: 192 rows x 4 segs, hi+lo (768 jobs/tensor over 512 threads)
        #pragma unroll
        for (int it = 0; it < 2; it++) {
            int jdx = it * 512 + t;
            if (jdx < 768) {
                int row = jdx >> 2, seg = jdx & 3;
                uint32_t d = st + 20480u + (uint32_t)row * 80u + (uint32_t)seg * 16u;
                cp16(d,          g_kh + (size_t)(bk * HWs + hk0 + row) * CC + k0 + seg * 8);
                cp16(d + 15360u, g_kl + (size_t)(bk * HWs + hk0 + row) * CC + k0 + seg * 8);
            }
        }
    };

    float acc[2][6][4];
    float rm[2][2] = {{-3.402823e38f, -3.402823e38f}, {-3.402823e38f, -3.402823e38f}};

    load_stage(0, 0); cp_commit();
    load_stage(1, 1); cp_commit();

    for (int s = 0; s < A_NSTG; s++) {
        if (s + 1 < A_NSTG) cp_wait<1>(); else cp_wait<0>();
        __syncthreads();
        if (s + 2 < A_NSTG) { load_stage(s + 2, (s + 2) % 3); cp_commit(); }

        if ((s % 24) == 0) {
            #pragma unroll
            for (int mt = 0; mt < 2; mt++)
                #pragma unroll
                for (int j = 0; j < 6; j++)
                    #pragma unroll
                    for (int r = 0; r < 4; r++)
                        acc[mt][j][r] = 0.f;
        }

        const uint32_t st = smbase + (uint32_t)(s % 3) * A_STAGE;
        #pragma unroll
        for (int k16 = 0; k16 < 2; k16++) {
            const int kb = k16 * 16;
            #pragma unroll
            for (int mt = 0; mt < 2; mt++) {
                uint32_t ah[4], al[4];
                uint32_t aa = st
                    + (uint32_t)(warp_m * 32 + mt * 16 + (lid & 15)) * 80u
                    + (uint32_t)(kb + ((lid >> 4) & 1) * 8) * 2u;
                ldsm4(ah, aa);
                ldsm4(al, aa + 10240u);
                #pragma unroll
                for (int nt = 0; nt < 3; nt++) {
                    uint32_t bh4[4], bl4[4];
                    uint32_t ba = st + 20480u
                        + (uint32_t)(warp_n * 48 + nt * 16 + (lid & 7) + ((lid >> 4) & 1) * 8) * 80u
                        + (uint32_t)(kb + ((lid >> 3) & 1) * 8) * 2u;
                    ldsm4(bh4, ba);
                    ldsm4(bl4, ba + 15360u);
                    #pragma unroll
                    for (int hh = 0; hh < 2; hh++) {
                        int j = nt * 2 + hh;
                        mma16816(acc[mt][j], ah, &bh4[hh * 2]);
                        mma16816(acc[mt][j], ah, &bl4[hh * 2]);
                        mma16816(acc[mt][j], al, &bh4[hh * 2]);
                    }
                }
            }
        }

        if ((s % 24) == 23) {
            #pragma unroll
            for (int mt = 0; mt < 2; mt++) {
                float m0 = -3.402823e38f, m1 = -3.402823e38f;
                #pragma unroll
                for (int j = 0; j < 6; j++) {
                    m0 = fmaxf(m0, fmaxf(acc[mt][j][0], acc[mt][j][1]));
                    m1 = fmaxf(m1, fmaxf(acc[mt][j][2], acc[mt][j][3]));
                }
                m0 = fmaxf(m0, __shfl_xor_sync(0xffffffffu, m0, 1));
                m0 = fmaxf(m0, __shfl_xor_sync(0xffffffffu, m0, 2));
                m1 = fmaxf(m1, __shfl_xor_sync(0xffffffffu, m1, 1));
                m1 = fmaxf(m1, __shfl_xor_sync(0xffffffffu, m1, 2));
                rm[mt][0] = fmaxf(rm[mt][0], m0);
                rm[mt][1] = fmaxf(rm[mt][1], m1);
            }
        }
    }

    __syncthreads();
    if ((lid & 3) == 0) {
        #pragma unroll
        for (int mt = 0; mt < 2; mt++) {
            int r = warp_m * 32 + mt * 16 + (lid >> 2);
            srow[warp_n][r]     = rm[mt][0];
            srow[warp_n][r + 8] = rm[mt][1];
        }
    }
    __syncthreads();
    if (t < 128) {
        float m = fmaxf(fmaxf(srow[0][t], srow[1][t]), fmaxf(srow[2][t], srow[3][t]));
        g_maxpart[bk * NTOK + n0 + t] = m;
    }
}

// ---------------------------------------------------------------------------
__global__ void argmax_kernel()
{
    const int b = blockIdx.x;
    const int tid = threadIdx.x;
    __shared__ float sv[256];
    __shared__ int   si[256];

    float best = -3.402823e38f;
    int   bidx = 0;
    for (int hw = tid; hw < HWs; hw += 256) {
        float s = 0.f;
        #pragma unroll
        for (int bk = 0; bk < BB; bk++)
            s += g_maxpart[bk * NTOK + b * HWs + hw];
        if (s > best) { best = s; bidx = hw; }
    }
    sv[tid] = best; si[tid] = bidx;
    __syncthreads();
    for (int s = 128; s > 0; s >>= 1) {
        if (tid < s) {
            if (sv[tid + s] > sv[tid] ||
                (sv[tid + s] == sv[tid] && si[tid + s] < si[tid])) {
                sv[tid] = sv[tid + s];
                si[tid] = si[tid + s];
            }
        }
        __syncthreads();
    }
    if (tid == 0) g_hwstar[b] = si[0];
}

__global__ void norm_kernel()
{
    int p = blockIdx.x * blockDim.x + threadIdx.x;
    if (p >= NTOK) return;
    int b = p / HWs, hw = p % HWs;
    const float* xp = g_x5 + b * CC * HWs + hw;
    float s = 0.f;
    #pragma unroll 8
    for (int c = 0; c < CC; c++) {
        float v = xp[c * HWs];
        s = fmaf(v, v, s);
    }
    g_norm[p] = fmaxf(sqrtf(s), 1e-12f);
}

__global__ void seeds_kernel()
{
    int b = blockIdx.x;
    int c = threadIdx.x;
    int hws = g_hwstar[b];
    float inv = 1.f / g_norm[b * HWs + hws];
    g_seeds[b * CC + c] = g_x5[b * CC * HWs + c * HWs + hws] * inv;
}

__global__ void cor_kernel()
{
    __shared__ float ss[BB * CC];
    const int b = blockIdx.x;
    for (int i = threadIdx.x; i < BB * CC; i += blockDim.x) ss[i] = g_seeds[i];
    __syncthreads();

    const int hw = blockIdx.y * 192 + threadIdx.x;
    const float* xp = g_x5 + b * CC * HWs + hw;
    float acc[BB] = {};
    for (int c = 0; c < CC; c++) {
        float v = xp[c * HWs];
        #pragma unroll
        for (int o = 0; o < BB; o++)
            acc[o] = fmaf(v, ss[o * CC + c], acc[o]);
    }
    float s = 0.f;
    #pragma unroll
    for (int o = 0; o < BB; o++) s += fmaxf(acc[o], 0.f);
    g_cor[b * HWs + hw] = s / (16.f * g_norm[b * HWs + hw]);
}

__global__ void minmax_kernel()
{
    const int b = blockIdx.x;
    const int tid = threadIdx.x;
    __shared__ float smn[256], smx[256];
    float mn = 3.402823e38f, mx = -3.402823e38f;
    for (int hw = tid; hw < HWs; hw += 256) {
        float v = g_cor[b * HWs + hw];
        mn = fminf(mn, v);
        mx = fmaxf(mx, v);
    }
    smn[tid] = mn; smx[tid] = mx;
    __syncthreads();
    for (int s = 128; s > 0; s >>= 1) {
        if (tid < s) {
            smn[tid] = fminf(smn[tid], smn[tid + s]);
            smx[tid] = fmaxf(smx[tid], smx[tid + s]);
        }
        __syncthreads();
    }
    float m0 = smn[0];
    float inv = 1.f / (smx[0] - m0 + 1e-12f);
    for (int hw = tid; hw < HWs; hw += 256)
        g_cor[b * HWs + hw] = (g_cor[b * HWs + hw] - m0) * inv;
}

__global__ void apply_kernel(int add_prev)
{
    int idx = blockIdx.x * 256 + threadIdx.x;
    int b  = idx / (CC * HWs);
    int hw = idx % HWs;
    float v = g_x5[idx] * g_cor[b * HWs + hw];
    g_cur[idx] = (add_prev ? g_cur[idx] : 0.f) + v;
}

__global__ void consen_kernel()
{
    const int c = blockIdx.x;
    const int tid = threadIdx.x;
    __shared__ float sm[256];
    float s = 0.f;
    for (int b = 0; b < BB; b++) {
        const float* p = g_cur + b * CC * HWs + c * HWs;
        for (int hw = tid; hw < HWs; hw += 256) s += p[hw];
    }
    sm[tid] = s;
    __syncthreads();
    for (int st = 128; st > 0; st >>= 1) {
        if (tid < st) sm[tid] += sm[tid + st];
        __syncthreads();
    }
    if (tid == 0) g_consen[c] = sm[0] * (1.f / (float)(BB * HWs));
}

__global__ void final_kernel(const float* __restrict__ xin, float* __restrict__ out)
{
    int idx = blockIdx.x * 256 + threadIdx.x;
    int c = (idx / HWs) % CC;
    out[idx] = g_cur[idx] + xin[idx] * g_consen[c];
}

// ---------------------------------------------------------------------------
extern "C" void kernel_launch(void* const* d_in, const int* in_sizes, int n_in,
                              void* d_out, int out_size)
{
    const float* x5      = (const float*)d_in[0];
    const float* conv_w  = (const float*)d_in[1];
    const float* conv_b  = (const float*)d_in[2];
    const float* query_w = (const float*)d_in[3];
    const float* query_b = (const float*)d_in[4];
    const float* key_w   = (const float*)d_in[5];
    const float* key_b   = (const float*)d_in[6];
    float* out = (float*)d_out;

    cudaFuncSetAttribute(attn_mma_kernel,
                         cudaFuncAttributeMaxDynamicSharedMemorySize, A_DYN);
    cudaFuncSetAttribute(gemm_mma_kernel,
                         cudaFuncAttributeMaxDynamicSharedMemorySize, GEMM_DYN);

    __nv_bfloat16 *wh_p, *wl_p, *xth_p, *xtl_p, *x5th_p, *x5tl_p;
    __nv_bfloat16 *qh_p, *ql_p, *kh_p, *kl_p;
    cudaGetSymbolAddress((void**)&wh_p, g_wh);
    cudaGetSymbolAddress((void**)&wl_p, g_wl);
    cudaGetSymbolAddress((void**)&xth_p, g_xth);
    cudaGetSymbolAddress((void**)&xtl_p, g_xtl);
    cudaGetSymbolAddress((void**)&x5th_p, g_x5th);
    cudaGetSymbolAddress((void**)&x5tl_p, g_x5tl);
    cudaGetSymbolAddress((void**)&qh_p, g_qh);
    cudaGetSymbolAddress((void**)&ql_p, g_ql);
    cudaGetSymbolAddress((void**)&kh_p, g_kh);
    cudaGetSymbolAddress((void**)&kl_p, g_kl);
    float *x5g_p, *cur_p;
    cudaGetSymbolAddress((void**)&x5g_p, g_x5);
    cudaGetSymbolAddress((void**)&cur_p, g_cur);

    dim3 wgrid(NLAYER * CC * CC / 256, 3);  // (9216, 3)
    dim3 xgrid(HWs / 32, CC / 32, BB);      // (18, 24, 16)
    dim3 mgrid(HWs / 64, CC / 128, BB);     // (9, 6, 16)
    dim3 agrid(NTOK / 128, BB);             // (72, 16)
    dim3 cgrid(BB, HWs / 192);              // (16, 3)
    const int egrid = ELEMS / 256;          // 27648

    convert_w_kernel<<<wgrid, 256>>>(conv_w, query_w, key_w);

    const size_t WSZ = (size_t)CC * CC;
    for (int i = 0; i < NLAYER; i++) {
        // layer input -> transposed bf16
        convert_x_kernel<<<xgrid, dim3(32, 8)>>>(x5, (i == 0) ? 0 : 1);
        // x5 = conv(cur) + bias + cur   (fp32 + fused transposed bf16 out)
        gemm_mma_kernel<<<mgrid, 256, GEMM_DYN>>>(
            wh_p + i * WSZ, wl_p + i * WSZ, xth_p, xtl_p,
            conv_b + i * CC, (i == 0) ? x5 : cur_p, 1,
            x5g_p, 1, x5th_p, x5tl_p);
        // q, k: bf16 hi/lo transposed only (no fp32)
        gemm_mma_kernel<<<mgrid, 256, GEMM_DYN>>>(
            wh_p + (NLAYER + i) * WSZ, wl_p + (NLAYER + i) * WSZ, x5th_p, x5tl_p,
            query_b + i * CC, nullptr, 0,
            nullptr, 0, qh_p, ql_p);
        gemm_mma_kernel<<<mgrid, 256, GEMM_DYN>>>(
            wh_p + (2 * NLAYER + i) * WSZ, wl_p + (2 * NLAYER + i) * WSZ, x5th_p, x5tl_p,
            key_b + i * CC, nullptr, 0,
            nullptr, 0, kh_p, kl_p);
        attn_mma_kernel<<<agrid, 512, A_DYN>>>();
        argmax_kernel<<<BB, 256>>>();
        norm_kernel<<<NTOK / 256, 256>>>();
        seeds_kernel<<<BB, CC>>>();
        cor_kernel<<<cgrid, 192>>>();
        minmax_kernel<<<BB, 256>>>();
        apply_kernel<<<egrid, 256>>>(i > 0 ? 1 : 0);
    }
    consen_kernel<<<CC, 256>>>();
    final_kernel<<<egrid, 256>>>(x5, out);
}

// round 8
// speedup vs baseline: 3.2481x; 1.0178x over previous
#include <cuda_runtime.h>
#include <cuda_bf16.h>
#include <cstdint>

// Problem constants
#define BB   16
#define CC   768
#define HWs  576
#define NTOK (BB*HWs)          // 9216
#define ELEMS (BB*CC*HWs)      // 7,077,888
#define NLAYER 4

// Scratch (device globals; no allocation allowed)
__device__ float g_cur[ELEMS];
__device__ float g_x5[ELEMS];
__device__ __nv_bfloat16 g_qh[(size_t)NTOK*CC];
__device__ __nv_bfloat16 g_ql[(size_t)NTOK*CC];
__device__ __nv_bfloat16 g_kh[(size_t)NTOK*CC];
__device__ __nv_bfloat16 g_kl[(size_t)NTOK*CC];
__device__ __nv_bfloat16 g_xth[(size_t)NTOK*CC];    // layer input transposed hi
__device__ __nv_bfloat16 g_xtl[(size_t)NTOK*CC];    // lo
__device__ __nv_bfloat16 g_x5th[(size_t)NTOK*CC];   // x5 transposed hi
__device__ __nv_bfloat16 g_x5tl[(size_t)NTOK*CC];   // lo
__device__ __nv_bfloat16 g_wh[(size_t)3*NLAYER*CC*CC];
__device__ __nv_bfloat16 g_wl[(size_t)3*NLAYER*CC*CC];
__device__ float g_maxpart[BB*NTOK];
__device__ int   g_hwstar[BB];
__device__ float g_norm[BB*HWs];
__device__ float g_seeds[BB*CC];
__device__ float g_cor[BB*HWs];
__device__ float g_consen[CC];

// ============================ PTX helpers (sm_80+ only) =====================
__device__ __forceinline__ uint32_t smem_u32(const void* p) {
    uint32_t a;
    asm("{ .reg .u64 t; cvta.to.shared.u64 t, %1; cvt.u32.u64 %0, t; }" : "=r"(a) : "l"(p));
    return a;
}
__device__ __forceinline__ void cp16(uint32_t d, const void* s) {
    asm volatile("cp.async.cg.shared.global [%0], [%1], 16;" :: "r"(d), "l"(s));
}
__device__ __forceinline__ void cp_commit() { asm volatile("cp.async.commit_group;"); }
template<int N> __device__ __forceinline__ void cp_wait() {
    asm volatile("cp.async.wait_group %0;" :: "n"(N));
}
__device__ __forceinline__ void ldsm4(uint32_t* r, uint32_t a) {
    asm volatile("ldmatrix.sync.aligned.m8n8.x4.shared.b16 {%0,%1,%2,%3}, [%4];"
                 : "=r"(r[0]), "=r"(r[1]), "=r"(r[2]), "=r"(r[3]) : "r"(a));
}
__device__ __forceinline__ void mma16816(float* d, const uint32_t* a, const uint32_t* b) {
    asm volatile("mma.sync.aligned.m16n8k16.row.col.f32.bf16.bf16.f32 "
                 "{%0,%1,%2,%3}, {%4,%5,%6,%7}, {%8,%9}, {%0,%1,%2,%3};"
                 : "+f"(d[0]), "+f"(d[1]), "+f"(d[2]), "+f"(d[3])
                 : "r"(a[0]), "r"(a[1]), "r"(a[2]), "r"(a[3]), "r"(b[0]), "r"(b[1]));
}

// Shared 128x192x32 stage geometry (80B rows):
// Ah[128]@0 | Al@10240 | Bh[192]@20480 | Bl@35840  => 51200 B/stage
#define TS_STAGE 51200
#define TS_DYN   (3*TS_STAGE)    // 153600

// ---------------------------------------------------------------------------
// Weight conversion: fp32 [o][c] -> bf16 hi/lo.  grid (9216, 3), block 256.
// ---------------------------------------------------------------------------
__global__ void convert_w_kernel(const float* __restrict__ cw,
                                 const float* __restrict__ qw,
                                 const float* __restrict__ kw)
{
    const int z = blockIdx.y;
    const float* src = (z == 0) ? cw : (z == 1 ? qw : kw);
    const size_t off = (size_t)z * NLAYER * CC * CC;
    const size_t idx = (size_t)blockIdx.x * 256 + threadIdx.x;
    float v = src[idx];
    __nv_bfloat16 h = __float2bfloat16(v);
    __nv_bfloat16 l = __float2bfloat16(v - __bfloat162float(h));
    g_wh[off + idx] = h;
    g_wl[off + idx] = l;
}

// ---------------------------------------------------------------------------
// Layer-input conversion+transpose: src [b][c][hw] fp32 -> g_xt [n][c] bf16.
// src_sel: 0 ext, 1 g_cur.  grid (18, 24, 16), block (32,8).
// ---------------------------------------------------------------------------
__global__ void convert_x_kernel(const float* __restrict__ ext, int src_sel)
{
    __shared__ float tile[32][33];
    const int b = blockIdx.z;
    const float* src = ((src_sel == 0) ? ext : g_cur) + (size_t)b * CC * HWs;
    const int hw0 = blockIdx.x * 32;
    const int c0  = blockIdx.y * 32;
    const int tx = threadIdx.x, ty = threadIdx.y;

    #pragma unroll
    for (int j = 0; j < 4; j++) {
        int c = ty * 4 + j;
        tile[c][tx] = src[(size_t)(c0 + c) * HWs + hw0 + tx];
    }
    __syncthreads();
    #pragma unroll
    for (int j = 0; j < 4; j++) {
        int hwl = ty * 4 + j;
        float v = tile[tx][hwl];
        __nv_bfloat16 h = __float2bfloat16(v);
        __nv_bfloat16 l = __float2bfloat16(v - __bfloat162float(h));
        size_t o = (size_t)(b * HWs + hw0 + hwl) * CC + c0 + tx;
        g_xth[o] = h;
        g_xtl[o] = l;
    }
}

// ---------------------------------------------------------------------------
// Split-bf16 mma.sync GEMM, 128(o) x 192(hw) per CTA, 512 threads,
// 3-stage cp.async ring, 1 barrier/stage, B-fragment hoisting.
// Y[b,o,hw] = sum_c W[o,c] X[b,c,hw] + bias[o] (+res); fused transposed
// bf16 hi/lo output dh/dl[(b*HWs+hw)*CC + o]; optional fp32 Y.
// grid (3, 6, 16).
// ---------------------------------------------------------------------------
__global__ void __launch_bounds__(512, 1) gemm_mma_kernel(
    const __nv_bfloat16* __restrict__ Wh, const __nv_bfloat16* __restrict__ Wl,
    const __nv_bfloat16* __restrict__ Bh, const __nv_bfloat16* __restrict__ Bl,
    const float* __restrict__ bias, const float* __restrict__ resid, int residual,
    float* __restrict__ Y, int write_f32,
    __nv_bfloat16* __restrict__ dh, __nv_bfloat16* __restrict__ dl)
{
    extern __shared__ __align__(16) char sm[];
    const int t   = threadIdx.x;
    const int wid = t >> 5;
    const int lid = t & 31;
    const int n0  = blockIdx.x * 192;     // hw
    const int m0  = blockIdx.y * 128;     // o
    const int b   = blockIdx.z;
    const int warp_m = wid & 3;           // 32-row slice of o
    const int warp_n = wid >> 2;          // 48-col slice of hw
    const uint32_t smbase = smem_u32(sm);

    auto load_stage = [&](int s, int slot) {
        const int k0 = s * 32;
        const uint32_t st = smbase + (uint32_t)slot * TS_STAGE;
        {   // A: 128 rows (W)
            int row = t >> 2, seg = t & 3;
            uint32_t d = st + (uint32_t)row * 80u + (uint32_t)seg * 16u;
            cp16(d,          Wh + (size_t)(m0 + row) * CC + k0 + seg * 8);
            cp16(d + 10240u, Wl + (size_t)(m0 + row) * CC + k0 + seg * 8);
        }
        #pragma unroll
        for (int it = 0; it < 2; it++) {   // B: 192 rows (X^T)
            int jdx = it * 512 + t;
            if (jdx < 768) {
                int row = jdx >> 2, seg = jdx & 3;
                uint32_t d = st + 20480u + (uint32_t)row * 80u + (uint32_t)seg * 16u;
                cp16(d,          Bh + (size_t)(b * HWs + n0 + row) * CC + k0 + seg * 8);
                cp16(d + 15360u, Bl + (size_t)(b * HWs + n0 + row) * CC + k0 + seg * 8);
            }
        }
    };

    float acc[2][6][4];
    #pragma unroll
    for (int mt = 0; mt < 2; mt++)
        #pragma unroll
        for (int j = 0; j < 6; j++)
            #pragma unroll
            for (int r = 0; r < 4; r++)
                acc[mt][j][r] = 0.f;

    load_stage(0, 0); cp_commit();
    load_stage(1, 1); cp_commit();

    for (int s = 0; s < 24; s++) {
        if (s + 1 < 24) cp_wait<1>(); else cp_wait<0>();
        __syncthreads();
        if (s + 2 < 24) { load_stage(s + 2, (s + 2) % 3); cp_commit(); }

        const uint32_t st = smbase + (uint32_t)(s % 3) * TS_STAGE;
        #pragma unroll
        for (int k16 = 0; k16 < 2; k16++) {
            const int kb = k16 * 16;
            uint32_t bh[12], bl[12];
            #pragma unroll
            for (int nt = 0; nt < 3; nt++) {
                uint32_t ba = st + 20480u
                    + (uint32_t)(warp_n * 48 + nt * 16 + (lid & 7) + ((lid >> 4) & 1) * 8) * 80u
                    + (uint32_t)(kb + ((lid >> 3) & 1) * 8) * 2u;
                ldsm4(&bh[nt * 4], ba);
                ldsm4(&bl[nt * 4], ba + 15360u);
            }
            #pragma unroll
            for (int mt = 0; mt < 2; mt++) {
                uint32_t ah[4], al[4];
                uint32_t aa = st
                    + (uint32_t)(warp_m * 32 + mt * 16 + (lid & 15)) * 80u
                    + (uint32_t)(kb + ((lid >> 4) & 1) * 8) * 2u;
                ldsm4(ah, aa);
                ldsm4(al, aa + 10240u);
                #pragma unroll
                for (int j = 0; j < 6; j++) {
                    const uint32_t* bhp = &bh[(j >> 1) * 4 + (j & 1) * 2];
                    const uint32_t* blp = &bl[(j >> 1) * 4 + (j & 1) * 2];
                    mma16816(acc[mt][j], ah, bhp);
                    mma16816(acc[mt][j], ah, blp);
                    mma16816(acc[mt][j], al, bhp);
                }
            }
        }
    }

    // epilogue
    const size_t Yb = (size_t)b * CC * HWs;
    const int nb = b * HWs;
    #pragma unroll
    for (int mt = 0; mt < 2; mt++) {
        int R = m0 + warp_m * 32 + mt * 16 + (lid >> 2);
        float bs0 = bias[R], bs1 = bias[R + 8];
        #pragma unroll
        for (int j = 0; j < 6; j++) {
            int cb = n0 + warp_n * 48 + (j >> 1) * 16 + (j & 1) * 8 + (lid & 3) * 2;
            float v00 = acc[mt][j][0] + bs0, v01 = acc[mt][j][1] + bs0;
            float v10 = acc[mt][j][2] + bs1, v11 = acc[mt][j][3] + bs1;
            size_t a0 = Yb + (size_t)R * HWs + cb;
            size_t a1 = a0 + 8 * HWs;
            if (residual) {
                float2 r0 = *(const float2*)(resid + a0);
                float2 r1 = *(const float2*)(resid + a1);
                v00 += r0.x; v01 += r0.y; v10 += r1.x; v11 += r1.y;
            }
            if (write_f32) {
                *(float2*)(Y + a0) = make_float2(v00, v01);
                *(float2*)(Y + a1) = make_float2(v10, v11);
            }
            size_t r0o = (size_t)(nb + cb) * CC;
            size_t r1o = r0o + CC;
            __nv_bfloat16 h;
            h = __float2bfloat16(v00); dh[r0o + R]     = h; dl[r0o + R]     = __float2bfloat16(v00 - __bfloat162float(h));
            h = __float2bfloat16(v01); dh[r1o + R]     = h; dl[r1o + R]     = __float2bfloat16(v01 - __bfloat162float(h));
            h = __float2bfloat16(v10); dh[r0o + R + 8] = h; dl[r0o + R + 8] = __float2bfloat16(v10 - __bfloat162float(h));
            h = __float2bfloat16(v11); dh[r1o + R + 8] = h; dl[r1o + R + 8] = __float2bfloat16(v11 - __bfloat162float(h));
        }
    }
}

// ---------------------------------------------------------------------------
// mma.sync attention row-max: CTA 128 q x 192 keys, 512 threads, 3 ct-tiles,
// 24 k-chunks, 3-stage ring, 1 barrier/stage, B-fragment hoisting.
// grid (72 m-tiles, 16 bk).
// ---------------------------------------------------------------------------
#define A_NSTG  72               // 3 ct * 24 k-chunks

__global__ void __launch_bounds__(512, 1) attn_mma_kernel()
{
    extern __shared__ __align__(16) char sm[];
    __shared__ float srow[4][128];

    const int t   = threadIdx.x;
    const int wid = t >> 5;
    const int lid = t & 31;
    const int n0  = blockIdx.x * 128;
    const int bk  = blockIdx.y;
    const int warp_m = wid & 3;
    const int warp_n = wid >> 2;
    const uint32_t smbase = smem_u32(sm);

    auto load_stage = [&](int s, int slot) {
        const int hk0 = (s / 24) * 192;
        const int k0  = (s % 24) * 32;
        const uint32_t st = smbase + (uint32_t)slot * TS_STAGE;
        {
            int row = t >> 2, seg = t & 3;
            uint32_t d = st + (uint32_t)row * 80u + (uint32_t)seg * 16u;
            cp16(d,          g_qh + (size_t)(n0 + row) * CC + k0 + seg * 8);
            cp16(d + 10240u, g_ql + (size_t)(n0 + row) * CC + k0 + seg * 8);
        }
        #pragma unroll
        for (int it = 0; it < 2; it++) {
            int jdx = it * 512 + t;
            if (jdx < 768) {
                int row = jdx >> 2, seg = jdx & 3;
                uint32_t d = st + 20480u + (uint32_t)row * 80u + (uint32_t)seg * 16u;
                cp16(d,          g_kh + (size_t)(bk * HWs + hk0 + row) * CC + k0 + seg * 8);
                cp16(d + 15360u, g_kl + (size_t)(bk * HWs + hk0 + row) * CC + k0 + seg * 8);
            }
        }
    };

    float acc[2][6][4];
    float rm[2][2] = {{-3.402823e38f, -3.402823e38f}, {-3.402823e38f, -3.402823e38f}};

    load_stage(0, 0); cp_commit();
    load_stage(1, 1); cp_commit();

    for (int s = 0; s < A_NSTG; s++) {
        if (s + 1 < A_NSTG) cp_wait<1>(); else cp_wait<0>();
        __syncthreads();
        if (s + 2 < A_NSTG) { load_stage(s + 2, (s + 2) % 3); cp_commit(); }

        if ((s % 24) == 0) {
            #pragma unroll
            for (int mt = 0; mt < 2; mt++)
                #pragma unroll
                for (int j = 0; j < 6; j++)
                    #pragma unroll
                    for (int r = 0; r < 4; r++)
                        acc[mt][j][r] = 0.f;
        }

        const uint32_t st = smbase + (uint32_t)(s % 3) * TS_STAGE;
        #pragma unroll
        for (int k16 = 0; k16 < 2; k16++) {
            const int kb = k16 * 16;
            uint32_t bh[12], bl[12];
            #pragma unroll
            for (int nt = 0; nt < 3; nt++) {
                uint32_t ba = st + 20480u
                    + (uint32_t)(warp_n * 48 + nt * 16 + (lid & 7) + ((lid >> 4) & 1) * 8) * 80u
                    + (uint32_t)(kb + ((lid >> 3) & 1) * 8) * 2u;
                ldsm4(&bh[nt * 4], ba);
                ldsm4(&bl[nt * 4], ba + 15360u);
            }
            #pragma unroll
            for (int mt = 0; mt < 2; mt++) {
                uint32_t ah[4], al[4];
                uint32_t aa = st
                    + (uint32_t)(warp_m * 32 + mt * 16 + (lid & 15)) * 80u
                    + (uint32_t)(kb + ((lid >> 4) & 1) * 8) * 2u;
                ldsm4(ah, aa);
                ldsm4(al, aa + 10240u);
                #pragma unroll
                for (int j = 0; j < 6; j++) {
                    const uint32_t* bhp = &bh[(j >> 1) * 4 + (j & 1) * 2];
                    const uint32_t* blp = &bl[(j >> 1) * 4 + (j & 1) * 2];
                    mma16816(acc[mt][j], ah, bhp);
                    mma16816(acc[mt][j], ah, blp);
                    mma16816(acc[mt][j], al, bhp);
                }
            }
        }

        if ((s % 24) == 23) {
            #pragma unroll
            for (int mt = 0; mt < 2; mt++) {
                float m0 = -3.402823e38f, m1 = -3.402823e38f;
                #pragma unroll
                for (int j = 0; j < 6; j++) {
                    m0 = fmaxf(m0, fmaxf(acc[mt][j][0], acc[mt][j][1]));
                    m1 = fmaxf(m1, fmaxf(acc[mt][j][2], acc[mt][j][3]));
                }
                m0 = fmaxf(m0, __shfl_xor_sync(0xffffffffu, m0, 1));
                m0 = fmaxf(m0, __shfl_xor_sync(0xffffffffu, m0, 2));
                m1 = fmaxf(m1, __shfl_xor_sync(0xffffffffu, m1, 1));
                m1 = fmaxf(m1, __shfl_xor_sync(0xffffffffu, m1, 2));
                rm[mt][0] = fmaxf(rm[mt][0], m0);
                rm[mt][1] = fmaxf(rm[mt][1], m1);
            }
        }
    }

    __syncthreads();
    if ((lid & 3) == 0) {
        #pragma unroll
        for (int mt = 0; mt < 2; mt++) {
            int r = warp_m * 32 + mt * 16 + (lid >> 2);
            srow[warp_n][r]     = rm[mt][0];
            srow[warp_n][r + 8] = rm[mt][1];
        }
    }
    __syncthreads();
    if (t < 128) {
        float m = fmaxf(fmaxf(srow[0][t], srow[1][t]), fmaxf(srow[2][t], srow[3][t]));
        g_maxpart[bk * NTOK + n0 + t] = m;
    }
}

// ---------------------------------------------------------------------------
__global__ void argmax_kernel()
{
    const int b = blockIdx.x;
    const int tid = threadIdx.x;
    __shared__ float sv[256];
    __shared__ int   si[256];

    float best = -3.402823e38f;
    int   bidx = 0;
    for (int hw = tid; hw < HWs; hw += 256) {
        float s = 0.f;
        #pragma unroll
        for (int bk = 0; bk < BB; bk++)
            s += g_maxpart[bk * NTOK + b * HWs + hw];
        if (s > best) { best = s; bidx = hw; }
    }
    sv[tid] = best; si[tid] = bidx;
    __syncthreads();
    for (int s = 128; s > 0; s >>= 1) {
        if (tid < s) {
            if (sv[tid + s] > sv[tid] ||
                (sv[tid + s] == sv[tid] && si[tid + s] < si[tid])) {
                sv[tid] = sv[tid + s];
                si[tid] = si[tid + s];
            }
        }
        __syncthreads();
    }
    if (tid == 0) g_hwstar[b] = si[0];
}

__global__ void norm_kernel()
{
    int p = blockIdx.x * blockDim.x + threadIdx.x;
    if (p >= NTOK) return;
    int b = p / HWs, hw = p % HWs;
    const float* xp = g_x5 + b * CC * HWs + hw;
    float s = 0.f;
    #pragma unroll 8
    for (int c = 0; c < CC; c++) {
        float v = xp[c * HWs];
        s = fmaf(v, v, s);
    }
    g_norm[p] = fmaxf(sqrtf(s), 1e-12f);
}

__global__ void seeds_kernel()
{
    int b = blockIdx.x;
    int c = threadIdx.x;
    int hws = g_hwstar[b];
    float inv = 1.f / g_norm[b * HWs + hws];
    g_seeds[b * CC + c] = g_x5[b * CC * HWs + c * HWs + hws] * inv;
}

__global__ void cor_kernel()
{
    __shared__ float ss[BB * CC];
    const int b = blockIdx.x;
    for (int i = threadIdx.x; i < BB * CC; i += blockDim.x) ss[i] = g_seeds[i];
    __syncthreads();

    const int hw = blockIdx.y * 192 + threadIdx.x;
    const float* xp = g_x5 + b * CC * HWs + hw;
    float acc[BB] = {};
    for (int c = 0; c < CC; c++) {
        float v = xp[c * HWs];
        #pragma unroll
        for (int o = 0; o < BB; o++)
            acc[o] = fmaf(v, ss[o * CC + c], acc[o]);
    }
    float s = 0.f;
    #pragma unroll
    for (int o = 0; o < BB; o++) s += fmaxf(acc[o], 0.f);
    g_cor[b * HWs + hw] = s / (16.f * g_norm[b * HWs + hw]);
}

__global__ void minmax_kernel()
{
    const int b = blockIdx.x;
    const int tid = threadIdx.x;
    __shared__ float smn[256], smx[256];
    float mn = 3.402823e38f, mx = -3.402823e38f;
    for (int hw = tid; hw < HWs; hw += 256) {
        float v = g_cor[b * HWs + hw];
        mn = fminf(mn, v);
        mx = fmaxf(mx, v);
    }
    smn[tid] = mn; smx[tid] = mx;
    __syncthreads();
    for (int s = 128; s > 0; s >>= 1) {
        if (tid < s) {
            smn[tid] = fminf(smn[tid], smn[tid + s]);
            smx[tid] = fmaxf(smx[tid], smx[tid + s]);
        }
        __syncthreads();
    }
    float m0 = smn[0];
    float inv = 1.f / (smx[0] - m0 + 1e-12f);
    for (int hw = tid; hw < HWs; hw += 256)
        g_cor[b * HWs + hw] = (g_cor[b * HWs + hw] - m0) * inv;
}

__global__ void apply_kernel(int add_prev)
{
    int idx = blockIdx.x * 256 + threadIdx.x;
    int b  = idx / (CC * HWs);
    int hw = idx % HWs;
    float v = g_x5[idx] * g_cor[b * HWs + hw];
    g_cur[idx] = (add_prev ? g_cur[idx] : 0.f) + v;
}

__global__ void consen_kernel()
{
    const int c = blockIdx.x;
    const int tid = threadIdx.x;
    __shared__ float sm[256];
    float s = 0.f;
    for (int b = 0; b < BB; b++) {
        const float* p = g_cur + b * CC * HWs + c * HWs;
        for (int hw = tid; hw < HWs; hw += 256) s += p[hw];
    }
    sm[tid] = s;
    __syncthreads();
    for (int st = 128; st > 0; st >>= 1) {
        if (tid < st) sm[tid] += sm[tid + st];
        __syncthreads();
    }
    if (tid == 0) g_consen[c] = sm[0] * (1.f / (float)(BB * HWs));
}

__global__ void final_kernel(const float* __restrict__ xin, float* __restrict__ out)
{
    int idx = blockIdx.x * 256 + threadIdx.x;
    int c = (idx / HWs) % CC;
    out[idx] = g_cur[idx] + xin[idx] * g_consen[c];
}

// ---------------------------------------------------------------------------
extern "C" void kernel_launch(void* const* d_in, const int* in_sizes, int n_in,
                              void* d_out, int out_size)
{
    const float* x5      = (const float*)d_in[0];
    const float* conv_w  = (const float*)d_in[1];
    const float* conv_b  = (const float*)d_in[2];
    const float* query_w = (const float*)d_in[3];
    const float* query_b = (const float*)d_in[4];
    const float* key_w   = (const float*)d_in[5];
    const float* key_b   = (const float*)d_in[6];
    float* out = (float*)d_out;

    cudaFuncSetAttribute(attn_mma_kernel,
                         cudaFuncAttributeMaxDynamicSharedMemorySize, TS_DYN);
    cudaFuncSetAttribute(gemm_mma_kernel,
                         cudaFuncAttributeMaxDynamicSharedMemorySize, TS_DYN);

    __nv_bfloat16 *wh_p, *wl_p, *xth_p, *xtl_p, *x5th_p, *x5tl_p;
    __nv_bfloat16 *qh_p, *ql_p, *kh_p, *kl_p;
    cudaGetSymbolAddress((void**)&wh_p, g_wh);
    cudaGetSymbolAddress((void**)&wl_p, g_wl);
    cudaGetSymbolAddress((void**)&xth_p, g_xth);
    cudaGetSymbolAddress((void**)&xtl_p, g_xtl);
    cudaGetSymbolAddress((void**)&x5th_p, g_x5th);
    cudaGetSymbolAddress((void**)&x5tl_p, g_x5tl);
    cudaGetSymbolAddress((void**)&qh_p, g_qh);
    cudaGetSymbolAddress((void**)&ql_p, g_ql);
    cudaGetSymbolAddress((void**)&kh_p, g_kh);
    cudaGetSymbolAddress((void**)&kl_p, g_kl);
    float *x5g_p, *cur_p;
    cudaGetSymbolAddress((void**)&x5g_p, g_x5);
    cudaGetSymbolAddress((void**)&cur_p, g_cur);

    dim3 wgrid(NLAYER * CC * CC / 256, 3);  // (9216, 3)
    dim3 xgrid(HWs / 32, CC / 32, BB);      // (18, 24, 16)
    dim3 mgrid(HWs / 192, CC / 128, BB);    // (3, 6, 16)
    dim3 agrid(NTOK / 128, BB);             // (72, 16)
    dim3 cgrid(BB, HWs / 192);              // (16, 3)
    const int egrid = ELEMS / 256;          // 27648

    convert_w_kernel<<<wgrid, 256>>>(conv_w, query_w, key_w);

    const size_t WSZ = (size_t)CC * CC;
    for (int i = 0; i < NLAYER; i++) {
        convert_x_kernel<<<xgrid, dim3(32, 8)>>>(x5, (i == 0) ? 0 : 1);
        // x5 = conv(cur) + bias + cur   (fp32 + fused transposed bf16 out)
        gemm_mma_kernel<<<mgrid, 512, TS_DYN>>>(
            wh_p + i * WSZ, wl_p + i * WSZ, xth_p, xtl_p,
            conv_b + i * CC, (i == 0) ? x5 : cur_p, 1,
            x5g_p, 1, x5th_p, x5tl_p);
        // q, k: transposed bf16 hi/lo only
        gemm_mma_kernel<<<mgrid, 512, TS_DYN>>>(
            wh_p + (NLAYER + i) * WSZ, wl_p + (NLAYER + i) * WSZ, x5th_p, x5tl_p,
            query_b + i * CC, nullptr, 0,
            nullptr, 0, qh_p, ql_p);
        gemm_mma_kernel<<<mgrid, 512, TS_DYN>>>(
            wh_p + (2 * NLAYER + i) * WSZ, wl_p + (2 * NLAYER + i) * WSZ, x5th_p, x5tl_p,
            key_b + i * CC, nullptr, 0,
            nullptr, 0, kh_p, kl_p);
        attn_mma_kernel<<<agrid, 512, TS_DYN>>>();
        argmax_kernel<<<BB, 256>>>();
        norm_kernel<<<NTOK / 256, 256>>>();
        seeds_kernel<<<BB, CC>>>();
        cor_kernel<<<cgrid, 192>>>();
        minmax_kernel<<<BB, 256>>>();
        apply_kernel<<<egrid, 256>>>(i > 0 ? 1 : 0);
    }
    consen_kernel<<<CC, 256>>>();
    final_kernel<<<egrid, 256>>>(x5, out);
}

// round 9
// speedup vs baseline: 3.2594x; 1.0035x over previous
#include <cuda_runtime.h>
#include <cuda_bf16.h>
#include <cstdint>

// Problem constants
#define BB   16
#define CC   768
#define HWs  576
#define NTOK (BB*HWs)          // 9216
#define ELEMS (BB*CC*HWs)      // 7,077,888
#define NLAYER 4

// Scratch (device globals; no allocation allowed)
__device__ float g_cur[ELEMS];
__device__ float g_x5[ELEMS];
__device__ __nv_bfloat16 g_qh[(size_t)NTOK*CC];
__device__ __nv_bfloat16 g_ql[(size_t)NTOK*CC];
__device__ __nv_bfloat16 g_kh[(size_t)NTOK*CC];
__device__ __nv_bfloat16 g_kl[(size_t)NTOK*CC];
__device__ __nv_bfloat16 g_xth[(size_t)NTOK*CC];    // layer input transposed hi
__device__ __nv_bfloat16 g_xtl[(size_t)NTOK*CC];    // lo
__device__ __nv_bfloat16 g_x5th[(size_t)NTOK*CC];   // x5 transposed hi
__device__ __nv_bfloat16 g_x5tl[(size_t)NTOK*CC];   // lo
__device__ __nv_bfloat16 g_wh[(size_t)3*NLAYER*CC*CC];
__device__ __nv_bfloat16 g_wl[(size_t)3*NLAYER*CC*CC];
__device__ float g_maxpart[BB*NTOK];
__device__ int   g_hwstar[BB];
__device__ float g_norm[BB*HWs];
__device__ float g_seeds[BB*CC];
__device__ float g_cor[BB*HWs];
__device__ float g_consen[CC];

// ============================ PTX helpers (sm_80+ only) =====================
__device__ __forceinline__ uint32_t smem_u32(const void* p) {
    uint32_t a;
    asm("{ .reg .u64 t; cvta.to.shared.u64 t, %1; cvt.u32.u64 %0, t; }" : "=r"(a) : "l"(p));
    return a;
}
__device__ __forceinline__ void cp16(uint32_t d, const void* s) {
    asm volatile("cp.async.cg.shared.global [%0], [%1], 16;" :: "r"(d), "l"(s));
}
__device__ __forceinline__ void cp_commit() { asm volatile("cp.async.commit_group;"); }
template<int N> __device__ __forceinline__ void cp_wait() {
    asm volatile("cp.async.wait_group %0;" :: "n"(N));
}
__device__ __forceinline__ void ldsm4(uint32_t* r, uint32_t a) {
    asm volatile("ldmatrix.sync.aligned.m8n8.x4.shared.b16 {%0,%1,%2,%3}, [%4];"
                 : "=r"(r[0]), "=r"(r[1]), "=r"(r[2]), "=r"(r[3]) : "r"(a));
}
__device__ __forceinline__ void mma16816(float* d, const uint32_t* a, const uint32_t* b) {
    asm volatile("mma.sync.aligned.m16n8k16.row.col.f32.bf16.bf16.f32 "
                 "{%0,%1,%2,%3}, {%4,%5,%6,%7}, {%8,%9}, {%0,%1,%2,%3};"
                 : "+f"(d[0]), "+f"(d[1]), "+f"(d[2]), "+f"(d[3])
                 : "r"(a[0]), "r"(a[1]), "r"(a[2]), "r"(a[3]), "r"(b[0]), "r"(b[1]));
}

// Shared 128x192x32 stage geometry (80B rows):
// Ah[128]@0 | Al@10240 | Bh[192]@20480 | Bl@35840  => 51200 B/stage
#define TS_STAGE 51200
#define TS_DYN   (3*TS_STAGE)    // 153600

// ---------------------------------------------------------------------------
// Weight conversion: fp32 [o][c] -> bf16 hi/lo.  grid (9216, 3), block 256.
// ---------------------------------------------------------------------------
__global__ void convert_w_kernel(const float* __restrict__ cw,
                                 const float* __restrict__ qw,
                                 const float* __restrict__ kw)
{
    const int z = blockIdx.y;
    const float* src = (z == 0) ? cw : (z == 1 ? qw : kw);
    const size_t off = (size_t)z * NLAYER * CC * CC;
    const size_t idx = (size_t)blockIdx.x * 256 + threadIdx.x;
    float v = src[idx];
    __nv_bfloat16 h = __float2bfloat16(v);
    __nv_bfloat16 l = __float2bfloat16(v - __bfloat162float(h));
    g_wh[off + idx] = h;
    g_wl[off + idx] = l;
}

// ---------------------------------------------------------------------------
// Layer-input conversion+transpose: src [b][c][hw] fp32 -> g_xt [n][c] bf16.
// src_sel: 0 ext, 1 g_cur.  grid (18, 24, 16), block (32,8).
// ---------------------------------------------------------------------------
__global__ void convert_x_kernel(const float* __restrict__ ext, int src_sel)
{
    __shared__ float tile[32][33];
    const int b = blockIdx.z;
    const float* src = ((src_sel == 0) ? ext : g_cur) + (size_t)b * CC * HWs;
    const int hw0 = blockIdx.x * 32;
    const int c0  = blockIdx.y * 32;
    const int tx = threadIdx.x, ty = threadIdx.y;

    #pragma unroll
    for (int j = 0; j < 4; j++) {
        int c = ty * 4 + j;
        tile[c][tx] = src[(size_t)(c0 + c) * HWs + hw0 + tx];
    }
    __syncthreads();
    #pragma unroll
    for (int j = 0; j < 4; j++) {
        int hwl = ty * 4 + j;
        float v = tile[tx][hwl];
        __nv_bfloat16 h = __float2bfloat16(v);
        __nv_bfloat16 l = __float2bfloat16(v - __bfloat162float(h));
        size_t o = (size_t)(b * HWs + hw0 + hwl) * CC + c0 + tx;
        g_xth[o] = h;
        g_xtl[o] = l;
    }
}

// ---------------------------------------------------------------------------
// Split-bf16 mma.sync GEMM, 128(o) x 192(hw) per CTA, 512 threads,
// 3-stage cp.async ring, 1 barrier/stage, B-fragment hoisting,
// PASS-OUTER MMA ordering (same-acc reuse distance 6 -> hides HMMA latency).
// grid (3, 6, 16).
// ---------------------------------------------------------------------------
__global__ void __launch_bounds__(512, 1) gemm_mma_kernel(
    const __nv_bfloat16* __restrict__ Wh, const __nv_bfloat16* __restrict__ Wl,
    const __nv_bfloat16* __restrict__ Bh, const __nv_bfloat16* __restrict__ Bl,
    const float* __restrict__ bias, const float* __restrict__ resid, int residual,
    float* __restrict__ Y, int write_f32,
    __nv_bfloat16* __restrict__ dh, __nv_bfloat16* __restrict__ dl)
{
    extern __shared__ __align__(16) char sm[];
    const int t   = threadIdx.x;
    const int wid = t >> 5;
    const int lid = t & 31;
    const int n0  = blockIdx.x * 192;     // hw
    const int m0  = blockIdx.y * 128;     // o
    const int b   = blockIdx.z;
    const int warp_m = wid & 3;
    const int warp_n = wid >> 2;
    const uint32_t smbase = smem_u32(sm);

    auto load_stage = [&](int s, int slot) {
        const int k0 = s * 32;
        const uint32_t st = smbase + (uint32_t)slot * TS_STAGE;
        {
            int row = t >> 2, seg = t & 3;
            uint32_t d = st + (uint32_t)row * 80u + (uint32_t)seg * 16u;
            cp16(d,          Wh + (size_t)(m0 + row) * CC + k0 + seg * 8);
            cp16(d + 10240u, Wl + (size_t)(m0 + row) * CC + k0 + seg * 8);
        }
        #pragma unroll
        for (int it = 0; it < 2; it++) {
            int jdx = it * 512 + t;
            if (jdx < 768) {
                int row = jdx >> 2, seg = jdx & 3;
                uint32_t d = st + 20480u + (uint32_t)row * 80u + (uint32_t)seg * 16u;
                cp16(d,          Bh + (size_t)(b * HWs + n0 + row) * CC + k0 + seg * 8);
                cp16(d + 15360u, Bl + (size_t)(b * HWs + n0 + row) * CC + k0 + seg * 8);
            }
        }
    };

    float acc[2][6][4];
    #pragma unroll
    for (int mt = 0; mt < 2; mt++)
        #pragma unroll
        for (int j = 0; j < 6; j++)
            #pragma unroll
            for (int r = 0; r < 4; r++)
                acc[mt][j][r] = 0.f;

    load_stage(0, 0); cp_commit();
    load_stage(1, 1); cp_commit();

    for (int s = 0; s < 24; s++) {
        if (s + 1 < 24) cp_wait<1>(); else cp_wait<0>();
        __syncthreads();
        if (s + 2 < 24) { load_stage(s + 2, (s + 2) % 3); cp_commit(); }

        const uint32_t st = smbase + (uint32_t)(s % 3) * TS_STAGE;
        #pragma unroll
        for (int k16 = 0; k16 < 2; k16++) {
            const int kb = k16 * 16;
            uint32_t bh[12], bl[12];
            #pragma unroll
            for (int nt = 0; nt < 3; nt++) {
                uint32_t ba = st + 20480u
                    + (uint32_t)(warp_n * 48 + nt * 16 + (lid & 7) + ((lid >> 4) & 1) * 8) * 80u
                    + (uint32_t)(kb + ((lid >> 3) & 1) * 8) * 2u;
                ldsm4(&bh[nt * 4], ba);
                ldsm4(&bl[nt * 4], ba + 15360u);
            }
            #pragma unroll
            for (int mt = 0; mt < 2; mt++) {
                uint32_t ah[4], al[4];
                uint32_t aa = st
                    + (uint32_t)(warp_m * 32 + mt * 16 + (lid & 15)) * 80u
                    + (uint32_t)(kb + ((lid >> 4) & 1) * 8) * 2u;
                ldsm4(ah, aa);
                ldsm4(al, aa + 10240u);
                // pass-outer: same acc re-touched at distance 6 MMAs
                #pragma unroll
                for (int j = 0; j < 6; j++)
                    mma16816(acc[mt][j], ah, &bh[(j >> 1) * 4 + (j & 1) * 2]);
                #pragma unroll
                for (int j = 0; j < 6; j++)
                    mma16816(acc[mt][j], ah, &bl[(j >> 1) * 4 + (j & 1) * 2]);
                #pragma unroll
                for (int j = 0; j < 6; j++)
                    mma16816(acc[mt][j], al, &bh[(j >> 1) * 4 + (j & 1) * 2]);
            }
        }
    }

    // epilogue
    const size_t Yb = (size_t)b * CC * HWs;
    const int nb = b * HWs;
    #pragma unroll
    for (int mt = 0; mt < 2; mt++) {
        int R = m0 + warp_m * 32 + mt * 16 + (lid >> 2);
        float bs0 = bias[R], bs1 = bias[R + 8];
        #pragma unroll
        for (int j = 0; j < 6; j++) {
            int cb = n0 + warp_n * 48 + (j >> 1) * 16 + (j & 1) * 8 + (lid & 3) * 2;
            float v00 = acc[mt][j][0] + bs0, v01 = acc[mt][j][1] + bs0;
            float v10 = acc[mt][j][2] + bs1, v11 = acc[mt][j][3] + bs1;
            size_t a0 = Yb + (size_t)R * HWs + cb;
            size_t a1 = a0 + 8 * HWs;
            if (residual) {
                float2 r0 = *(const float2*)(resid + a0);
                float2 r1 = *(const float2*)(resid + a1);
                v00 += r0.x; v01 += r0.y; v10 += r1.x; v11 += r1.y;
            }
            if (write_f32) {
                *(float2*)(Y + a0) = make_float2(v00, v01);
                *(float2*)(Y + a1) = make_float2(v10, v11);
            }
            size_t r0o = (size_t)(nb + cb) * CC;
            size_t r1o = r0o + CC;
            __nv_bfloat16 h;
            h = __float2bfloat16(v00); dh[r0o + R]     = h; dl[r0o + R]     = __float2bfloat16(v00 - __bfloat162float(h));
            h = __float2bfloat16(v01); dh[r1o + R]     = h; dl[r1o + R]     = __float2bfloat16(v01 - __bfloat162float(h));
            h = __float2bfloat16(v10); dh[r0o + R + 8] = h; dl[r0o + R + 8] = __float2bfloat16(v10 - __bfloat162float(h));
            h = __float2bfloat16(v11); dh[r1o + R + 8] = h; dl[r1o + R + 8] = __float2bfloat16(v11 - __bfloat162float(h));
        }
    }
}

// ---------------------------------------------------------------------------
// mma.sync attention row-max: CTA 128 q x 192 keys, 512 threads, 3 ct-tiles,
// 24 k-chunks, 3-stage ring, 1 barrier/stage, pass-outer MMA ordering.
// grid (72 m-tiles, 16 bk).
// ---------------------------------------------------------------------------
#define A_NSTG  72               // 3 ct * 24 k-chunks

__global__ void __launch_bounds__(512, 1) attn_mma_kernel()
{
    extern __shared__ __align__(16) char sm[];
    __shared__ float srow[4][128];

    const int t   = threadIdx.x;
    const int wid = t >> 5;
    const int lid = t & 31;
    const int n0  = blockIdx.x * 128;
    const int bk  = blockIdx.y;
    const int warp_m = wid & 3;
    const int warp_n = wid >> 2;
    const uint32_t smbase = smem_u32(sm);

    auto load_stage = [&](int s, int slot) {
        const int hk0 = (s / 24) * 192;
        const int k0  = (s % 24) * 32;
        const uint32_t st = smbase + (uint32_t)slot * TS_STAGE;
        {
            int row = t >> 2, seg = t & 3;
            uint32_t d = st + (uint32_t)row * 80u + (uint32_t)seg * 16u;
            cp16(d,          g_qh + (size_t)(n0 + row) * CC + k0 + seg * 8);
            cp16(d + 10240u, g_ql + (size_t)(n0 + row) * CC + k0 + seg * 8);
        }
        #pragma unroll
        for (int it = 0; it < 2; it++) {
            int jdx = it * 512 + t;
            if (jdx < 768) {
                int row = jdx >> 2, seg = jdx & 3;
                uint32_t d = st + 20480u + (uint32_t)row * 80u + (uint32_t)seg * 16u;
                cp16(d,          g_kh + (size_t)(bk * HWs + hk0 + row) * CC + k0 + seg * 8);
                cp16(d + 15360u, g_kl + (size_t)(bk * HWs + hk0 + row) * CC + k0 + seg * 8);
            }
        }
    };

    float acc[2][6][4];
    float rm[2][2] = {{-3.402823e38f, -3.402823e38f}, {-3.402823e38f, -3.402823e38f}};

    load_stage(0, 0); cp_commit();
    load_stage(1, 1); cp_commit();

    for (int s = 0; s < A_NSTG; s++) {
        if (s + 1 < A_NSTG) cp_wait<1>(); else cp_wait<0>();
        __syncthreads();
        if (s + 2 < A_NSTG) { load_stage(s + 2, (s + 2) % 3); cp_commit(); }

        if ((s % 24) == 0) {
            #pragma unroll
            for (int mt = 0; mt < 2; mt++)
                #pragma unroll
                for (int j = 0; j < 6; j++)
                    #pragma unroll
                    for (int r = 0; r < 4; r++)
                        acc[mt][j][r] = 0.f;
        }

        const uint32_t st = smbase + (uint32_t)(s % 3) * TS_STAGE;
        #pragma unroll
        for (int k16 = 0; k16 < 2; k16++) {
            const int kb = k16 * 16;
            uint32_t bh[12], bl[12];
            #pragma unroll
            for (int nt = 0; nt < 3; nt++) {
                uint32_t ba = st + 20480u
                    + (uint32_t)(warp_n * 48 + nt * 16 + (lid & 7) + ((lid >> 4) & 1) * 8) * 80u
                    + (uint32_t)(kb + ((lid >> 3) & 1) * 8) * 2u;
                ldsm4(&bh[nt * 4], ba);
                ldsm4(&bl[nt * 4], ba + 15360u);
            }
            #pragma unroll
            for (int mt = 0; mt < 2; mt++) {
                uint32_t ah[4], al[4];
                uint32_t aa = st
                    + (uint32_t)(warp_m * 32 + mt * 16 + (lid & 15)) * 80u
                    + (uint32_t)(kb + ((lid >> 4) & 1) * 8) * 2u;
                ldsm4(ah, aa);
                ldsm4(al, aa + 10240u);
                #pragma unroll
                for (int j = 0; j < 6; j++)
                    mma16816(acc[mt][j], ah, &bh[(j >> 1) * 4 + (j & 1) * 2]);
                #pragma unroll
                for (int j = 0; j < 6; j++)
                    mma16816(acc[mt][j], ah, &bl[(j >> 1) * 4 + (j & 1) * 2]);
                #pragma unroll
                for (int j = 0; j < 6; j++)
                    mma16816(acc[mt][j], al, &bh[(j >> 1) * 4 + (j & 1) * 2]);
            }
        }

        if ((s % 24) == 23) {
            #pragma unroll
            for (int mt = 0; mt < 2; mt++) {
                float m0 = -3.402823e38f, m1 = -3.402823e38f;
                #pragma unroll
                for (int j = 0; j < 6; j++) {
                    m0 = fmaxf(m0, fmaxf(acc[mt][j][0], acc[mt][j][1]));
                    m1 = fmaxf(m1, fmaxf(acc[mt][j][2], acc[mt][j][3]));
                }
                m0 = fmaxf(m0, __shfl_xor_sync(0xffffffffu, m0, 1));
                m0 = fmaxf(m0, __shfl_xor_sync(0xffffffffu, m0, 2));
                m1 = fmaxf(m1, __shfl_xor_sync(0xffffffffu, m1, 1));
                m1 = fmaxf(m1, __shfl_xor_sync(0xffffffffu, m1, 2));
                rm[mt][0] = fmaxf(rm[mt][0], m0);
                rm[mt][1] = fmaxf(rm[mt][1], m1);
            }
        }
    }

    __syncthreads();
    if ((lid & 3) == 0) {
        #pragma unroll
        for (int mt = 0; mt < 2; mt++) {
            int r = warp_m * 32 + mt * 16 + (lid >> 2);
            srow[warp_n][r]     = rm[mt][0];
            srow[warp_n][r + 8] = rm[mt][1];
        }
    }
    __syncthreads();
    if (t < 128) {
        float m = fmaxf(fmaxf(srow[0][t], srow[1][t]), fmaxf(srow[2][t], srow[3][t]));
        g_maxpart[bk * NTOK + n0 + t] = m;
    }
}

// ---------------------------------------------------------------------------
__global__ void argmax_kernel()
{
    const int b = blockIdx.x;
    const int tid = threadIdx.x;
    __shared__ float sv[256];
    __shared__ int   si[256];

    float best = -3.402823e38f;
    int   bidx = 0;
    for (int hw = tid; hw < HWs; hw += 256) {
        float s = 0.f;
        #pragma unroll
        for (int bk = 0; bk < BB; bk++)
            s += g_maxpart[bk * NTOK + b * HWs + hw];
        if (s > best) { best = s; bidx = hw; }
    }
    sv[tid] = best; si[tid] = bidx;
    __syncthreads();
    for (int s = 128; s > 0; s >>= 1) {
        if (tid < s) {
            if (sv[tid + s] > sv[tid] ||
                (sv[tid + s] == sv[tid] && si[tid + s] < si[tid])) {
                sv[tid] = sv[tid + s];
                si[tid] = si[tid + s];
            }
        }
        __syncthreads();
    }
    if (tid == 0) g_hwstar[b] = si[0];
}

__global__ void norm_kernel()
{
    int p = blockIdx.x * blockDim.x + threadIdx.x;
    if (p >= NTOK) return;
    int b = p / HWs, hw = p % HWs;
    const float* xp = g_x5 + b * CC * HWs + hw;
    float s = 0.f;
    #pragma unroll 8
    for (int c = 0; c < CC; c++) {
        float v = xp[c * HWs];
        s = fmaf(v, v, s);
    }
    g_norm[p] = fmaxf(sqrtf(s), 1e-12f);
}

__global__ void seeds_kernel()
{
    int b = blockIdx.x;
    int c = threadIdx.x;
    int hws = g_hwstar[b];
    float inv = 1.f / g_norm[b * HWs + hws];
    g_seeds[b * CC + c] = g_x5[b * CC * HWs + c * HWs + hws] * inv;
}

__global__ void cor_kernel()
{
    __shared__ float ss[BB * CC];
    const int b = blockIdx.x;
    for (int i = threadIdx.x; i < BB * CC; i += blockDim.x) ss[i] = g_seeds[i];
    __syncthreads();

    const int hw = blockIdx.y * 192 + threadIdx.x;
    const float* xp = g_x5 + b * CC * HWs + hw;
    float acc[BB] = {};
    for (int c = 0; c < CC; c++) {
        float v = xp[c * HWs];
        #pragma unroll
        for (int o = 0; o < BB; o++)
            acc[o] = fmaf(v, ss[o * CC + c], acc[o]);
    }
    float s = 0.f;
    #pragma unroll
    for (int o = 0; o < BB; o++) s += fmaxf(acc[o], 0.f);
    g_cor[b * HWs + hw] = s / (16.f * g_norm[b * HWs + hw]);
}

__global__ void minmax_kernel()
{
    const int b = blockIdx.x;
    const int tid = threadIdx.x;
    __shared__ float smn[256], smx[256];
    float mn = 3.402823e38f, mx = -3.402823e38f;
    for (int hw = tid; hw < HWs; hw += 256) {
        float v = g_cor[b * HWs + hw];
        mn = fminf(mn, v);
        mx = fmaxf(mx, v);
    }
    smn[tid] = mn; smx[tid] = mx;
    __syncthreads();
    for (int s = 128; s > 0; s >>= 1) {
        if (tid < s) {
            smn[tid] = fminf(smn[tid], smn[tid + s]);
            smx[tid] = fmaxf(smx[tid], smx[tid + s]);
        }
        __syncthreads();
    }
    float m0 = smn[0];
    float inv = 1.f / (smx[0] - m0 + 1e-12f);
    for (int hw = tid; hw < HWs; hw += 256)
        g_cor[b * HWs + hw] = (g_cor[b * HWs + hw] - m0) * inv;
}

__global__ void apply_kernel(int add_prev)
{
    int idx = blockIdx.x * 256 + threadIdx.x;
    int b  = idx / (CC * HWs);
    int hw = idx % HWs;
    float v = g_x5[idx] * g_cor[b * HWs + hw];
    g_cur[idx] = (add_prev ? g_cur[idx] : 0.f) + v;
}

__global__ void consen_kernel()
{
    const int c = blockIdx.x;
    const int tid = threadIdx.x;
    __shared__ float sm[256];
    float s = 0.f;
    for (int b = 0; b < BB; b++) {
        const float* p = g_cur + b * CC * HWs + c * HWs;
        for (int hw = tid; hw < HWs; hw += 256) s += p[hw];
    }
    sm[tid] = s;
    __syncthreads();
    for (int st = 128; st > 0; st >>= 1) {
        if (tid < st) sm[tid] += sm[tid + st];
        __syncthreads();
    }
    if (tid == 0) g_consen[c] = sm[0] * (1.f / (float)(BB * HWs));
}

__global__ void final_kernel(const float* __restrict__ xin, float* __restrict__ out)
{
    int idx = blockIdx.x * 256 + threadIdx.x;
    int c = (idx / HWs) % CC;
    out[idx] = g_cur[idx] + xin[idx] * g_consen[c];
}

// ---------------------------------------------------------------------------
extern "C" void kernel_launch(void* const* d_in, const int* in_sizes, int n_in,
                              void* d_out, int out_size)
{
    const float* x5      = (const float*)d_in[0];
    const float* conv_w  = (const float*)d_in[1];
    const float* conv_b  = (const float*)d_in[2];
    const float* query_w = (const float*)d_in[3];
    const float* query_b = (const float*)d_in[4];
    const float* key_w   = (const float*)d_in[5];
    const float* key_b   = (const float*)d_in[6];
    float* out = (float*)d_out;

    cudaFuncSetAttribute(attn_mma_kernel,
                         cudaFuncAttributeMaxDynamicSharedMemorySize, TS_DYN);
    cudaFuncSetAttribute(gemm_mma_kernel,
                         cudaFuncAttributeMaxDynamicSharedMemorySize, TS_DYN);

    __nv_bfloat16 *wh_p, *wl_p, *xth_p, *xtl_p, *x5th_p, *x5tl_p;
    __nv_bfloat16 *qh_p, *ql_p, *kh_p, *kl_p;
    cudaGetSymbolAddress((void**)&wh_p, g_wh);
    cudaGetSymbolAddress((void**)&wl_p, g_wl);
    cudaGetSymbolAddress((void**)&xth_p, g_xth);
    cudaGetSymbolAddress((void**)&xtl_p, g_xtl);
    cudaGetSymbolAddress((void**)&x5th_p, g_x5th);
    cudaGetSymbolAddress((void**)&x5tl_p, g_x5tl);
    cudaGetSymbolAddress((void**)&qh_p, g_qh);
    cudaGetSymbolAddress((void**)&ql_p, g_ql);
    cudaGetSymbolAddress((void**)&kh_p, g_kh);
    cudaGetSymbolAddress((void**)&kl_p, g_kl);
    float *x5g_p, *cur_p;
    cudaGetSymbolAddress((void**)&x5g_p, g_x5);
    cudaGetSymbolAddress((void**)&cur_p, g_cur);

    dim3 wgrid(NLAYER * CC * CC / 256, 3);  // (9216, 3)
    dim3 xgrid(HWs / 32, CC / 32, BB);      // (18, 24, 16)
    dim3 mgrid(HWs / 192, CC / 128, BB);    // (3, 6, 16)
    dim3 agrid(NTOK / 128, BB);             // (72, 16)
    dim3 cgrid(BB, HWs / 192);              // (16, 3)
    const int egrid = ELEMS / 256;          // 27648

    convert_w_kernel<<<wgrid, 256>>>(conv_w, query_w, key_w);

    const size_t WSZ = (size_t)CC * CC;
    for (int i = 0; i < NLAYER; i++) {
        convert_x_kernel<<<xgrid, dim3(32, 8)>>>(x5, (i == 0) ? 0 : 1);
        // x5 = conv(cur) + bias + cur   (fp32 + fused transposed bf16 out)
        gemm_mma_kernel<<<mgrid, 512, TS_DYN>>>(
            wh_p + i * WSZ, wl_p + i * WSZ, xth_p, xtl_p,
            conv_b + i * CC, (i == 0) ? x5 : cur_p, 1,
            x5g_p, 1, x5th_p, x5tl_p);
        // q, k: transposed bf16 hi/lo only
        gemm_mma_kernel<<<mgrid, 512, TS_DYN>>>(
            wh_p + (NLAYER + i) * WSZ, wl_p + (NLAYER + i) * WSZ, x5th_p, x5tl_p,
            query_b + i * CC, nullptr, 0,
            nullptr, 0, qh_p, ql_p);
        gemm_mma_kernel<<<mgrid, 512, TS_DYN>>>(
            wh_p + (2 * NLAYER + i) * WSZ, wl_p + (2 * NLAYER + i) * WSZ, x5th_p, x5tl_p,
            key_b + i * CC, nullptr, 0,
            nullptr, 0, kh_p, kl_p);
        attn_mma_kernel<<<agrid, 512, TS_DYN>>>();
        argmax_kernel<<<BB, 256>>>();
        norm_kernel<<<NTOK / 256, 256>>>();
        seeds_kernel<<<BB, CC>>>();
        cor_kernel<<<cgrid, 192>>>();
        minmax_kernel<<<BB, 256>>>();
        apply_kernel<<<egrid, 256>>>(i > 0 ? 1 : 0);
    }
    consen_kernel<<<CC, 256>>>();
    final_kernel<<<egrid, 256>>>(x5, out);
}

// round 10
// speedup vs baseline: 3.4286x; 1.0519x over previous
#include <cuda_runtime.h>
#include <cuda_bf16.h>
#include <cstdint>

// Problem constants
#define BB   16
#define CC   768
#define HWs  576
#define NTOK (BB*HWs)          // 9216
#define ELEMS (BB*CC*HWs)      // 7,077,888
#define NLAYER 4

// Scratch (device globals; no allocation allowed)
__device__ float g_cur[ELEMS];
__device__ float g_x5[ELEMS];
__device__ __nv_bfloat16 g_qh[(size_t)NTOK*CC];
__device__ __nv_bfloat16 g_ql[(size_t)NTOK*CC];
__device__ __nv_bfloat16 g_kh[(size_t)NTOK*CC];
__device__ __nv_bfloat16 g_kl[(size_t)NTOK*CC];
__device__ __nv_bfloat16 g_xth[(size_t)NTOK*CC];    // layer input transposed hi
__device__ __nv_bfloat16 g_xtl[(size_t)NTOK*CC];    // lo
__device__ __nv_bfloat16 g_x5th[(size_t)NTOK*CC];   // x5 transposed hi
__device__ __nv_bfloat16 g_x5tl[(size_t)NTOK*CC];   // lo
__device__ __nv_bfloat16 g_wh[(size_t)3*NLAYER*CC*CC];
__device__ __nv_bfloat16 g_wl[(size_t)3*NLAYER*CC*CC];
__device__ float g_maxpart[BB*NTOK];
__device__ float g_seeds[BB*CC];
__device__ float g_cor[BB*HWs];
__device__ float g_consen[CC];

// ============================ PTX helpers (sm_80+ only) =====================
__device__ __forceinline__ uint32_t smem_u32(const void* p) {
    uint32_t a;
    asm("{ .reg .u64 t; cvta.to.shared.u64 t, %1; cvt.u32.u64 %0, t; }" : "=r"(a) : "l"(p));
    return a;
}
__device__ __forceinline__ void cp16(uint32_t d, const void* s) {
    asm volatile("cp.async.cg.shared.global [%0], [%1], 16;" :: "r"(d), "l"(s));
}
__device__ __forceinline__ void cp_commit() { asm volatile("cp.async.commit_group;"); }
template<int N> __device__ __forceinline__ void cp_wait() {
    asm volatile("cp.async.wait_group %0;" :: "n"(N));
}
__device__ __forceinline__ void ldsm4(uint32_t* r, uint32_t a) {
    asm volatile("ldmatrix.sync.aligned.m8n8.x4.shared.b16 {%0,%1,%2,%3}, [%4];"
                 : "=r"(r[0]), "=r"(r[1]), "=r"(r[2]), "=r"(r[3]) : "r"(a));
}
__device__ __forceinline__ void mma16816(float* d, const uint32_t* a, const uint32_t* b) {
    asm volatile("mma.sync.aligned.m16n8k16.row.col.f32.bf16.bf16.f32 "
                 "{%0,%1,%2,%3}, {%4,%5,%6,%7}, {%8,%9}, {%0,%1,%2,%3};"
                 : "+f"(d[0]), "+f"(d[1]), "+f"(d[2]), "+f"(d[3])
                 : "r"(a[0]), "r"(a[1]), "r"(a[2]), "r"(a[3]), "r"(b[0]), "r"(b[1]));
}

// 128(A rows) x 96(B rows) x 32(k) stage, 80B rows:
// Ah[128]@0 (10240) | Al@10240 | Bh[96]@20480 (7680) | Bl@28160  => 35840 B
#define TS_STAGE 35840
#define TS_DYN   (3*TS_STAGE)    // 107520  (x2 CTAs = 215040 <= 228KB/SM)

// ---------------------------------------------------------------------------
// Weight conversion: fp32 [o][c] -> bf16 hi/lo.  grid (9216, 3), block 256.
// ---------------------------------------------------------------------------
__global__ void convert_w_kernel(const float* __restrict__ cw,
                                 const float* __restrict__ qw,
                                 const float* __restrict__ kw)
{
    const int z = blockIdx.y;
    const float* src = (z == 0) ? cw : (z == 1 ? qw : kw);
    const size_t off = (size_t)z * NLAYER * CC * CC;
    const size_t idx = (size_t)blockIdx.x * 256 + threadIdx.x;
    float v = src[idx];
    __nv_bfloat16 h = __float2bfloat16(v);
    __nv_bfloat16 l = __float2bfloat16(v - __bfloat162float(h));
    g_wh[off + idx] = h;
    g_wl[off + idx] = l;
}

// ---------------------------------------------------------------------------
// Layer-0 input conversion+transpose: ext [b][c][hw] fp32 -> g_xt [n][c] bf16.
// grid (18, 24, 16), block (32,8).
// ---------------------------------------------------------------------------
__global__ void convert_x_kernel(const float* __restrict__ ext)
{
    __shared__ float tile[32][33];
    const int b = blockIdx.z;
    const float* src = ext + (size_t)b * CC * HWs;
    const int hw0 = blockIdx.x * 32;
    const int c0  = blockIdx.y * 32;
    const int tx = threadIdx.x, ty = threadIdx.y;

    #pragma unroll
    for (int j = 0; j < 4; j++) {
        int c = ty * 4 + j;
        tile[c][tx] = src[(size_t)(c0 + c) * HWs + hw0 + tx];
    }
    __syncthreads();
    #pragma unroll
    for (int j = 0; j < 4; j++) {
        int hwl = ty * 4 + j;
        float v = tile[tx][hwl];
        __nv_bfloat16 h = __float2bfloat16(v);
        __nv_bfloat16 l = __float2bfloat16(v - __bfloat162float(h));
        size_t o = (size_t)(b * HWs + hw0 + hwl) * CC + c0 + tx;
        g_xth[o] = h;
        g_xtl[o] = l;
    }
}

// ---------------------------------------------------------------------------
// Split-bf16 mma.sync GEMM, 128(o) x 96(hw) per CTA, 256 threads, 2 CTAs/SM,
// 3-stage cp.async ring, 1 barrier/stage.  grid (6, 6, 16).
// ---------------------------------------------------------------------------
__global__ void __launch_bounds__(256, 2) gemm_mma_kernel(
    const __nv_bfloat16* __restrict__ Wh, const __nv_bfloat16* __restrict__ Wl,
    const __nv_bfloat16* __restrict__ Bh, const __nv_bfloat16* __restrict__ Bl,
    const float* __restrict__ bias, const float* __restrict__ resid, int residual,
    float* __restrict__ Y, int write_f32,
    __nv_bfloat16* __restrict__ dh, __nv_bfloat16* __restrict__ dl)
{
    extern __shared__ __align__(16) char sm[];
    const int t   = threadIdx.x;
    const int wid = t >> 5;
    const int lid = t & 31;
    const int n0  = blockIdx.x * 96;      // hw
    const int m0  = blockIdx.y * 128;     // o
    const int b   = blockIdx.z;
    const int warp_m = wid & 3;           // 32-row slice of o
    const int warp_n = wid >> 2;          // 0..1 -> 48-col slice of hw
    const uint32_t smbase = smem_u32(sm);

    auto load_stage = [&](int s, int slot) {
        const int k0 = s * 32;
        const uint32_t st = smbase + (uint32_t)slot * TS_STAGE;
        #pragma unroll
        for (int it = 0; it < 2; it++) {   // A: 128 rows x 4 segs
            int jdx = it * 256 + t;
            int row = jdx >> 2, seg = jdx & 3;
            uint32_t d = st + (uint32_t)row * 80u + (uint32_t)seg * 16u;
            cp16(d,          Wh + (size_t)(m0 + row) * CC + k0 + seg * 8);
            cp16(d + 10240u, Wl + (size_t)(m0 + row) * CC + k0 + seg * 8);
        }
        #pragma unroll
        for (int it = 0; it < 2; it++) {   // B: 96 rows x 4 segs = 384 jobs
            int jdx = it * 256 + t;
            if (jdx < 384) {
                int row = jdx >> 2, seg = jdx & 3;
                uint32_t d = st + 20480u + (uint32_t)row * 80u + (uint32_t)seg * 16u;
                cp16(d,         Bh + (size_t)(b * HWs + n0 + row) * CC + k0 + seg * 8);
                cp16(d + 7680u, Bl + (size_t)(b * HWs + n0 + row) * CC + k0 + seg * 8);
            }
        }
    };

    float acc[2][6][4];
    #pragma unroll
    for (int mt = 0; mt < 2; mt++)
        #pragma unroll
        for (int j = 0; j < 6; j++)
            #pragma unroll
            for (int r = 0; r < 4; r++)
                acc[mt][j][r] = 0.f;

    load_stage(0, 0); cp_commit();
    load_stage(1, 1); cp_commit();

    for (int s = 0; s < 24; s++) {
        if (s + 1 < 24) cp_wait<1>(); else cp_wait<0>();
        __syncthreads();
        if (s + 2 < 24) { load_stage(s + 2, (s + 2) % 3); cp_commit(); }

        const uint32_t st = smbase + (uint32_t)(s % 3) * TS_STAGE;
        #pragma unroll
        for (int k16 = 0; k16 < 2; k16++) {
            const int kb = k16 * 16;
            uint32_t bh[12], bl[12];
            #pragma unroll
            for (int nt = 0; nt < 3; nt++) {
                uint32_t ba = st + 20480u
                    + (uint32_t)(warp_n * 48 + nt * 16 + (lid & 7) + ((lid >> 4) & 1) * 8) * 80u
                    + (uint32_t)(kb + ((lid >> 3) & 1) * 8) * 2u;
                ldsm4(&bh[nt * 4], ba);
                ldsm4(&bl[nt * 4], ba + 7680u);
            }
            #pragma unroll
            for (int mt = 0; mt < 2; mt++) {
                uint32_t ah[4], al[4];
                uint32_t aa = st
                    + (uint32_t)(warp_m * 32 + mt * 16 + (lid & 15)) * 80u
                    + (uint32_t)(kb + ((lid >> 4) & 1) * 8) * 2u;
                ldsm4(ah, aa);
                ldsm4(al, aa + 10240u);
                #pragma unroll
                for (int j = 0; j < 6; j++)
                    mma16816(acc[mt][j], ah, &bh[(j >> 1) * 4 + (j & 1) * 2]);
                #pragma unroll
                for (int j = 0; j < 6; j++)
                    mma16816(acc[mt][j], ah, &bl[(j >> 1) * 4 + (j & 1) * 2]);
                #pragma unroll
                for (int j = 0; j < 6; j++)
                    mma16816(acc[mt][j], al, &bh[(j >> 1) * 4 + (j & 1) * 2]);
            }
        }
    }

    // epilogue
    const size_t Yb = (size_t)b * CC * HWs;
    const int nb = b * HWs;
    #pragma unroll
    for (int mt = 0; mt < 2; mt++) {
        int R = m0 + warp_m * 32 + mt * 16 + (lid >> 2);
        float bs0 = bias[R], bs1 = bias[R + 8];
        #pragma unroll
        for (int j = 0; j < 6; j++) {
            int cb = n0 + warp_n * 48 + (j >> 1) * 16 + (j & 1) * 8 + (lid & 3) * 2;
            float v00 = acc[mt][j][0] + bs0, v01 = acc[mt][j][1] + bs0;
            float v10 = acc[mt][j][2] + bs1, v11 = acc[mt][j][3] + bs1;
            size_t a0 = Yb + (size_t)R * HWs + cb;
            size_t a1 = a0 + 8 * HWs;
            if (residual) {
                float2 r0 = *(const float2*)(resid + a0);
                float2 r1 = *(const float2*)(resid + a1);
                v00 += r0.x; v01 += r0.y; v10 += r1.x; v11 += r1.y;
            }
            if (write_f32) {
                *(float2*)(Y + a0) = make_float2(v00, v01);
                *(float2*)(Y + a1) = make_float2(v10, v11);
            }
            size_t r0o = (size_t)(nb + cb) * CC;
            size_t r1o = r0o + CC;
            __nv_bfloat16 h;
            h = __float2bfloat16(v00); dh[r0o + R]     = h; dl[r0o + R]     = __float2bfloat16(v00 - __bfloat162float(h));
            h = __float2bfloat16(v01); dh[r1o + R]     = h; dl[r1o + R]     = __float2bfloat16(v01 - __bfloat162float(h));
            h = __float2bfloat16(v10); dh[r0o + R + 8] = h; dl[r0o + R + 8] = __float2bfloat16(v10 - __bfloat162float(h));
            h = __float2bfloat16(v11); dh[r1o + R + 8] = h; dl[r1o + R + 8] = __float2bfloat16(v11 - __bfloat162float(h));
        }
    }
}

// ---------------------------------------------------------------------------
// mma.sync attention row-max: CTA 128 q x 96 keys, 256 threads, 2 CTAs/SM,
// 6 ct-tiles x 24 k-chunks = 144 stages, 3-stage ring.
// grid (72 m-tiles, 16 bk).
// ---------------------------------------------------------------------------
#define A_NSTG  144              // 6 ct * 24 k-chunks

__global__ void __launch_bounds__(256, 2) attn_mma_kernel()
{
    extern __shared__ __align__(16) char sm[];
    __shared__ float srow[2][128];

    const int t   = threadIdx.x;
    const int wid = t >> 5;
    const int lid = t & 31;
    const int n0  = blockIdx.x * 128;
    const int bk  = blockIdx.y;
    const int warp_m = wid & 3;
    const int warp_n = wid >> 2;
    const uint32_t smbase = smem_u32(sm);

    auto load_stage = [&](int s, int slot) {
        const int hk0 = (s / 24) * 96;
        const int k0  = (s % 24) * 32;
        const uint32_t st = smbase + (uint32_t)slot * TS_STAGE;
        #pragma unroll
        for (int it = 0; it < 2; it++) {
            int jdx = it * 256 + t;
            int row = jdx >> 2, seg = jdx & 3;
            uint32_t d = st + (uint32_t)row * 80u + (uint32_t)seg * 16u;
            cp16(d,          g_qh + (size_t)(n0 + row) * CC + k0 + seg * 8);
            cp16(d + 10240u, g_ql + (size_t)(n0 + row) * CC + k0 + seg * 8);
        }
        #pragma unroll
        for (int it = 0; it < 2; it++) {
            int jdx = it * 256 + t;
            if (jdx < 384) {
                int row = jdx >> 2, seg = jdx & 3;
                uint32_t d = st + 20480u + (uint32_t)row * 80u + (uint32_t)seg * 16u;
                cp16(d,         g_kh + (size_t)(bk * HWs + hk0 + row) * CC + k0 + seg * 8);
                cp16(d + 7680u, g_kl + (size_t)(bk * HWs + hk0 + row) * CC + k0 + seg * 8);
            }
        }
    };

    float acc[2][6][4];
    float rm[2][2] = {{-3.402823e38f, -3.402823e38f}, {-3.402823e38f, -3.402823e38f}};

    load_stage(0, 0); cp_commit();
    load_stage(1, 1); cp_commit();

    for (int s = 0; s < A_NSTG; s++) {
        if (s + 1 < A_NSTG) cp_wait<1>(); else cp_wait<0>();
        __syncthreads();
        if (s + 2 < A_NSTG) { load_stage(s + 2, (s + 2) % 3); cp_commit(); }

        if ((s % 24) == 0) {
            #pragma unroll
            for (int mt = 0; mt < 2; mt++)
                #pragma unroll
                for (int j = 0; j < 6; j++)
                    #pragma unroll
                    for (int r = 0; r < 4; r++)
                        acc[mt][j][r] = 0.f;
        }

        const uint32_t st = smbase + (uint32_t)(s % 3) * TS_STAGE;
        #pragma unroll
        for (int k16 = 0; k16 < 2; k16++) {
            const int kb = k16 * 16;
            uint32_t bh[12], bl[12];
            #pragma unroll
            for (int nt = 0; nt < 3; nt++) {
                uint32_t ba = st + 20480u
                    + (uint32_t)(warp_n * 48 + nt * 16 + (lid & 7) + ((lid >> 4) & 1) * 8) * 80u
                    + (uint32_t)(kb + ((lid >> 3) & 1) * 8) * 2u;
                ldsm4(&bh[nt * 4], ba);
                ldsm4(&bl[nt * 4], ba + 7680u);
            }
            #pragma unroll
            for (int mt = 0; mt < 2; mt++) {
                uint32_t ah[4], al[4];
                uint32_t aa = st
                    + (uint32_t)(warp_m * 32 + mt * 16 + (lid & 15)) * 80u
                    + (uint32_t)(kb + ((lid >> 4) & 1) * 8) * 2u;
                ldsm4(ah, aa);
                ldsm4(al, aa + 10240u);
                #pragma unroll
                for (int j = 0; j < 6; j++)
                    mma16816(acc[mt][j], ah, &bh[(j >> 1) * 4 + (j & 1) * 2]);
                #pragma unroll
                for (int j = 0; j < 6; j++)
                    mma16816(acc[mt][j], ah, &bl[(j >> 1) * 4 + (j & 1) * 2]);
                #pragma unroll
                for (int j = 0; j < 6; j++)
                    mma16816(acc[mt][j], al, &bh[(j >> 1) * 4 + (j & 1) * 2]);
            }
        }

        if ((s % 24) == 23) {
            #pragma unroll
            for (int mt = 0; mt < 2; mt++) {
                float m0 = -3.402823e38f, m1 = -3.402823e38f;
                #pragma unroll
                for (int j = 0; j < 6; j++) {
                    m0 = fmaxf(m0, fmaxf(acc[mt][j][0], acc[mt][j][1]));
                    m1 = fmaxf(m1, fmaxf(acc[mt][j][2], acc[mt][j][3]));
                }
                m0 = fmaxf(m0, __shfl_xor_sync(0xffffffffu, m0, 1));
                m0 = fmaxf(m0, __shfl_xor_sync(0xffffffffu, m0, 2));
                m1 = fmaxf(m1, __shfl_xor_sync(0xffffffffu, m1, 1));
                m1 = fmaxf(m1, __shfl_xor_sync(0xffffffffu, m1, 2));
                rm[mt][0] = fmaxf(rm[mt][0], m0);
                rm[mt][1] = fmaxf(rm[mt][1], m1);
            }
        }
    }

    __syncthreads();
    if ((lid & 3) == 0) {
        #pragma unroll
        for (int mt = 0; mt < 2; mt++) {
            int r = warp_m * 32 + mt * 16 + (lid >> 2);
            srow[warp_n][r]     = rm[mt][0];
            srow[warp_n][r + 8] = rm[mt][1];
        }
    }
    __syncthreads();
    if (t < 128)
        g_maxpart[bk * NTOK + n0 + t] = fmaxf(srow[0][t], srow[1][t]);
}

// ---------------------------------------------------------------------------
// argmax over hw of sum_bk maxpart, then seeds = x5[:,hw*]/||x5[:,hw*]||.
// grid = 16 (one block per b), block 256.
// ---------------------------------------------------------------------------
__global__ void argmax_seeds_kernel()
{
    const int b = blockIdx.x;
    const int tid = threadIdx.x;
    __shared__ float sv[256];
    __shared__ int   si[256];
    __shared__ int   s_hw;
    __shared__ float s_inv;

    float best = -3.402823e38f;
    int   bidx = 0;
    for (int hw = tid; hw < HWs; hw += 256) {
        float s = 0.f;
        #pragma unroll
        for (int bk = 0; bk < BB; bk++)
            s += g_maxpart[bk * NTOK + b * HWs + hw];
        if (s > best) { best = s; bidx = hw; }
    }
    sv[tid] = best; si[tid] = bidx;
    __syncthreads();
    for (int s = 128; s > 0; s >>= 1) {
        if (tid < s) {
            if (sv[tid + s] > sv[tid] ||
                (sv[tid + s] == sv[tid] && si[tid + s] < si[tid])) {
                sv[tid] = sv[tid + s];
                si[tid] = si[tid + s];
            }
        }
        __syncthreads();
    }
    if (tid == 0) s_hw = si[0];
    __syncthreads();

    // gather column, compute norm, write seeds
    const int hws = s_hw;
    float vv[3];
    float sq = 0.f;
    #pragma unroll
    for (int j = 0; j < 3; j++) {
        int c = tid + j * 256;
        vv[j] = g_x5[(size_t)b * CC * HWs + (size_t)c * HWs + hws];
        sq = fmaf(vv[j], vv[j], sq);
    }
    sv[tid] = sq;
    __syncthreads();
    for (int s = 128; s > 0; s >>= 1) {
        if (tid < s) sv[tid] += sv[tid + s];
        __syncthreads();
    }
    if (tid == 0) s_inv = 1.f / fmaxf(sqrtf(sv[0]), 1e-12f);
    __syncthreads();
    float inv = s_inv;
    #pragma unroll
    for (int j = 0; j < 3; j++)
        g_seeds[b * CC + tid + j * 256] = vv[j] * inv;
}

// ---------------------------------------------------------------------------
// cor[b,hw] = (1/16) * sum_{b'} relu(x5[b,:,hw] . seeds[b',:]) / ||x5[b,:,hw]||
// self-norm fused into the same serial c loop (bit-exact vs old norm_kernel).
// grid=(16,3), block=192.
// ---------------------------------------------------------------------------
__global__ void cor_kernel()
{
    __shared__ float ss[BB * CC];
    const int b = blockIdx.x;
    for (int i = threadIdx.x; i < BB * CC; i += blockDim.x) ss[i] = g_seeds[i];
    __syncthreads();

    const int hw = blockIdx.y * 192 + threadIdx.x;
    const float* xp = g_x5 + (size_t)b * CC * HWs + hw;
    float acc[BB] = {};
    float sq = 0.f;
    for (int c = 0; c < CC; c++) {
        float v = xp[(size_t)c * HWs];
        sq = fmaf(v, v, sq);
        #pragma unroll
        for (int o = 0; o < BB; o++)
            acc[o] = fmaf(v, ss[o * CC + c], acc[o]);
    }
    float s = 0.f;
    #pragma unroll
    for (int o = 0; o < BB; o++) s += fmaxf(acc[o], 0.f);
    float nrm = fmaxf(sqrtf(sq), 1e-12f);
    g_cor[b * HWs + hw] = s / (16.f * nrm);
}

// Per-batch min-max normalize of cor. grid=16, block=256.
__global__ void minmax_kernel()
{
    const int b = blockIdx.x;
    const int tid = threadIdx.x;
    __shared__ float smn[256], smx[256];
    float mn = 3.402823e38f, mx = -3.402823e38f;
    for (int hw = tid; hw < HWs; hw += 256) {
        float v = g_cor[b * HWs + hw];
        mn = fminf(mn, v);
        mx = fmaxf(mx, v);
    }
    smn[tid] = mn; smx[tid] = mx;
    __syncthreads();
    for (int s = 128; s > 0; s >>= 1) {
        if (tid < s) {
            smn[tid] = fminf(smn[tid], smn[tid + s]);
            smx[tid] = fmaxf(smx[tid], smx[tid + s]);
        }
        __syncthreads();
    }
    float m0 = smn[0];
    float inv = 1.f / (smx[0] - m0 + 1e-12f);
    for (int hw = tid; hw < HWs; hw += 256)
        g_cor[b * HWs + hw] = (g_cor[b * HWs + hw] - m0) * inv;
}

// ---------------------------------------------------------------------------
// apply + transpose-convert: cur = (add_prev?cur:0) + x5*cor, AND write
// cur transposed bf16 hi/lo (next layer's GEMM B operand).
// grid (18, 24, 16), block (32,8).
// ---------------------------------------------------------------------------
__global__ void apply_t_kernel(int add_prev)
{
    __shared__ float tile[32][33];
    const int b = blockIdx.z;
    const int hw0 = blockIdx.x * 32;
    const int c0  = blockIdx.y * 32;
    const int tx = threadIdx.x, ty = threadIdx.y;

    const float corv = g_cor[b * HWs + hw0 + tx];
    const size_t base = (size_t)b * CC * HWs;

    #pragma unroll
    for (int j = 0; j < 4; j++) {
        int c = c0 + ty * 4 + j;
        size_t idx = base + (size_t)c * HWs + hw0 + tx;
        float v = g_x5[idx] * corv;
        if (add_prev) v += g_cur[idx];
        g_cur[idx] = v;
        tile[ty * 4 + j][tx] = v;
    }
    __syncthreads();
    #pragma unroll
    for (int j = 0; j < 4; j++) {
        int hwl = ty * 4 + j;
        float v = tile[tx][hwl];
        __nv_bfloat16 h = __float2bfloat16(v);
        __nv_bfloat16 l = __float2bfloat16(v - __bfloat162float(h));
        size_t o = (size_t)(b * HWs + hw0 + hwl) * CC + c0 + tx;
        g_xth[o] = h;
        g_xtl[o] = l;
    }
}

// consen[c] = mean over (b,hw) of cur. grid=768, block=256.
__global__ void consen_kernel()
{
    const int c = blockIdx.x;
    const int tid = threadIdx.x;
    __shared__ float sm[256];
    float s = 0.f;
    for (int b = 0; b < BB; b++) {
        const float* p = g_cur + (size_t)b * CC * HWs + (size_t)c * HWs;
        for (int hw = tid; hw < HWs; hw += 256) s += p[hw];
    }
    sm[tid] = s;
    __syncthreads();
    for (int st = 128; st > 0; st >>= 1) {
        if (tid < st) sm[tid] += sm[tid + st];
        __syncthreads();
    }
    if (tid == 0) g_consen[c] = sm[0] * (1.f / (float)(BB * HWs));
}

__global__ void final_kernel(const float* __restrict__ xin, float* __restrict__ out)
{
    int idx = blockIdx.x * 256 + threadIdx.x;
    int c = (idx / HWs) % CC;
    out[idx] = g_cur[idx] + xin[idx] * g_consen[c];
}

// ---------------------------------------------------------------------------
extern "C" void kernel_launch(void* const* d_in, const int* in_sizes, int n_in,
                              void* d_out, int out_size)
{
    const float* x5      = (const float*)d_in[0];
    const float* conv_w  = (const float*)d_in[1];
    const float* conv_b  = (const float*)d_in[2];
    const float* query_w = (const float*)d_in[3];
    const float* query_b = (const float*)d_in[4];
    const float* key_w   = (const float*)d_in[5];
    const float* key_b   = (const float*)d_in[6];
    float* out = (float*)d_out;

    cudaFuncSetAttribute(attn_mma_kernel,
                         cudaFuncAttributeMaxDynamicSharedMemorySize, TS_DYN);
    cudaFuncSetAttribute(gemm_mma_kernel,
                         cudaFuncAttributeMaxDynamicSharedMemorySize, TS_DYN);

    __nv_bfloat16 *wh_p, *wl_p, *xth_p, *xtl_p, *x5th_p, *x5tl_p;
    __nv_bfloat16 *qh_p, *ql_p, *kh_p, *kl_p;
    cudaGetSymbolAddress((void**)&wh_p, g_wh);
    cudaGetSymbolAddress((void**)&wl_p, g_wl);
    cudaGetSymbolAddress((void**)&xth_p, g_xth);
    cudaGetSymbolAddress((void**)&xtl_p, g_xtl);
    cudaGetSymbolAddress((void**)&x5th_p, g_x5th);
    cudaGetSymbolAddress((void**)&x5tl_p, g_x5tl);
    cudaGetSymbolAddress((void**)&qh_p, g_qh);
    cudaGetSymbolAddress((void**)&ql_p, g_ql);
    cudaGetSymbolAddress((void**)&kh_p, g_kh);
    cudaGetSymbolAddress((void**)&kl_p, g_kl);
    float *x5g_p, *cur_p;
    cudaGetSymbolAddress((void**)&x5g_p, g_x5);
    cudaGetSymbolAddress((void**)&cur_p, g_cur);

    dim3 wgrid(NLAYER * CC * CC / 256, 3);  // (9216, 3)
    dim3 xgrid(HWs / 32, CC / 32, BB);      // (18, 24, 16)
    dim3 mgrid(HWs / 96, CC / 128, BB);     // (6, 6, 16)
    dim3 agrid(NTOK / 128, BB);             // (72, 16)
    dim3 cgrid(BB, HWs / 192);              // (16, 3)
    const int egrid = ELEMS / 256;          // 27648

    convert_w_kernel<<<wgrid, 256>>>(conv_w, query_w, key_w);
    convert_x_kernel<<<xgrid, dim3(32, 8)>>>(x5);   // layer-0 input only

    const size_t WSZ = (size_t)CC * CC;
    for (int i = 0; i < NLAYER; i++) {
        // x5 = conv(cur) + bias + cur   (fp32 + fused transposed bf16 out)
        gemm_mma_kernel<<<mgrid, 256, TS_DYN>>>(
            wh_p + i * WSZ, wl_p + i * WSZ, xth_p, xtl_p,
            conv_b + i * CC, (i == 0) ? x5 : cur_p, 1,
            x5g_p, 1, x5th_p, x5tl_p);
        // q, k: transposed bf16 hi/lo only
        gemm_mma_kernel<<<mgrid, 256, TS_DYN>>>(
            wh_p + (NLAYER + i) * WSZ, wl_p + (NLAYER + i) * WSZ, x5th_p, x5tl_p,
            query_b + i * CC, nullptr, 0,
            nullptr, 0, qh_p, ql_p);
        gemm_mma_kernel<<<mgrid, 256, TS_DYN>>>(
            wh_p + (2 * NLAYER + i) * WSZ, wl_p + (2 * NLAYER + i) * WSZ, x5th_p, x5tl_p,
            key_b + i * CC, nullptr, 0,
            nullptr, 0, kh_p, kl_p);
        attn_mma_kernel<<<agrid, 256, TS_DYN>>>();
        argmax_seeds_kernel<<<BB, 256>>>();
        cor_kernel<<<cgrid, 192>>>();
        minmax_kernel<<<BB, 256>>>();
        apply_t_kernel<<<xgrid, dim3(32, 8)>>>(i > 0 ? 1 : 0);   // writes cur + next xt
    }
    consen_kernel<<<CC, 256>>>();
    final_kernel<<<egrid, 256>>>(x5, out);
}

// round 12
// speedup vs baseline: 3.5151x; 1.0252x over previous
#include <cuda_runtime.h>
#include <cuda_bf16.h>
#include <cstdint>

// Problem constants
#define BB   16
#define CC   768
#define HWs  576
#define NTOK (BB*HWs)          // 9216
#define ELEMS (BB*CC*HWs)      // 7,077,888
#define NLAYER 4

// Scratch (device globals; no allocation allowed)
__device__ float g_cur[ELEMS];
__device__ float g_x5[ELEMS];
__device__ float g_qt[(size_t)NTOK*CC];             // q transposed fp32 [n][c]
__device__ float g_kt[(size_t)NTOK*CC];             // k transposed fp32 [n][c]
__device__ __nv_bfloat16 g_xth[(size_t)NTOK*CC];    // layer input transposed hi
__device__ __nv_bfloat16 g_xtl[(size_t)NTOK*CC];    // lo
__device__ __nv_bfloat16 g_x5th[(size_t)NTOK*CC];   // x5 transposed hi
__device__ __nv_bfloat16 g_x5tl[(size_t)NTOK*CC];   // lo
__device__ __nv_bfloat16 g_wh[(size_t)3*NLAYER*CC*CC];
__device__ __nv_bfloat16 g_wl[(size_t)3*NLAYER*CC*CC];
__device__ float g_maxpart[BB*NTOK];
__device__ float g_seeds[BB*CC];
__device__ float g_cor[BB*HWs];
__device__ float g_consen[CC];

// ============================ PTX helpers (sm_80+ only) =====================
__device__ __forceinline__ uint32_t smem_u32(const void* p) {
    uint32_t a;
    asm("{ .reg .u64 t; cvta.to.shared.u64 t, %1; cvt.u32.u64 %0, t; }" : "=r"(a) : "l"(p));
    return a;
}
__device__ __forceinline__ void cp16(uint32_t d, const void* s) {
    asm volatile("cp.async.cg.shared.global [%0], [%1], 16;" :: "r"(d), "l"(s));
}
__device__ __forceinline__ void cp_commit() { asm volatile("cp.async.commit_group;"); }
template<int N> __device__ __forceinline__ void cp_wait() {
    asm volatile("cp.async.wait_group %0;" :: "n"(N));
}
__device__ __forceinline__ void ldsm4(uint32_t* r, uint32_t a) {
    asm volatile("ldmatrix.sync.aligned.m8n8.x4.shared.b16 {%0,%1,%2,%3}, [%4];"
                 : "=r"(r[0]), "=r"(r[1]), "=r"(r[2]), "=r"(r[3]) : "r"(a));
}
__device__ __forceinline__ void mma16816(float* d, const uint32_t* a, const uint32_t* b) {
    asm volatile("mma.sync.aligned.m16n8k16.row.col.f32.bf16.bf16.f32 "
                 "{%0,%1,%2,%3}, {%4,%5,%6,%7}, {%8,%9}, {%0,%1,%2,%3};"
                 : "+f"(d[0]), "+f"(d[1]), "+f"(d[2]), "+f"(d[3])
                 : "r"(a[0]), "r"(a[1]), "r"(a[2]), "r"(a[3]), "r"(b[0]), "r"(b[1]));
}
__device__ __forceinline__ float ldsf(uint32_t a) {
    float v;
    asm volatile("ld.shared.f32 %0, [%1];" : "=f"(v) : "r"(a));
    return v;
}
__device__ __forceinline__ uint32_t cvt_tf32(float v) {
    uint32_t r;
    asm volatile("cvt.rna.tf32.f32 %0, %1;" : "=r"(r) : "f"(v));
    return r;
}
__device__ __forceinline__ void mma1688_tf32(float* d, const uint32_t* a,
                                             uint32_t b0, uint32_t b1) {
    asm volatile("mma.sync.aligned.m16n8k8.row.col.f32.tf32.tf32.f32 "
                 "{%0,%1,%2,%3}, {%4,%5,%6,%7}, {%8,%9}, {%0,%1,%2,%3};"
                 : "+f"(d[0]), "+f"(d[1]), "+f"(d[2]), "+f"(d[3])
                 : "r"(a[0]), "r"(a[1]), "r"(a[2]), "r"(a[3]), "r"(b0), "r"(b1));
}

// ---- bf16 GEMM stage: 128(A) x 96(B) x 32k, 80B rows ----
// Ah[128]@0 (10240) | Al@10240 | Bh[96]@20480 (7680) | Bl@28160 => 35840 B
#define TS_STAGE 35840
#define TS_DYN   (3*TS_STAGE)    // 107520  (x2 CTAs = 215040 <= 228KB/SM)

// ---- tf32 attention stage: 128(q) x 96(k) x 32k fp32, 144B rows (36 floats) ----
// A[128]@0 (18432) | B[96]@18432 (13824) => 32256 B
#define AT_STAGE 32256
#define AT_DYN   (3*AT_STAGE)    // 96768  (x2 CTAs = 193536 <= 228KB/SM)

// ---------------------------------------------------------------------------
// Weight conversion: fp32 [o][c] -> bf16 hi/lo.  grid (9216, 3), block 256.
// ---------------------------------------------------------------------------
__global__ void convert_w_kernel(const float* __restrict__ cw,
                                 const float* __restrict__ qw,
                                 const float* __restrict__ kw)
{
    const int z = blockIdx.y;
    const float* src = (z == 0) ? cw : (z == 1 ? qw : kw);
    const size_t off = (size_t)z * NLAYER * CC * CC;
    const size_t idx = (size_t)blockIdx.x * 256 + threadIdx.x;
    float v = src[idx];
    __nv_bfloat16 h = __float2bfloat16(v);
    __nv_bfloat16 l = __float2bfloat16(v - __bfloat162float(h));
    g_wh[off + idx] = h;
    g_wl[off + idx] = l;
}

// ---------------------------------------------------------------------------
// Layer-0 input conversion+transpose: ext [b][c][hw] fp32 -> g_xt [n][c] bf16.
// grid (18, 24, 16), block (32,8).
// ---------------------------------------------------------------------------
__global__ void convert_x_kernel(const float* __restrict__ ext)
{
    __shared__ float tile[32][33];
    const int b = blockIdx.z;
    const float* src = ext + (size_t)b * CC * HWs;
    const int hw0 = blockIdx.x * 32;
    const int c0  = blockIdx.y * 32;
    const int tx = threadIdx.x, ty = threadIdx.y;

    #pragma unroll
    for (int j = 0; j < 4; j++) {
        int c = ty * 4 + j;
        tile[c][tx] = src[(size_t)(c0 + c) * HWs + hw0 + tx];
    }
    __syncthreads();
    #pragma unroll
    for (int j = 0; j < 4; j++) {
        int hwl = ty * 4 + j;
        float v = tile[tx][hwl];
        __nv_bfloat16 h = __float2bfloat16(v);
        __nv_bfloat16 l = __float2bfloat16(v - __bfloat162float(h));
        size_t o = (size_t)(b * HWs + hw0 + hwl) * CC + c0 + tx;
        g_xth[o] = h;
        g_xtl[o] = l;
    }
}

// ---------------------------------------------------------------------------
// Split-bf16 mma.sync GEMM, 128(o) x 96(hw) per CTA, 256 threads, 2 CTAs/SM,
// 3-stage cp.async ring.  grid (6, 6, 16).
// Output: if ft != nullptr -> fp32 transposed [(b*HWs+hw)*CC + o] (q/k path);
// else bf16 hi/lo transposed dh/dl, and optionally fp32 Y (+residual).
// ---------------------------------------------------------------------------
__global__ void __launch_bounds__(256, 2) gemm_mma_kernel(
    const __nv_bfloat16* __restrict__ Wh, const __nv_bfloat16* __restrict__ Wl,
    const __nv_bfloat16* __restrict__ Bh, const __nv_bfloat16* __restrict__ Bl,
    const float* __restrict__ bias, const float* __restrict__ resid, int residual,
    float* __restrict__ Y, int write_f32,
    __nv_bfloat16* __restrict__ dh, __nv_bfloat16* __restrict__ dl,
    float* __restrict__ ft)
{
    extern __shared__ __align__(16) char sm[];
    const int t   = threadIdx.x;
    const int wid = t >> 5;
    const int lid = t & 31;
    const int n0  = blockIdx.x * 96;      // hw
    const int m0  = blockIdx.y * 128;     // o
    const int b   = blockIdx.z;
    const int warp_m = wid & 3;
    const int warp_n = wid >> 2;
    const uint32_t smbase = smem_u32(sm);

    auto load_stage = [&](int s, int slot) {
        const int k0 = s * 32;
        const uint32_t st = smbase + (uint32_t)slot * TS_STAGE;
        #pragma unroll
        for (int it = 0; it < 2; it++) {   // A: 128 rows x 4 segs
            int jdx = it * 256 + t;
            int row = jdx >> 2, seg = jdx & 3;
            uint32_t d = st + (uint32_t)row * 80u + (uint32_t)seg * 16u;
            cp16(d,          Wh + (size_t)(m0 + row) * CC + k0 + seg * 8);
            cp16(d + 10240u, Wl + (size_t)(m0 + row) * CC + k0 + seg * 8);
        }
        #pragma unroll
        for (int it = 0; it < 2; it++) {   // B: 96 rows x 4 segs = 384 jobs
            int jdx = it * 256 + t;
            if (jdx < 384) {
                int row = jdx >> 2, seg = jdx & 3;
                uint32_t d = st + 20480u + (uint32_t)row * 80u + (uint32_t)seg * 16u;
                cp16(d,         Bh + (size_t)(b * HWs + n0 + row) * CC + k0 + seg * 8);
                cp16(d + 7680u, Bl + (size_t)(b * HWs + n0 + row) * CC + k0 + seg * 8);
            }
        }
    };

    float acc[2][6][4];
    #pragma unroll
    for (int mt = 0; mt < 2; mt++)
        #pragma unroll
        for (int j = 0; j < 6; j++)
            #pragma unroll
            for (int r = 0; r < 4; r++)
                acc[mt][j][r] = 0.f;

    load_stage(0, 0); cp_commit();
    load_stage(1, 1); cp_commit();

    for (int s = 0; s < 24; s++) {
        if (s + 1 < 24) cp_wait<1>(); else cp_wait<0>();
        __syncthreads();
        if (s + 2 < 24) { load_stage(s + 2, (s + 2) % 3); cp_commit(); }

        const uint32_t st = smbase + (uint32_t)(s % 3) * TS_STAGE;
        #pragma unroll
        for (int k16 = 0; k16 < 2; k16++) {
            const int kb = k16 * 16;
            uint32_t bh[12], bl[12];
            #pragma unroll
            for (int nt = 0; nt < 3; nt++) {
                uint32_t ba = st + 20480u
                    + (uint32_t)(warp_n * 48 + nt * 16 + (lid & 7) + ((lid >> 4) & 1) * 8) * 80u
                    + (uint32_t)(kb + ((lid >> 3) & 1) * 8) * 2u;
                ldsm4(&bh[nt * 4], ba);
                ldsm4(&bl[nt * 4], ba + 7680u);
            }
            #pragma unroll
            for (int mt = 0; mt < 2; mt++) {
                uint32_t ah[4], al[4];
                uint32_t aa = st
                    + (uint32_t)(warp_m * 32 + mt * 16 + (lid & 15)) * 80u
                    + (uint32_t)(kb + ((lid >> 4) & 1) * 8) * 2u;
                ldsm4(ah, aa);
                ldsm4(al, aa + 10240u);
                #pragma unroll
                for (int j = 0; j < 6; j++)
                    mma16816(acc[mt][j], ah, &bh[(j >> 1) * 4 + (j & 1) * 2]);
                #pragma unroll
                for (int j = 0; j < 6; j++)
                    mma16816(acc[mt][j], ah, &bl[(j >> 1) * 4 + (j & 1) * 2]);
                #pragma unroll
                for (int j = 0; j < 6; j++)
                    mma16816(acc[mt][j], al, &bh[(j >> 1) * 4 + (j & 1) * 2]);
            }
        }
    }

    // epilogue
    const size_t Yb = (size_t)b * CC * HWs;
    const int nb = b * HWs;
    #pragma unroll
    for (int mt = 0; mt < 2; mt++) {
        int R = m0 + warp_m * 32 + mt * 16 + (lid >> 2);
        float bs0 = bias[R], bs1 = bias[R + 8];
        #pragma unroll
        for (int j = 0; j < 6; j++) {
            int cb = n0 + warp_n * 48 + (j >> 1) * 16 + (j & 1) * 8 + (lid & 3) * 2;
            float v00 = acc[mt][j][0] + bs0, v01 = acc[mt][j][1] + bs0;
            float v10 = acc[mt][j][2] + bs1, v11 = acc[mt][j][3] + bs1;
            size_t r0o = (size_t)(nb + cb) * CC;
            size_t r1o = r0o + CC;
            if (ft) {
                ft[r0o + R]     = v00;
                ft[r1o + R]     = v01;
                ft[r0o + R + 8] = v10;
                ft[r1o + R + 8] = v11;
            } else {
                size_t a0 = Yb + (size_t)R * HWs + cb;
                size_t a1 = a0 + 8 * HWs;
                if (residual) {
                    float2 r0 = *(const float2*)(resid + a0);
                    float2 r1 = *(const float2*)(resid + a1);
                    v00 += r0.x; v01 += r0.y; v10 += r1.x; v11 += r1.y;
                }
                if (write_f32) {
                    *(float2*)(Y + a0) = make_float2(v00, v01);
                    *(float2*)(Y + a1) = make_float2(v10, v11);
                }
                __nv_bfloat16 h;
                h = __float2bfloat16(v00); dh[r0o + R]     = h; dl[r0o + R]     = __float2bfloat16(v00 - __bfloat162float(h));
                h = __float2bfloat16(v01); dh[r1o + R]     = h; dl[r1o + R]     = __float2bfloat16(v01 - __bfloat162float(h));
                h = __float2bfloat16(v10); dh[r0o + R + 8] = h; dl[r0o + R + 8] = __float2bfloat16(v10 - __bfloat162float(h));
                h = __float2bfloat16(v11); dh[r1o + R + 8] = h; dl[r1o + R + 8] = __float2bfloat16(v11 - __bfloat162float(h));
            }
        }
    }
}

// ---------------------------------------------------------------------------
// tf32 attention row-max: CTA 128 q x 96 keys, 256 threads, 2 CTAs/SM,
// 6 ct-tiles x 24 k-chunks = 144 stages, 3-stage ring, 1-pass tf32 m16n8k8.
// grid (72 m-tiles, 16 bk).
// ---------------------------------------------------------------------------
#define A_NSTG  144              // 6 ct * 24 k-chunks

__global__ void __launch_bounds__(256, 2) attn_mma_kernel()
{
    extern __shared__ __align__(16) char sm[];
    __shared__ float srow[2][128];

    const int t   = threadIdx.x;
    const int wid = t >> 5;
    const int lid = t & 31;
    const int n0  = blockIdx.x * 128;
    const int bk  = blockIdx.y;
    const int warp_m = wid & 3;
    const int warp_n = wid >> 2;
    const uint32_t smbase = smem_u32(sm);

    auto load_stage = [&](int s, int slot) {
        const int hk0 = (s / 24) * 96;
        const int k0  = (s % 24) * 32;
        const uint32_t st = smbase + (uint32_t)slot * AT_STAGE;
        #pragma unroll
        for (int it = 0; it < 4; it++) {   // A: 128 rows x 8 segs = 1024 jobs
            int jdx = it * 256 + t;
            int row = jdx >> 3, seg = jdx & 7;
            uint32_t d = st + (uint32_t)row * 144u + (uint32_t)seg * 16u;
            cp16(d, g_qt + (size_t)(n0 + row) * CC + k0 + seg * 4);
        }
        #pragma unroll
        for (int it = 0; it < 3; it++) {   // B: 96 rows x 8 segs = 768 jobs
            int jdx = it * 256 + t;
            int row = jdx >> 3, seg = jdx & 7;
            uint32_t d = st + 18432u + (uint32_t)row * 144u + (uint32_t)seg * 16u;
            cp16(d, g_kt + (size_t)(bk * HWs + hk0 + row) * CC + k0 + seg * 4);
        }
    };

    float acc[2][6][4];
    float rm[2][2] = {{-3.402823e38f, -3.402823e38f}, {-3.402823e38f, -3.402823e38f}};

    load_stage(0, 0); cp_commit();
    load_stage(1, 1); cp_commit();

    for (int s = 0; s < A_NSTG; s++) {
        if (s + 1 < A_NSTG) cp_wait<1>(); else cp_wait<0>();
        __syncthreads();
        if (s + 2 < A_NSTG) { load_stage(s + 2, (s + 2) % 3); cp_commit(); }

        if ((s % 24) == 0) {
            #pragma unroll
            for (int mt = 0; mt < 2; mt++)
                #pragma unroll
                for (int j = 0; j < 6; j++)
                    #pragma unroll
                    for (int r = 0; r < 4; r++)
                        acc[mt][j][r] = 0.f;
        }

        const uint32_t st = smbase + (uint32_t)(s % 3) * AT_STAGE;
        #pragma unroll
        for (int k8 = 0; k8 < 4; k8++) {
            const uint32_t kb4 = (uint32_t)(k8 * 8 + (lid & 3)) * 4u;
            // B fragments: 6 n8-tiles x 2 regs
            uint32_t bf0[6], bf1[6];
            #pragma unroll
            for (int nt = 0; nt < 6; nt++) {
                uint32_t ba = st + 18432u
                    + (uint32_t)(warp_n * 48 + nt * 8 + (lid >> 2)) * 144u + kb4;
                bf0[nt] = cvt_tf32(ldsf(ba));
                bf1[nt] = cvt_tf32(ldsf(ba + 16u));
            }
            #pragma unroll
            for (int mt = 0; mt < 2; mt++) {
                uint32_t aa = st
                    + (uint32_t)(warp_m * 32 + mt * 16 + (lid >> 2)) * 144u + kb4;
                uint32_t af[4];
                af[0] = cvt_tf32(ldsf(aa));                  // (r,   c)
                af[1] = cvt_tf32(ldsf(aa + 8u * 144u));      // (r+8, c)
                af[2] = cvt_tf32(ldsf(aa + 16u));            // (r,   c+4)
                af[3] = cvt_tf32(ldsf(aa + 8u * 144u + 16u));// (r+8, c+4)
                #pragma unroll
                for (int nt = 0; nt < 6; nt++)
                    mma1688_tf32(acc[mt][nt], af, bf0[nt], bf1[nt]);
            }
        }

        if ((s % 24) == 23) {
            #pragma unroll
            for (int mt = 0; mt < 2; mt++) {
                float m0 = -3.402823e38f, m1 = -3.402823e38f;
                #pragma unroll
                for (int j = 0; j < 6; j++) {
                    m0 = fmaxf(m0, fmaxf(acc[mt][j][0], acc[mt][j][1]));
                    m1 = fmaxf(m1, fmaxf(acc[mt][j][2], acc[mt][j][3]));
                }
                m0 = fmaxf(m0, __shfl_xor_sync(0xffffffffu, m0, 1));
                m0 = fmaxf(m0, __shfl_xor_sync(0xffffffffu, m0, 2));
                m1 = fmaxf(m1, __shfl_xor_sync(0xffffffffu, m1, 1));
                m1 = fmaxf(m1, __shfl_xor_sync(0xffffffffu, m1, 2));
                rm[mt][0] = fmaxf(rm[mt][0], m0);
                rm[mt][1] = fmaxf(rm[mt][1], m1);
            }
        }
    }

    __syncthreads();
    if ((lid & 3) == 0) {
        #pragma unroll
        for (int mt = 0; mt < 2; mt++) {
            int r = warp_m * 32 + mt * 16 + (lid >> 2);
            srow[warp_n][r]     = rm[mt][0];
            srow[warp_n][r + 8] = rm[mt][1];
        }
    }
    __syncthreads();
    if (t < 128)
        g_maxpart[bk * NTOK + n0 + t] = fmaxf(srow[0][t], srow[1][t]);
}

// ---------------------------------------------------------------------------
// argmax over hw of sum_bk maxpart, then seeds = x5[:,hw*]/||x5[:,hw*]||.
// grid = 16, block 256.
// ---------------------------------------------------------------------------
__global__ void argmax_seeds_kernel()
{
    const int b = blockIdx.x;
    const int tid = threadIdx.x;
    __shared__ float sv[256];
    __shared__ int   si[256];
    __shared__ int   s_hw;
    __shared__ float s_inv;

    float best = -3.402823e38f;
    int   bidx = 0;
    for (int hw = tid; hw < HWs; hw += 256) {
        float s = 0.f;
        #pragma unroll
        for (int bk = 0; bk < BB; bk++)
            s += g_maxpart[bk * NTOK + b * HWs + hw];
        if (s > best) { best = s; bidx = hw; }
    }
    sv[tid] = best; si[tid] = bidx;
    __syncthreads();
    for (int s = 128; s > 0; s >>= 1) {
        if (tid < s) {
            if (sv[tid + s] > sv[tid] ||
                (sv[tid + s] == sv[tid] && si[tid + s] < si[tid])) {
                sv[tid] = sv[tid + s];
                si[tid] = si[tid + s];
            }
        }
        __syncthreads();
    }
    if (tid == 0) s_hw = si[0];
    __syncthreads();

    const int hws = s_hw;
    float vv[3];
    float sq = 0.f;
    #pragma unroll
    for (int j = 0; j < 3; j++) {
        int c = tid + j * 256;
        vv[j] = g_x5[(size_t)b * CC * HWs + (size_t)c * HWs + hws];
        sq = fmaf(vv[j], vv[j], sq);
    }
    sv[tid] = sq;
    __syncthreads();
    for (int s = 128; s > 0; s >>= 1) {
        if (tid < s) sv[tid] += sv[tid + s];
        __syncthreads();
    }
    if (tid == 0) s_inv = 1.f / fmaxf(sqrtf(sv[0]), 1e-12f);
    __syncthreads();
    float inv = s_inv;
    #pragma unroll
    for (int j = 0; j < 3; j++)
        g_seeds[b * CC + tid + j * 256] = vv[j] * inv;
}

// ---------------------------------------------------------------------------
// cor[b,hw] = (1/16) * sum_{b'} relu(x5[b,:,hw] . seeds[b',:]) / ||x5[b,:,hw]||
// grid=(16,3), block=192.
// ---------------------------------------------------------------------------
__global__ void cor_kernel()
{
    __shared__ float ss[BB * CC];
    const int b = blockIdx.x;
    for (int i = threadIdx.x; i < BB * CC; i += blockDim.x) ss[i] = g_seeds[i];
    __syncthreads();

    const int hw = blockIdx.y * 192 + threadIdx.x;
    const float* xp = g_x5 + (size_t)b * CC * HWs + hw;
    float acc[BB] = {};
    float sq = 0.f;
    for (int c = 0; c < CC; c++) {
        float v = xp[(size_t)c * HWs];
        sq = fmaf(v, v, sq);
        #pragma unroll
        for (int o = 0; o < BB; o++)
            acc[o] = fmaf(v, ss[o * CC + c], acc[o]);
    }
    float s = 0.f;
    #pragma unroll
    for (int o = 0; o < BB; o++) s += fmaxf(acc[o], 0.f);
    float nrm = fmaxf(sqrtf(sq), 1e-12f);
    g_cor[b * HWs + hw] = s / (16.f * nrm);
}

// Per-batch min-max normalize of cor. grid=16, block=256.
__global__ void minmax_kernel()
{
    const int b = blockIdx.x;
    const int tid = threadIdx.x;
    __shared__ float smn[256], smx[256];
    float mn = 3.402823e38f, mx = -3.402823e38f;
    for (int hw = tid; hw < HWs; hw += 256) {
        float v = g_cor[b * HWs + hw];
        mn = fminf(mn, v);
        mx = fmaxf(mx, v);
    }
    smn[tid] = mn; smx[tid] = mx;
    __syncthreads();
    for (int s = 128; s > 0; s >>= 1) {
        if (tid < s) {
            smn[tid] = fminf(smn[tid], smn[tid + s]);
            smx[tid] = fmaxf(smx[tid], smx[tid + s]);
        }
        __syncthreads();
    }
    float m0 = smn[0];
    float inv = 1.f / (smx[0] - m0 + 1e-12f);
    for (int hw = tid; hw < HWs; hw += 256)
        g_cor[b * HWs + hw] = (g_cor[b * HWs + hw] - m0) * inv;
}

// ---------------------------------------------------------------------------
// apply + transpose-convert: cur = (add_prev?cur:0) + x5*cor, AND write
// cur transposed bf16 hi/lo.  grid (18, 24, 16), block (32,8).
// ---------------------------------------------------------------------------
__global__ void apply_t_kernel(int add_prev)
{
    __shared__ float tile[32][33];
    const int b = blockIdx.z;
    const int hw0 = blockIdx.x * 32;
    const int c0  = blockIdx.y * 32;
    const int tx = threadIdx.x, ty = threadIdx.y;

    const float corv = g_cor[b * HWs + hw0 + tx];
    const size_t base = (size_t)b * CC * HWs;

    #pragma unroll
    for (int j = 0; j < 4; j++) {
        int c = c0 + ty * 4 + j;
        size_t idx = base + (size_t)c * HWs + hw0 + tx;
        float v = g_x5[idx] * corv;
        if (add_prev) v += g_cur[idx];
        g_cur[idx] = v;
        tile[ty * 4 + j][tx] = v;
    }
    __syncthreads();
    #pragma unroll
    for (int j = 0; j < 4; j++) {
        int hwl = ty * 4 + j;
        float v = tile[tx][hwl];
        __nv_bfloat16 h = __float2bfloat16(v);
        __nv_bfloat16 l = __float2bfloat16(v - __bfloat162float(h));
        size_t o = (size_t)(b * HWs + hw0 + hwl) * CC + c0 + tx;
        g_xth[o] = h;
        g_xtl[o] = l;
    }
}

// consen[c] = mean over (b,hw) of cur. grid=768, block=256.
__global__ void consen_kernel()
{
    const int c = blockIdx.x;
    const int tid = threadIdx.x;
    __shared__ float sm[256];
    float s = 0.f;
    for (int b = 0; b < BB; b++) {
        const float* p = g_cur + (size_t)b * CC * HWs + (size_t)c * HWs;
        for (int hw = tid; hw < HWs; hw += 256) s += p[hw];
    }
    sm[tid] = s;
    __syncthreads();
    for (int st = 128; st > 0; st >>= 1) {
        if (tid < st) sm[tid] += sm[tid + st];
        __syncthreads();
    }
    if (tid == 0) g_consen[c] = sm[0] * (1.f / (float)(BB * HWs));
}

__global__ void final_kernel(const float* __restrict__ xin, float* __restrict__ out)
{
    int idx = blockIdx.x * 256 + threadIdx.x;
    int c = (idx / HWs) % CC;
    out[idx] = g_cur[idx] + xin[idx] * g_consen[c];
}

// ---------------------------------------------------------------------------
extern "C" void kernel_launch(void* const* d_in, const int* in_sizes, int n_in,
                              void* d_out, int out_size)
{
    const float* x5      = (const float*)d_in[0];
    const float* conv_w  = (const float*)d_in[1];
    const float* conv_b  = (const float*)d_in[2];
    const float* query_w = (const float*)d_in[3];
    const float* query_b = (const float*)d_in[4];
    const float* key_w   = (const float*)d_in[5];
    const float* key_b   = (const float*)d_in[6];
    float* out = (float*)d_out;

    cudaFuncSetAttribute(attn_mma_kernel,
                         cudaFuncAttributeMaxDynamicSharedMemorySize, AT_DYN);
    cudaFuncSetAttribute(gemm_mma_kernel,
                         cudaFuncAttributeMaxDynamicSharedMemorySize, TS_DYN);

    __nv_bfloat16 *wh_p, *wl_p, *xth_p, *xtl_p, *x5th_p, *x5tl_p;
    cudaGetSymbolAddress((void**)&wh_p, g_wh);
    cudaGetSymbolAddress((void**)&wl_p, g_wl);
    cudaGetSymbolAddress((void**)&xth_p, g_xth);
    cudaGetSymbolAddress((void**)&xtl_p, g_xtl);
    cudaGetSymbolAddress((void**)&x5th_p, g_x5th);
    cudaGetSymbolAddress((void**)&x5tl_p, g_x5tl);
    float *x5g_p, *cur_p, *qt_p, *kt_p;
    cudaGetSymbolAddress((void**)&x5g_p, g_x5);
    cudaGetSymbolAddress((void**)&cur_p, g_cur);
    cudaGetSymbolAddress((void**)&qt_p, g_qt);
    cudaGetSymbolAddress((void**)&kt_p, g_kt);

    dim3 wgrid(NLAYER * CC * CC / 256, 3);  // (9216, 3)
    dim3 xgrid(HWs / 32, CC / 32, BB);      // (18, 24, 16)
    dim3 mgrid(HWs / 96, CC / 128, BB);     // (6, 6, 16)
    dim3 agrid(NTOK / 128, BB);             // (72, 16)
    dim3 cgrid(BB, HWs / 192);              // (16, 3)
    const int egrid = ELEMS / 256;          // 27648

    convert_w_kernel<<<wgrid, 256>>>(conv_w, query_w, key_w);
    convert_x_kernel<<<xgrid, dim3(32, 8)>>>(x5);   // layer-0 input only

    const size_t WSZ = (size_t)CC * CC;
    for (int i = 0; i < NLAYER; i++) {
        // x5 = conv(cur) + bias + cur   (fp32 + fused transposed bf16 out)
        gemm_mma_kernel<<<mgrid, 256, TS_DYN>>>(
            wh_p + i * WSZ, wl_p + i * WSZ, xth_p, xtl_p,
            conv_b + i * CC, (i == 0) ? x5 : cur_p, 1,
            x5g_p, 1, x5th_p, x5tl_p, nullptr);
        // q, k: fp32 transposed (tf32 attention operands)
        gemm_mma_kernel<<<mgrid, 256, TS_DYN>>>(
            wh_p + (NLAYER + i) * WSZ, wl_p + (NLAYER + i) * WSZ, x5th_p, x5tl_p,
            query_b + i * CC, nullptr, 0,
            nullptr, 0, nullptr, nullptr, qt_p);
        gemm_mma_kernel<<<mgrid, 256, TS_DYN>>>(
            wh_p + (2 * NLAYER + i) * WSZ, wl_p + (2 * NLAYER + i) * WSZ, x5th_p, x5tl_p,
            key_b + i * CC, nullptr, 0,
            nullptr, 0, nullptr, nullptr, kt_p);
        attn_mma_kernel<<<agrid, 256, AT_DYN>>>();
        argmax_seeds_kernel<<<BB, 256>>>();
        cor_kernel<<<cgrid, 192>>>();
        minmax_kernel<<<BB, 256>>>();
        apply_t_kernel<<<xgrid, dim3(32, 8)>>>(i > 0 ? 1 : 0);
    }
    consen_kernel<<<CC, 256>>>();
    final_kernel<<<egrid, 256>>>(x5, out);
}

// round 13
// speedup vs baseline: 4.0573x; 1.1543x over previous
#include <cuda_runtime.h>
#include <cuda_bf16.h>
#include <cstdint>

// Problem constants
#define BB   16
#define CC   768
#define HWs  576
#define NTOK (BB*HWs)          // 9216
#define ELEMS (BB*CC*HWs)      // 7,077,888
#define NLAYER 4

// Scratch (device globals; no allocation allowed)
__device__ float g_cur[ELEMS];
__device__ float g_x5[ELEMS];
__device__ float g_qt[(size_t)NTOK*CC];             // q transposed, tf32-rounded fp32 [n][c]
__device__ float g_kt[(size_t)NTOK*CC];             // k transposed, tf32-rounded fp32 [n][c]
__device__ __nv_bfloat16 g_xth[(size_t)NTOK*CC];    // layer input transposed hi
__device__ __nv_bfloat16 g_xtl[(size_t)NTOK*CC];    // lo
__device__ __nv_bfloat16 g_x5th[(size_t)NTOK*CC];   // x5 transposed hi
__device__ __nv_bfloat16 g_x5tl[(size_t)NTOK*CC];   // lo
__device__ __nv_bfloat16 g_wh[(size_t)3*NLAYER*CC*CC];
__device__ __nv_bfloat16 g_wl[(size_t)3*NLAYER*CC*CC];
__device__ float g_maxpart[BB*NTOK];
__device__ float g_seeds[BB*CC];
__device__ float g_cor[BB*HWs];
__device__ float g_consen[CC];

// ============================ PTX helpers (sm_80+ only) =====================
__device__ __forceinline__ uint32_t smem_u32(const void* p) {
    uint32_t a;
    asm("{ .reg .u64 t; cvta.to.shared.u64 t, %1; cvt.u32.u64 %0, t; }" : "=r"(a) : "l"(p));
    return a;
}
__device__ __forceinline__ void cp16(uint32_t d, const void* s) {
    asm volatile("cp.async.cg.shared.global [%0], [%1], 16;" :: "r"(d), "l"(s));
}
__device__ __forceinline__ void cp_commit() { asm volatile("cp.async.commit_group;"); }
template<int N> __device__ __forceinline__ void cp_wait() {
    asm volatile("cp.async.wait_group %0;" :: "n"(N));
}
__device__ __forceinline__ void ldsm4(uint32_t* r, uint32_t a) {
    asm volatile("ldmatrix.sync.aligned.m8n8.x4.shared.b16 {%0,%1,%2,%3}, [%4];"
                 : "=r"(r[0]), "=r"(r[1]), "=r"(r[2]), "=r"(r[3]) : "r"(a));
}
__device__ __forceinline__ void mma16816(float* d, const uint32_t* a, const uint32_t* b) {
    asm volatile("mma.sync.aligned.m16n8k16.row.col.f32.bf16.bf16.f32 "
                 "{%0,%1,%2,%3}, {%4,%5,%6,%7}, {%8,%9}, {%0,%1,%2,%3};"
                 : "+f"(d[0]), "+f"(d[1]), "+f"(d[2]), "+f"(d[3])
                 : "r"(a[0]), "r"(a[1]), "r"(a[2]), "r"(a[3]), "r"(b[0]), "r"(b[1]));
}
__device__ __forceinline__ uint32_t cvt_tf32(float v) {
    uint32_t r;
    asm volatile("cvt.rna.tf32.f32 %0, %1;" : "=r"(r) : "f"(v));
    return r;
}
__device__ __forceinline__ void mma1688_tf32(float* d, const uint32_t* a,
                                             uint32_t b0, uint32_t b1) {
    asm volatile("mma.sync.aligned.m16n8k8.row.col.f32.tf32.tf32.f32 "
                 "{%0,%1,%2,%3}, {%4,%5,%6,%7}, {%8,%9}, {%0,%1,%2,%3};"
                 : "+f"(d[0]), "+f"(d[1]), "+f"(d[2]), "+f"(d[3])
                 : "r"(a[0]), "r"(a[1]), "r"(a[2]), "r"(a[3]), "r"(b0), "r"(b1));
}

// ---- bf16 GEMM stage: 128(A) x 96(B) x 32k, 80B rows ----
// Ah[128]@0 (10240) | Al@10240 | Bh[96]@20480 (7680) | Bl@28160 => 35840 B
#define TS_STAGE 35840
#define TS_DYN   (3*TS_STAGE)    // 107520  (x2 CTAs = 215040 <= 228KB/SM)

// ---- tf32 attention stage: 128(q) x 96(k) x 32k fp32, 144B rows (36 floats) ----
// A[128]@0 (18432) | B[96]@18432 (13824) => 32256 B
#define AT_STAGE 32256
#define AT_DYN   (3*AT_STAGE)    // 96768  (x2 CTAs = 193536 <= 228KB/SM)

// ---------------------------------------------------------------------------
// Weight conversion: fp32 [o][c] -> bf16 hi/lo.  grid (9216, 3), block 256.
// ---------------------------------------------------------------------------
__global__ void convert_w_kernel(const float* __restrict__ cw,
                                 const float* __restrict__ qw,
                                 const float* __restrict__ kw)
{
    const int z = blockIdx.y;
    const float* src = (z == 0) ? cw : (z == 1 ? qw : kw);
    const size_t off = (size_t)z * NLAYER * CC * CC;
    const size_t idx = (size_t)blockIdx.x * 256 + threadIdx.x;
    float v = src[idx];
    __nv_bfloat16 h = __float2bfloat16(v);
    __nv_bfloat16 l = __float2bfloat16(v - __bfloat162float(h));
    g_wh[off + idx] = h;
    g_wl[off + idx] = l;
}

// ---------------------------------------------------------------------------
// Layer-0 input conversion+transpose: ext [b][c][hw] fp32 -> g_xt [n][c] bf16.
// grid (18, 24, 16), block (32,8).
// ---------------------------------------------------------------------------
__global__ void convert_x_kernel(const float* __restrict__ ext)
{
    __shared__ float tile[32][33];
    const int b = blockIdx.z;
    const float* src = ext + (size_t)b * CC * HWs;
    const int hw0 = blockIdx.x * 32;
    const int c0  = blockIdx.y * 32;
    const int tx = threadIdx.x, ty = threadIdx.y;

    #pragma unroll
    for (int j = 0; j < 4; j++) {
        int c = ty * 4 + j;
        tile[c][tx] = src[(size_t)(c0 + c) * HWs + hw0 + tx];
    }
    __syncthreads();
    #pragma unroll
    for (int j = 0; j < 4; j++) {
        int hwl = ty * 4 + j;
        float v = tile[tx][hwl];
        __nv_bfloat16 h = __float2bfloat16(v);
        __nv_bfloat16 l = __float2bfloat16(v - __bfloat162float(h));
        size_t o = (size_t)(b * HWs + hw0 + hwl) * CC + c0 + tx;
        g_xth[o] = h;
        g_xtl[o] = l;
    }
}

// ---------------------------------------------------------------------------
// Split-bf16 mma.sync GEMM, 128(o) x 96(hw) per CTA, 256 threads, 2 CTAs/SM,
// 3-stage cp.async ring.  grid (6, 6, 16).
// Output: if ft != nullptr -> tf32-rounded fp32 transposed (q/k path);
// else bf16 hi/lo transposed dh/dl, and optionally fp32 Y (+residual).
// ---------------------------------------------------------------------------
__global__ void __launch_bounds__(256, 2) gemm_mma_kernel(
    const __nv_bfloat16* __restrict__ Wh, const __nv_bfloat16* __restrict__ Wl,
    const __nv_bfloat16* __restrict__ Bh, const __nv_bfloat16* __restrict__ Bl,
    const float* __restrict__ bias, const float* __restrict__ resid, int residual,
    float* __restrict__ Y, int write_f32,
    __nv_bfloat16* __restrict__ dh, __nv_bfloat16* __restrict__ dl,
    float* __restrict__ ft)
{
    extern __shared__ __align__(16) char sm[];
    const int t   = threadIdx.x;
    const int wid = t >> 5;
    const int lid = t & 31;
    const int n0  = blockIdx.x * 96;      // hw
    const int m0  = blockIdx.y * 128;     // o
    const int b   = blockIdx.z;
    const int warp_m = wid & 3;
    const int warp_n = wid >> 2;
    const uint32_t smbase = smem_u32(sm);

    auto load_stage = [&](int s, int slot) {
        const int k0 = s * 32;
        const uint32_t st = smbase + (uint32_t)slot * TS_STAGE;
        #pragma unroll
        for (int it = 0; it < 2; it++) {   // A: 128 rows x 4 segs
            int jdx = it * 256 + t;
            int row = jdx >> 2, seg = jdx & 3;
            uint32_t d = st + (uint32_t)row * 80u + (uint32_t)seg * 16u;
            cp16(d,          Wh + (size_t)(m0 + row) * CC + k0 + seg * 8);
            cp16(d + 10240u, Wl + (size_t)(m0 + row) * CC + k0 + seg * 8);
        }
        #pragma unroll
        for (int it = 0; it < 2; it++) {   // B: 96 rows x 4 segs = 384 jobs
            int jdx = it * 256 + t;
            if (jdx < 384) {
                int row = jdx >> 2, seg = jdx & 3;
                uint32_t d = st + 20480u + (uint32_t)row * 80u + (uint32_t)seg * 16u;
                cp16(d,         Bh + (size_t)(b * HWs + n0 + row) * CC + k0 + seg * 8);
                cp16(d + 7680u, Bl + (size_t)(b * HWs + n0 + row) * CC + k0 + seg * 8);
            }
        }
    };

    float acc[2][6][4];
    #pragma unroll
    for (int mt = 0; mt < 2; mt++)
        #pragma unroll
        for (int j = 0; j < 6; j++)
            #pragma unroll
            for (int r = 0; r < 4; r++)
                acc[mt][j][r] = 0.f;

    load_stage(0, 0); cp_commit();
    load_stage(1, 1); cp_commit();

    for (int s = 0; s < 24; s++) {
        if (s + 1 < 24) cp_wait<1>(); else cp_wait<0>();
        __syncthreads();
        if (s + 2 < 24) { load_stage(s + 2, (s + 2) % 3); cp_commit(); }

        const uint32_t st = smbase + (uint32_t)(s % 3) * TS_STAGE;
        #pragma unroll
        for (int k16 = 0; k16 < 2; k16++) {
            const int kb = k16 * 16;
            uint32_t bh[12], bl[12];
            #pragma unroll
            for (int nt = 0; nt < 3; nt++) {
                uint32_t ba = st + 20480u
                    + (uint32_t)(warp_n * 48 + nt * 16 + (lid & 7) + ((lid >> 4) & 1) * 8) * 80u
                    + (uint32_t)(kb + ((lid >> 3) & 1) * 8) * 2u;
                ldsm4(&bh[nt * 4], ba);
                ldsm4(&bl[nt * 4], ba + 7680u);
            }
            #pragma unroll
            for (int mt = 0; mt < 2; mt++) {
                uint32_t ah[4], al[4];
                uint32_t aa = st
                    + (uint32_t)(warp_m * 32 + mt * 16 + (lid & 15)) * 80u
                    + (uint32_t)(kb + ((lid >> 4) & 1) * 8) * 2u;
                ldsm4(ah, aa);
                ldsm4(al, aa + 10240u);
                #pragma unroll
                for (int j = 0; j < 6; j++)
                    mma16816(acc[mt][j], ah, &bh[(j >> 1) * 4 + (j & 1) * 2]);
                #pragma unroll
                for (int j = 0; j < 6; j++)
                    mma16816(acc[mt][j], ah, &bl[(j >> 1) * 4 + (j & 1) * 2]);
                #pragma unroll
                for (int j = 0; j < 6; j++)
                    mma16816(acc[mt][j], al, &bh[(j >> 1) * 4 + (j & 1) * 2]);
            }
        }
    }

    // epilogue
    const size_t Yb = (size_t)b * CC * HWs;
    const int nb = b * HWs;
    #pragma unroll
    for (int mt = 0; mt < 2; mt++) {
        int R = m0 + warp_m * 32 + mt * 16 + (lid >> 2);
        float bs0 = bias[R], bs1 = bias[R + 8];
        #pragma unroll
        for (int j = 0; j < 6; j++) {
            int cb = n0 + warp_n * 48 + (j >> 1) * 16 + (j & 1) * 8 + (lid & 3) * 2;
            float v00 = acc[mt][j][0] + bs0, v01 = acc[mt][j][1] + bs0;
            float v10 = acc[mt][j][2] + bs1, v11 = acc[mt][j][3] + bs1;
            size_t r0o = (size_t)(nb + cb) * CC;
            size_t r1o = r0o + CC;
            if (ft) {
                // pre-round to tf32 so the attention mainloop needs no cvt
                ft[r0o + R]     = __uint_as_float(cvt_tf32(v00));
                ft[r1o + R]     = __uint_as_float(cvt_tf32(v01));
                ft[r0o + R + 8] = __uint_as_float(cvt_tf32(v10));
                ft[r1o + R + 8] = __uint_as_float(cvt_tf32(v11));
            } else {
                size_t a0 = Yb + (size_t)R * HWs + cb;
                size_t a1 = a0 + 8 * HWs;
                if (residual) {
                    float2 r0 = *(const float2*)(resid + a0);
                    float2 r1 = *(const float2*)(resid + a1);
                    v00 += r0.x; v01 += r0.y; v10 += r1.x; v11 += r1.y;
                }
                if (write_f32) {
                    *(float2*)(Y + a0) = make_float2(v00, v01);
                    *(float2*)(Y + a1) = make_float2(v10, v11);
                }
                __nv_bfloat16 h;
                h = __float2bfloat16(v00); dh[r0o + R]     = h; dl[r0o + R]     = __float2bfloat16(v00 - __bfloat162float(h));
                h = __float2bfloat16(v01); dh[r1o + R]     = h; dl[r1o + R]     = __float2bfloat16(v01 - __bfloat162float(h));
                h = __float2bfloat16(v10); dh[r0o + R + 8] = h; dl[r0o + R + 8] = __float2bfloat16(v10 - __bfloat162float(h));
                h = __float2bfloat16(v11); dh[r1o + R + 8] = h; dl[r1o + R + 8] = __float2bfloat16(v11 - __bfloat162float(h));
            }
        }
    }
}

// ---------------------------------------------------------------------------
// tf32 attention row-max with LDMATRIX fragment loads.
// CTA 128 q x 96 keys, 256 threads, 2 CTAs/SM, 6 ct x 24 k-chunks = 144
// stages, 3-stage ring, 1-pass tf32 m16n8k8.
// ldmatrix.x4.b16 on fp32 data delivers 8x4-float tiles with per-thread
// layout (t>>2, t&3) == the tf32 A/B fragment layouts exactly:
//   A x4: quadrants (r,c),(r+8,c),(r,c+4),(r+8,c+4)  [one per mt]
//   B x4: b0/b1 for two adjacent n8-tiles            [3 per k8]
// Values are pre-rounded tf32 (gemm epilogue), so no cvt in the loop.
// grid (72 m-tiles, 16 bk).
// ---------------------------------------------------------------------------
#define A_NSTG  144              // 6 ct * 24 k-chunks

__global__ void __launch_bounds__(256, 2) attn_mma_kernel()
{
    extern __shared__ __align__(16) char sm[];
    __shared__ float srow[2][128];

    const int t   = threadIdx.x;
    const int wid = t >> 5;
    const int lid = t & 31;
    const int n0  = blockIdx.x * 128;
    const int bk  = blockIdx.y;
    const int warp_m = wid & 3;
    const int warp_n = wid >> 2;
    const uint32_t smbase = smem_u32(sm);

    // ldmatrix address offsets (k-independent part), per thread:
    // A(mt): group g=lid>>3: g0 rows m..m+7 @k, g1 rows m+8..15 @k,
    //        g2 rows m..m+7 @k+4, g3 rows m+8..15 @k+4
    uint32_t a_off[2];
    #pragma unroll
    for (int mt = 0; mt < 2; mt++)
        a_off[mt] = (uint32_t)(warp_m * 32 + mt * 16 + ((lid >> 3) & 1) * 8 + (lid & 7)) * 144u
                  + (uint32_t)((lid >> 4) & 1) * 16u;
    // B(pair p -> n-tiles 2p,2p+1): g0 nt=2p @k, g1 nt=2p @k+4,
    //                               g2 nt=2p+1 @k, g3 nt=2p+1 @k+4
    uint32_t b_off[3];
    #pragma unroll
    for (int p = 0; p < 3; p++)
        b_off[p] = 18432u
                 + (uint32_t)(warp_n * 48 + (2 * p + ((lid >> 4) & 1)) * 8 + (lid & 7)) * 144u
                 + (uint32_t)((lid >> 3) & 1) * 16u;

    auto load_stage = [&](int s, int slot) {
        const int hk0 = (s / 24) * 96;
        const int k0  = (s % 24) * 32;
        const uint32_t st = smbase + (uint32_t)slot * AT_STAGE;
        #pragma unroll
        for (int it = 0; it < 4; it++) {   // A: 128 rows x 8 segs = 1024 jobs
            int jdx = it * 256 + t;
            int row = jdx >> 3, seg = jdx & 7;
            uint32_t d = st + (uint32_t)row * 144u + (uint32_t)seg * 16u;
            cp16(d, g_qt + (size_t)(n0 + row) * CC + k0 + seg * 4);
        }
        #pragma unroll
        for (int it = 0; it < 3; it++) {   // B: 96 rows x 8 segs = 768 jobs
            int jdx = it * 256 + t;
            int row = jdx >> 3, seg = jdx & 7;
            uint32_t d = st + 18432u + (uint32_t)row * 144u + (uint32_t)seg * 16u;
            cp16(d, g_kt + (size_t)(bk * HWs + hk0 + row) * CC + k0 + seg * 4);
        }
    };

    float acc[2][6][4];
    float rm[2][2] = {{-3.402823e38f, -3.402823e38f}, {-3.402823e38f, -3.402823e38f}};

    load_stage(0, 0); cp_commit();
    load_stage(1, 1); cp_commit();

    for (int s = 0; s < A_NSTG; s++) {
        if (s + 1 < A_NSTG) cp_wait<1>(); else cp_wait<0>();
        __syncthreads();
        if (s + 2 < A_NSTG) { load_stage(s + 2, (s + 2) % 3); cp_commit(); }

        if ((s % 24) == 0) {
            #pragma unroll
            for (int mt = 0; mt < 2; mt++)
                #pragma unroll
                for (int j = 0; j < 6; j++)
                    #pragma unroll
                    for (int r = 0; r < 4; r++)
                        acc[mt][j][r] = 0.f;
        }

        const uint32_t st = smbase + (uint32_t)(s % 3) * AT_STAGE;
        #pragma unroll
        for (int k8 = 0; k8 < 4; k8++) {
            const uint32_t kbyte = (uint32_t)k8 * 32u;
            uint32_t bf[12];
            #pragma unroll
            for (int p = 0; p < 3; p++)
                ldsm4(&bf[p * 4], st + b_off[p] + kbyte);
            #pragma unroll
            for (int mt = 0; mt < 2; mt++) {
                uint32_t af[4];
                ldsm4(af, st + a_off[mt] + kbyte);
                #pragma unroll
                for (int nt = 0; nt < 6; nt++)
                    mma1688_tf32(acc[mt][nt], af, bf[2 * nt], bf[2 * nt + 1]);
            }
        }

        if ((s % 24) == 23) {
            #pragma unroll
            for (int mt = 0; mt < 2; mt++) {
                float m0 = -3.402823e38f, m1 = -3.402823e38f;
                #pragma unroll
                for (int j = 0; j < 6; j++) {
                    m0 = fmaxf(m0, fmaxf(acc[mt][j][0], acc[mt][j][1]));
                    m1 = fmaxf(m1, fmaxf(acc[mt][j][2], acc[mt][j][3]));
                }
                m0 = fmaxf(m0, __shfl_xor_sync(0xffffffffu, m0, 1));
                m0 = fmaxf(m0, __shfl_xor_sync(0xffffffffu, m0, 2));
                m1 = fmaxf(m1, __shfl_xor_sync(0xffffffffu, m1, 1));
                m1 = fmaxf(m1, __shfl_xor_sync(0xffffffffu, m1, 2));
                rm[mt][0] = fmaxf(rm[mt][0], m0);
                rm[mt][1] = fmaxf(rm[mt][1], m1);
            }
        }
    }

    __syncthreads();
    if ((lid & 3) == 0) {
        #pragma unroll
        for (int mt = 0; mt < 2; mt++) {
            int r = warp_m * 32 + mt * 16 + (lid >> 2);
            srow[warp_n][r]     = rm[mt][0];
            srow[warp_n][r + 8] = rm[mt][1];
        }
    }
    __syncthreads();
    if (t < 128)
        g_maxpart[bk * NTOK + n0 + t] = fmaxf(srow[0][t], srow[1][t]);
}

// ---------------------------------------------------------------------------
// argmax over hw of sum_bk maxpart, then seeds = x5[:,hw*]/||x5[:,hw*]||.
// grid = 16, block 256.
// ---------------------------------------------------------------------------
__global__ void argmax_seeds_kernel()
{
    const int b = blockIdx.x;
    const int tid = threadIdx.x;
    __shared__ float sv[256];
    __shared__ int   si[256];
    __shared__ int   s_hw;
    __shared__ float s_inv;

    float best = -3.402823e38f;
    int   bidx = 0;
    for (int hw = tid; hw < HWs; hw += 256) {
        float s = 0.f;
        #pragma unroll
        for (int bk = 0; bk < BB; bk++)
            s += g_maxpart[bk * NTOK + b * HWs + hw];
        if (s > best) { best = s; bidx = hw; }
    }
    sv[tid] = best; si[tid] = bidx;
    __syncthreads();
    for (int s = 128; s > 0; s >>= 1) {
        if (tid < s) {
            if (sv[tid + s] > sv[tid] ||
                (sv[tid + s] == sv[tid] && si[tid + s] < si[tid])) {
                sv[tid] = sv[tid + s];
                si[tid] = si[tid + s];
            }
        }
        __syncthreads();
    }
    if (tid == 0) s_hw = si[0];
    __syncthreads();

    const int hws = s_hw;
    float vv[3];
    float sq = 0.f;
    #pragma unroll
    for (int j = 0; j < 3; j++) {
        int c = tid + j * 256;
        vv[j] = g_x5[(size_t)b * CC * HWs + (size_t)c * HWs + hws];
        sq = fmaf(vv[j], vv[j], sq);
    }
    sv[tid] = sq;
    __syncthreads();
    for (int s = 128; s > 0; s >>= 1) {
        if (tid < s) sv[tid] += sv[tid + s];
        __syncthreads();
    }
    if (tid == 0) s_inv = 1.f / fmaxf(sqrtf(sv[0]), 1e-12f);
    __syncthreads();
    float inv = s_inv;
    #pragma unroll
    for (int j = 0; j < 3; j++)
        g_seeds[b * CC + tid + j * 256] = vv[j] * inv;
}

// ---------------------------------------------------------------------------
// cor[b,hw] = (1/16) * sum_{b'} relu(x5[b,:,hw] . seeds[b',:]) / ||x5[b,:,hw]||
// grid=(16,3), block=192.
// ---------------------------------------------------------------------------
__global__ void cor_kernel()
{
    __shared__ float ss[BB * CC];
    const int b = blockIdx.x;
    for (int i = threadIdx.x; i < BB * CC; i += blockDim.x) ss[i] = g_seeds[i];
    __syncthreads();

    const int hw = blockIdx.y * 192 + threadIdx.x;
    const float* xp = g_x5 + (size_t)b * CC * HWs + hw;
    float acc[BB] = {};
    float sq = 0.f;
    for (int c = 0; c < CC; c++) {
        float v = xp[(size_t)c * HWs];
        sq = fmaf(v, v, sq);
        #pragma unroll
        for (int o = 0; o < BB; o++)
            acc[o] = fmaf(v, ss[o * CC + c], acc[o]);
    }
    float s = 0.f;
    #pragma unroll
    for (int o = 0; o < BB; o++) s += fmaxf(acc[o], 0.f);
    float nrm = fmaxf(sqrtf(sq), 1e-12f);
    g_cor[b * HWs + hw] = s / (16.f * nrm);
}

// Per-batch min-max normalize of cor. grid=16, block=256.
__global__ void minmax_kernel()
{
    const int b = blockIdx.x;
    const int tid = threadIdx.x;
    __shared__ float smn[256], smx[256];
    float mn = 3.402823e38f, mx = -3.402823e38f;
    for (int hw = tid; hw < HWs; hw += 256) {
        float v = g_cor[b * HWs + hw];
        mn = fminf(mn, v);
        mx = fmaxf(mx, v);
    }
    smn[tid] = mn; smx[tid] = mx;
    __syncthreads();
    for (int s = 128; s > 0; s >>= 1) {
        if (tid < s) {
            smn[tid] = fminf(smn[tid], smn[tid + s]);
            smx[tid] = fmaxf(smx[tid], smx[tid + s]);
        }
        __syncthreads();
    }
    float m0 = smn[0];
    float inv = 1.f / (smx[0] - m0 + 1e-12f);
    for (int hw = tid; hw < HWs; hw += 256)
        g_cor[b * HWs + hw] = (g_cor[b * HWs + hw] - m0) * inv;
}

// ---------------------------------------------------------------------------
// apply + transpose-convert: cur = (add_prev?cur:0) + x5*cor, AND write
// cur transposed bf16 hi/lo.  grid (18, 24, 16), block (32,8).
// ---------------------------------------------------------------------------
__global__ void apply_t_kernel(int add_prev)
{
    __shared__ float tile[32][33];
    const int b = blockIdx.z;
    const int hw0 = blockIdx.x * 32;
    const int c0  = blockIdx.y * 32;
    const int tx = threadIdx.x, ty = threadIdx.y;

    const float corv = g_cor[b * HWs + hw0 + tx];
    const size_t base = (size_t)b * CC * HWs;

    #pragma unroll
    for (int j = 0; j < 4; j++) {
        int c = c0 + ty * 4 + j;
        size_t idx = base + (size_t)c * HWs + hw0 + tx;
        float v = g_x5[idx] * corv;
        if (add_prev) v += g_cur[idx];
        g_cur[idx] = v;
        tile[ty * 4 + j][tx] = v;
    }
    __syncthreads();
    #pragma unroll
    for (int j = 0; j < 4; j++) {
        int hwl = ty * 4 + j;
        float v = tile[tx][hwl];
        __nv_bfloat16 h = __float2bfloat16(v);
        __nv_bfloat16 l = __float2bfloat16(v - __bfloat162float(h));
        size_t o = (size_t)(b * HWs + hw0 + hwl) * CC + c0 + tx;
        g_xth[o] = h;
        g_xtl[o] = l;
    }
}

// consen[c] = mean over (b,hw) of cur. grid=768, block=256.
__global__ void consen_kernel()
{
    const int c = blockIdx.x;
    const int tid = threadIdx.x;
    __shared__ float sm[256];
    float s = 0.f;
    for (int b = 0; b < BB; b++) {
        const float* p = g_cur + (size_t)b * CC * HWs + (size_t)c * HWs;
        for (int hw = tid; hw < HWs; hw += 256) s += p[hw];
    }
    sm[tid] = s;
    __syncthreads();
    for (int st = 128; st > 0; st >>= 1) {
        if (tid < st) sm[tid] += sm[tid + st];
        __syncthreads();
    }
    if (tid == 0) g_consen[c] = sm[0] * (1.f / (float)(BB * HWs));
}

__global__ void final_kernel(const float* __restrict__ xin, float* __restrict__ out)
{
    int idx = blockIdx.x * 256 + threadIdx.x;
    int c = (idx / HWs) % CC;
    out[idx] = g_cur[idx] + xin[idx] * g_consen[c];
}

// ---------------------------------------------------------------------------
extern "C" void kernel_launch(void* const* d_in, const int* in_sizes, int n_in,
                              void* d_out, int out_size)
{
    const float* x5      = (const float*)d_in[0];
    const float* conv_w  = (const float*)d_in[1];
    const float* conv_b  = (const float*)d_in[2];
    const float* query_w = (const float*)d_in[3];
    const float* query_b = (const float*)d_in[4];
    const float* key_w   = (const float*)d_in[5];
    const float* key_b   = (const float*)d_in[6];
    float* out = (float*)d_out;

    cudaFuncSetAttribute(attn_mma_kernel,
                         cudaFuncAttributeMaxDynamicSharedMemorySize, AT_DYN);
    cudaFuncSetAttribute(gemm_mma_kernel,
                         cudaFuncAttributeMaxDynamicSharedMemorySize, TS_DYN);

    __nv_bfloat16 *wh_p, *wl_p, *xth_p, *xtl_p, *x5th_p, *x5tl_p;
    cudaGetSymbolAddress((void**)&wh_p, g_wh);
    cudaGetSymbolAddress((void**)&wl_p, g_wl);
    cudaGetSymbolAddress((void**)&xth_p, g_xth);
    cudaGetSymbolAddress((void**)&xtl_p, g_xtl);
    cudaGetSymbolAddress((void**)&x5th_p, g_x5th);
    cudaGetSymbolAddress((void**)&x5tl_p, g_x5tl);
    float *x5g_p, *cur_p, *qt_p, *kt_p;
    cudaGetSymbolAddress((void**)&x5g_p, g_x5);
    cudaGetSymbolAddress((void**)&cur_p, g_cur);
    cudaGetSymbolAddress((void**)&qt_p, g_qt);
    cudaGetSymbolAddress((void**)&kt_p, g_kt);

    dim3 wgrid(NLAYER * CC * CC / 256, 3);  // (9216, 3)
    dim3 xgrid(HWs / 32, CC / 32, BB);      // (18, 24, 16)
    dim3 mgrid(HWs / 96, CC / 128, BB);     // (6, 6, 16)
    dim3 agrid(NTOK / 128, BB);             // (72, 16)
    dim3 cgrid(BB, HWs / 192);              // (16, 3)
    const int egrid = ELEMS / 256;          // 27648

    convert_w_kernel<<<wgrid, 256>>>(conv_w, query_w, key_w);
    convert_x_kernel<<<xgrid, dim3(32, 8)>>>(x5);   // layer-0 input only

    const size_t WSZ = (size_t)CC * CC;
    for (int i = 0; i < NLAYER; i++) {
        // x5 = conv(cur) + bias + cur   (fp32 + fused transposed bf16 out)
        gemm_mma_kernel<<<mgrid, 256, TS_DYN>>>(
            wh_p + i * WSZ, wl_p + i * WSZ, xth_p, xtl_p,
            conv_b + i * CC, (i == 0) ? x5 : cur_p, 1,
            x5g_p, 1, x5th_p, x5tl_p, nullptr);
        // q, k: tf32-rounded fp32 transposed (attention operands)
        gemm_mma_kernel<<<mgrid, 256, TS_DYN>>>(
            wh_p + (NLAYER + i) * WSZ, wl_p + (NLAYER + i) * WSZ, x5th_p, x5tl_p,
            query_b + i * CC, nullptr, 0,
            nullptr, 0, nullptr, nullptr, qt_p);
        gemm_mma_kernel<<<mgrid, 256, TS_DYN>>>(
            wh_p + (2 * NLAYER + i) * WSZ, wl_p + (2 * NLAYER + i) * WSZ, x5th_p, x5tl_p,
            key_b + i * CC, nullptr, 0,
            nullptr, 0, nullptr, nullptr, kt_p);
        attn_mma_kernel<<<agrid, 256, AT_DYN>>>();
        argmax_seeds_kernel<<<BB, 256>>>();
        cor_kernel<<<cgrid, 192>>>();
        minmax_kernel<<<BB, 256>>>();
        apply_t_kernel<<<xgrid, dim3(32, 8)>>>(i > 0 ? 1 : 0);
    }
    consen_kernel<<<CC, 256>>>();
    final_kernel<<<egrid, 256>>>(x5, out);
}